// round 6
// baseline (speedup 1.0000x reference)
#include <cuda_runtime.h>
#include <cuda_bf16.h>
#include <cstdint>
#include <cstddef>

#define S_DIM 2048
#define E_DIM 1024
#define H_NUM 16
#define DH_DIM 64
#define B_NUM 2
#define BH_NUM (B_NUM * H_NUM)     // 32
#define M_ROWS (B_NUM * S_DIM)     // 4096
#define NROWS ((size_t)BH_NUM * S_DIM)  // 65536

__device__ float g_q[(size_t)BH_NUM * S_DIM * DH_DIM];
__device__ float g_k[(size_t)BH_NUM * S_DIM * DH_DIM];
__device__ float g_v[(size_t)BH_NUM * S_DIM * DH_DIM];
__device__ float g_ctx[(size_t)M_ROWS * E_DIM];
__device__ float g_attn[(size_t)BH_NUM * S_DIM * S_DIM];   // fallback
__device__ float g_partial[16 * NROWS];                    // per-jblock row sums
__device__ float g_invl[NROWS];

// ---------------------------------------------------------------------------
// helpers
// ---------------------------------------------------------------------------
__device__ __forceinline__ uint32_t smem_u32(const void* p) {
    uint32_t a;
    asm("{ .reg .u64 t; cvta.to.shared.u64 t, %1; cvt.u32.u64 %0, t; }" : "=r"(a) : "l"(p));
    return a;
}
__device__ __forceinline__ void ldm4(uint32_t* r, uint32_t a) {
    asm volatile("ldmatrix.sync.aligned.m8n8.x4.shared.b16 {%0,%1,%2,%3}, [%4];"
        : "=r"(r[0]), "=r"(r[1]), "=r"(r[2]), "=r"(r[3]) : "r"(a));
}
__device__ __forceinline__ void ldm4t(uint32_t* r, uint32_t a) {
    asm volatile("ldmatrix.sync.aligned.m8n8.x4.trans.shared.b16 {%0,%1,%2,%3}, [%4];"
        : "=r"(r[0]), "=r"(r[1]), "=r"(r[2]), "=r"(r[3]) : "r"(a));
}
__device__ __forceinline__ void mma_bf16(float* c, const uint32_t* a, uint32_t b0, uint32_t b1) {
    asm volatile(
        "mma.sync.aligned.m16n8k16.row.col.f32.bf16.bf16.f32 "
        "{%0,%1,%2,%3}, {%4,%5,%6,%7}, {%8,%9}, {%0,%1,%2,%3};"
        : "+f"(c[0]), "+f"(c[1]), "+f"(c[2]), "+f"(c[3])
        : "r"(a[0]), "r"(a[1]), "r"(a[2]), "r"(a[3]), "r"(b0), "r"(b1));
}
// swizzles: 128B-pitch rows rotate 16B-granule by (row&7); 64B-pitch by ((row>>1)&3); 256B by (row&7)
__device__ __forceinline__ uint32_t swp128(int row, int c2) { return (uint32_t)(row * 128 + c2) ^ ((row & 7) << 4); }
__device__ __forceinline__ uint32_t swp64 (int row, int c2) { return (uint32_t)(row * 64  + c2) ^ (((row >> 1) & 3) << 4); }
__device__ __forceinline__ uint32_t swp256(int row, int c2) { return (uint32_t)(row * 256 + c2) ^ ((row & 7) << 4); }

__device__ __forceinline__ void split8(const float* v, uint32_t* hi, uint32_t* lo) {
#pragma unroll
    for (int q = 0; q < 4; q++) {
        __nv_bfloat16 h0 = __float2bfloat16(v[2*q]);
        __nv_bfloat16 h1 = __float2bfloat16(v[2*q+1]);
        __nv_bfloat16 l0 = __float2bfloat16(v[2*q]   - __bfloat162float(h0));
        __nv_bfloat16 l1 = __float2bfloat16(v[2*q+1] - __bfloat162float(h1));
        hi[q] = (uint32_t)__bfloat16_as_ushort(h0) | ((uint32_t)__bfloat16_as_ushort(h1) << 16);
        lo[q] = (uint32_t)__bfloat16_as_ushort(l0) | ((uint32_t)__bfloat16_as_ushort(l1) << 16);
    }
}

// ---------------------------------------------------------------------------
// loaders
// ---------------------------------------------------------------------------
// 128x64, pitch 128 (logits Q/K tiles)
__device__ __forceinline__ void load_t128_64(const float* g, int ld, char* sm,
                                             int ohi, int olo, int tid) {
    int row = tid >> 1, c0 = (tid & 1) * 32;
    const float* p = g + (size_t)row * ld + c0;
#pragma unroll
    for (int gi = 0; gi < 4; gi++) {
        float v[8];
        *(float4*)(v)     = *(const float4*)(p + gi * 8);
        *(float4*)(v + 4) = *(const float4*)(p + gi * 8 + 4);
        uint32_t hi[4], lo[4];
        split8(v, hi, lo);
        uint32_t sw = swp128(row, (c0 + gi * 8) * 2);
        *(uint4*)(sm + ohi + sw) = make_uint4(hi[0], hi[1], hi[2], hi[3]);
        *(uint4*)(sm + olo + sw) = make_uint4(lo[0], lo[1], lo[2], lo[3]);
    }
}
// 128x32, pitch 64 (proj A tile)
__device__ __forceinline__ void load_t128_32(const float* g, int ld, char* sm,
                                             int ohi, int olo, int tid) {
    int row = tid >> 1, c0 = (tid & 1) * 16;
    const float* p = g + (size_t)row * ld + c0;
#pragma unroll
    for (int gi = 0; gi < 2; gi++) {
        float v[8];
        *(float4*)(v)     = *(const float4*)(p + gi * 8);
        *(float4*)(v + 4) = *(const float4*)(p + gi * 8 + 4);
        uint32_t hi[4], lo[4];
        split8(v, hi, lo);
        uint32_t sw = swp64(row, (c0 + gi * 8) * 2);
        *(uint4*)(sm + ohi + sw) = make_uint4(hi[0], hi[1], hi[2], hi[3]);
        *(uint4*)(sm + olo + sw) = make_uint4(lo[0], lo[1], lo[2], lo[3]);
    }
}
// 128x32 p tile with normalize + write-back (ctx)
__device__ __forceinline__ void load_p32(float* g, int ld, float scale, char* sm,
                                         int ohi, int olo, int tid) {
    int row = tid >> 1, c0 = (tid & 1) * 16;
    float* p = g + (size_t)row * ld + c0;
#pragma unroll
    for (int gi = 0; gi < 2; gi++) {
        float v[8];
        *(float4*)(v)     = *(const float4*)(p + gi * 8);
        *(float4*)(v + 4) = *(const float4*)(p + gi * 8 + 4);
#pragma unroll
        for (int q = 0; q < 8; q++) v[q] *= scale;
        *(float4*)(p + gi * 8)     = *(float4*)(v);
        *(float4*)(p + gi * 8 + 4) = *(float4*)(v + 4);
        uint32_t hi[4], lo[4];
        split8(v, hi, lo);
        uint32_t sw = swp64(row, (c0 + gi * 8) * 2);
        *(uint4*)(sm + ohi + sw) = make_uint4(hi[0], hi[1], hi[2], hi[3]);
        *(uint4*)(sm + olo + sw) = make_uint4(lo[0], lo[1], lo[2], lo[3]);
    }
}
// W chunk: 32 k-rows x 128 n-cols, pitch 256
__device__ __forceinline__ void load_w32(const float* W, int n0, int k0, char* sm,
                                         int ohi, int olo, int tid) {
    int krow = tid >> 3, nseg = (tid & 7) * 16;
    const float* p = W + (size_t)(k0 + krow) * E_DIM + n0 + nseg;
#pragma unroll
    for (int gi = 0; gi < 2; gi++) {
        float v[8];
        *(float4*)(v)     = *(const float4*)(p + gi * 8);
        *(float4*)(v + 4) = *(const float4*)(p + gi * 8 + 4);
        uint32_t hi[4], lo[4];
        split8(v, hi, lo);
        uint32_t sw = swp256(krow, (nseg + gi * 8) * 2);
        *(uint4*)(sm + ohi + sw) = make_uint4(hi[0], hi[1], hi[2], hi[3]);
        *(uint4*)(sm + olo + sw) = make_uint4(lo[0], lo[1], lo[2], lo[3]);
    }
}
// V chunk: 32 j-rows x 64 d-cols, pitch 128
__device__ __forceinline__ void load_v32(const float* V, char* sm,
                                         int ohi, int olo, int tid) {
    int row = tid >> 3, c0 = (tid & 7) * 8;
    const float* p = V + (size_t)row * DH_DIM + c0;
    float v[8];
    *(float4*)(v)     = *(const float4*)(p);
    *(float4*)(v + 4) = *(const float4*)(p + 4);
    uint32_t hi[4], lo[4];
    split8(v, hi, lo);
    uint32_t sw = swp128(row, c0 * 2);
    *(uint4*)(sm + ohi + sw) = make_uint4(hi[0], hi[1], hi[2], hi[3]);
    *(uint4*)(sm + olo + sw) = make_uint4(lo[0], lo[1], lo[2], lo[3]);
}

// ---------------------------------------------------------------------------
// Projection GEMM: C = A[4096,1024] @ W[1024,1024] + bias
// QKV fused via blockIdx.z. mode 0: split-head [z,s,d]; mode 2: plain [m,n].
// grid (8, 32, nz), 256 thr, KC=32, double-buffered (64KB smem).
// ---------------------------------------------------------------------------
#define PROJ_SMEM 65536
__global__ void __launch_bounds__(256) proj_mma(
    const float* __restrict__ A,
    const float* __restrict__ W0, const float* __restrict__ W1, const float* __restrict__ W2,
    const float* __restrict__ b0p, const float* __restrict__ b1p, const float* __restrict__ b2p,
    float* __restrict__ o0, float* __restrict__ o1, float* __restrict__ o2, int mode)
{
    extern __shared__ char sm[];
    uint32_t sb = smem_u32(sm);
    int zz = blockIdx.z;
    const float* W    = zz == 0 ? W0 : (zz == 1 ? W1 : W2);
    const float* bias = zz == 0 ? b0p : (zz == 1 ? b1p : b2p);
    float* out        = zz == 0 ? o0 : (zz == 1 ? o1 : o2);

    int tid = threadIdx.x, lane = tid & 31, wid = tid >> 5;
    int warp_m = wid & 3, warp_n = wid >> 2;
    int n0 = blockIdx.x * 128, m0 = blockIdx.y * 128;
    int lrow = lane & 7, grp = lane >> 3;

    float acc[16][4] = {};
    load_t128_32(A + (size_t)m0 * E_DIM, E_DIM, sm, 0, 8192, tid);
    load_w32(W, n0, 0, sm, 16384, 24576, tid);
    __syncthreads();

    for (int c = 0; c < 32; c++) {
        int cur = (c & 1) * 32768;
        if (c < 31) {
            int nb = ((c + 1) & 1) * 32768;
            load_t128_32(A + (size_t)m0 * E_DIM + (c + 1) * 32, E_DIM, sm, nb, nb + 8192, tid);
            load_w32(W, n0, (c + 1) * 32, sm, nb + 16384, nb + 24576, tid);
        }
        uint32_t sa_hi = sb + cur, sa_lo = sb + cur + 8192;
        uint32_t sw_hi = sb + cur + 16384, sw_lo = sb + cur + 24576;
#pragma unroll
        for (int ks = 0; ks < 2; ks++) {
            int k = ks * 16;
            uint32_t ah[2][4], al[2][4];
#pragma unroll
            for (int mt = 0; mt < 2; mt++) {
                int row = warp_m * 32 + mt * 16 + lrow + (grp & 1) * 8;
                uint32_t off = swp64(row, (k + (grp >> 1) * 8) * 2);
                ldm4(ah[mt], sa_hi + off);
                ldm4(al[mt], sa_lo + off);
            }
#pragma unroll
            for (int nh = 0; nh < 4; nh++) {
                int krow = k + (lane & 15);
                int ncol = warp_n * 64 + nh * 16 + (lane >> 4) * 8;
                uint32_t offb = swp256(krow, ncol * 2);
                uint32_t bh[4], bl[4];
                ldm4t(bh, sw_hi + offb);
                ldm4t(bl, sw_lo + offb);
#pragma unroll
                for (int mt = 0; mt < 2; mt++) {
                    float* c0a = acc[mt * 8 + nh * 2];
                    float* c1a = acc[mt * 8 + nh * 2 + 1];
                    mma_bf16(c0a, ah[mt], bh[0], bh[1]);
                    mma_bf16(c1a, ah[mt], bh[2], bh[3]);
                    mma_bf16(c0a, ah[mt], bl[0], bl[1]);
                    mma_bf16(c1a, ah[mt], bl[2], bl[3]);
                    mma_bf16(c0a, al[mt], bh[0], bh[1]);
                    mma_bf16(c1a, al[mt], bh[2], bh[3]);
                }
            }
        }
        __syncthreads();
    }

    int crow = lane >> 2, cc = (lane & 3) * 2;
#pragma unroll
    for (int mt = 0; mt < 2; mt++) {
#pragma unroll
        for (int t8 = 0; t8 < 8; t8++) {
            const float* c = acc[mt * 8 + t8];
            int n = n0 + warp_n * 64 + t8 * 8 + cc;
            int r0 = m0 + warp_m * 32 + mt * 16 + crow;
            float bb0 = bias[n], bb1 = bias[n + 1];
            if (mode == 2) {
                *(float2*)(out + (size_t)r0 * E_DIM + n)       = make_float2(c[0] + bb0, c[1] + bb1);
                *(float2*)(out + (size_t)(r0 + 8) * E_DIM + n) = make_float2(c[2] + bb0, c[3] + bb1);
            } else {
                int h = n >> 6, d = n & 63;
#pragma unroll
                for (int rr = 0; rr < 2; rr++) {
                    int m = r0 + rr * 8;
                    int b = m >> 11, s = m & (S_DIM - 1);
                    float* p = out + (((size_t)(b * H_NUM + h) * S_DIM + s) << 6) + d;
                    *(float2*)p = make_float2(c[2 * rr] + bb0, c[2 * rr + 1] + bb1);
                }
            }
        }
    }
}

// ---------------------------------------------------------------------------
// Logits + exp + partial row sums.
// p[z,i,j] = exp(0.125*Q·K - 1e9*mask[b,j]); partial[bx][z*2048+i] = rowsum over j-block
// grid (16, 16, 32), 256 threads.
// ---------------------------------------------------------------------------
#define LOG_SMEM (65536 + 1024)
__global__ void __launch_bounds__(256) logits_mma(
    const float* __restrict__ Q, const float* __restrict__ Kmat,
    const float* __restrict__ mask, float* __restrict__ attn,
    float* __restrict__ partial)
{
    extern __shared__ char sm[];
    uint32_t sb = smem_u32(sm);
    float* sums = (float*)(sm + 65536);   // [128][2]
    int tid = threadIdx.x, lane = tid & 31, wid = tid >> 5;
    int warp_m = wid & 3, warp_n = wid >> 2;
    int z = blockIdx.z;
    int i0 = blockIdx.y * 128, j0 = blockIdx.x * 128;
    const float* Qb = Q + (size_t)z * S_DIM * DH_DIM;
    const float* Kb = Kmat + (size_t)z * S_DIM * DH_DIM;
    const float* mb = mask + (size_t)(z >> 4) * S_DIM;
    int lrow = lane & 7, grp = lane >> 3;

    load_t128_64(Qb + (size_t)i0 * DH_DIM, DH_DIM, sm, 0, 16384, tid);
    load_t128_64(Kb + (size_t)j0 * DH_DIM, DH_DIM, sm, 32768, 49152, tid);
    __syncthreads();

    float acc[16][4] = {};
    {
        uint32_t sa_hi = sb, sa_lo = sb + 16384, sk_hi = sb + 32768, sk_lo = sb + 49152;
#pragma unroll
        for (int ks = 0; ks < 4; ks++) {
            int k = ks * 16;
            uint32_t ah[2][4], al[2][4];
#pragma unroll
            for (int mt = 0; mt < 2; mt++) {
                int row = warp_m * 32 + mt * 16 + lrow + (grp & 1) * 8;
                uint32_t off = swp128(row, (k + (grp >> 1) * 8) * 2);
                ldm4(ah[mt], sa_hi + off);
                ldm4(al[mt], sa_lo + off);
            }
#pragma unroll
            for (int nh = 0; nh < 4; nh++) {
                int rowb = warp_n * 64 + nh * 16 + lrow + ((grp >> 1) & 1) * 8;
                uint32_t offb = swp128(rowb, (k + (grp & 1) * 8) * 2);
                uint32_t bh[4], bl[4];
                ldm4(bh, sk_hi + offb);
                ldm4(bl, sk_lo + offb);
#pragma unroll
                for (int mt = 0; mt < 2; mt++) {
                    float* c0a = acc[mt * 8 + nh * 2];
                    float* c1a = acc[mt * 8 + nh * 2 + 1];
                    mma_bf16(c0a, ah[mt], bh[0], bh[1]);
                    mma_bf16(c1a, ah[mt], bh[2], bh[3]);
                    mma_bf16(c0a, ah[mt], bl[0], bl[1]);
                    mma_bf16(c1a, ah[mt], bl[2], bl[3]);
                    mma_bf16(c0a, al[mt], bh[0], bh[1]);
                    mma_bf16(c1a, al[mt], bh[2], bh[3]);
                }
            }
        }
    }

    int crow = lane >> 2, cc = (lane & 3) * 2;
    float rsum[4] = {0.f, 0.f, 0.f, 0.f};
#pragma unroll
    for (int mt = 0; mt < 2; mt++) {
#pragma unroll
        for (int t8 = 0; t8 < 8; t8++) {
            float* c = acc[mt * 8 + t8];
            int j = j0 + warp_n * 64 + t8 * 8 + cc;
            int i = i0 + warp_m * 32 + mt * 16 + crow;
            float m0v = 1e9f * mb[j], m1v = 1e9f * mb[j + 1];
            float p00 = __expf(c[0] * 0.125f - m0v);
            float p01 = __expf(c[1] * 0.125f - m1v);
            float p10 = __expf(c[2] * 0.125f - m0v);
            float p11 = __expf(c[3] * 0.125f - m1v);
            *(float2*)(attn + ((size_t)z * S_DIM + i) * S_DIM + j)     = make_float2(p00, p01);
            *(float2*)(attn + ((size_t)z * S_DIM + i + 8) * S_DIM + j) = make_float2(p10, p11);
            rsum[mt * 2]     += p00 + p01;
            rsum[mt * 2 + 1] += p10 + p11;
        }
    }
    // reduce across the 4 lanes sharing a row
#pragma unroll
    for (int q = 0; q < 4; q++) {
        rsum[q] += __shfl_xor_sync(0xFFFFFFFFu, rsum[q], 1);
        rsum[q] += __shfl_xor_sync(0xFFFFFFFFu, rsum[q], 2);
    }
    if ((lane & 3) == 0) {
#pragma unroll
        for (int q = 0; q < 4; q++) {
            int lr = warp_m * 32 + (q >> 1) * 16 + crow + (q & 1) * 8;
            sums[lr * 2 + warp_n] = rsum[q];
        }
    }
    __syncthreads();
    if (tid < 128) {
        float s = sums[tid * 2] + sums[tid * 2 + 1];
        partial[(size_t)blockIdx.x * NROWS + ((size_t)z << 11) + i0 + tid] = s;
    }
}

// inv_l[r] = 1 / sum_jb partial[jb][r]
__global__ void __launch_bounds__(256) reduce_inv(const float* __restrict__ partial,
                                                  float* __restrict__ invl)
{
    int r = blockIdx.x * 256 + threadIdx.x;
    float s = 0.f;
#pragma unroll
    for (int jb = 0; jb < 16; jb++) s += partial[(size_t)jb * NROWS + r];
    invl[r] = 1.0f / s;
}

// ---------------------------------------------------------------------------
// ctx: normalize p rows (write attn back), ctx = (p*inv) @ V. KC=32, grid (16, 32).
// ---------------------------------------------------------------------------
#define CTX_SMEM 49152
__global__ void __launch_bounds__(256) ctx_mma(
    float* __restrict__ attn, const float* __restrict__ V,
    const float* __restrict__ invl, float* __restrict__ ctx)
{
    extern __shared__ char sm[];
    uint32_t sb = smem_u32(sm);
    int tid = threadIdx.x, lane = tid & 31, wid = tid >> 5;
    int warp_m = wid & 3, warp_n = wid >> 2;
    int z = blockIdx.y, i0 = blockIdx.x * 128;
    float* Ab = attn + ((size_t)z * S_DIM + i0) * S_DIM;
    const float* Vb = V + (size_t)z * S_DIM * DH_DIM;
    int lrow = lane & 7, grp = lane >> 3;
    float scale = invl[((size_t)z << 11) + i0 + (tid >> 1)];

    float acc[8][4] = {};
    load_p32(Ab, S_DIM, scale, sm, 0, 8192, tid);
    load_v32(Vb, sm, 16384, 20480, tid);
    __syncthreads();

    for (int c = 0; c < 64; c++) {
        int cur = (c & 1) * 24576;
        if (c < 63) {
            int nb = ((c + 1) & 1) * 24576;
            load_p32(Ab + (c + 1) * 32, S_DIM, scale, sm, nb, nb + 8192, tid);
            load_v32(Vb + (size_t)(c + 1) * 32 * DH_DIM, sm, nb + 16384, nb + 20480, tid);
        }
        uint32_t sa_hi = sb + cur, sa_lo = sb + cur + 8192;
        uint32_t sv_hi = sb + cur + 16384, sv_lo = sb + cur + 20480;
#pragma unroll
        for (int ks = 0; ks < 2; ks++) {
            int k = ks * 16;
            uint32_t ah[2][4], al[2][4];
#pragma unroll
            for (int mt = 0; mt < 2; mt++) {
                int row = warp_m * 32 + mt * 16 + lrow + (grp & 1) * 8;
                uint32_t off = swp64(row, (k + (grp >> 1) * 8) * 2);
                ldm4(ah[mt], sa_hi + off);
                ldm4(al[mt], sa_lo + off);
            }
#pragma unroll
            for (int nh = 0; nh < 2; nh++) {
                int krow = k + (lane & 15);
                int ncol = warp_n * 32 + nh * 16 + (lane >> 4) * 8;
                uint32_t offb = swp128(krow, ncol * 2);
                uint32_t bh[4], bl[4];
                ldm4t(bh, sv_hi + offb);
                ldm4t(bl, sv_lo + offb);
#pragma unroll
                for (int mt = 0; mt < 2; mt++) {
                    float* c0a = acc[mt * 4 + nh * 2];
                    float* c1a = acc[mt * 4 + nh * 2 + 1];
                    mma_bf16(c0a, ah[mt], bh[0], bh[1]);
                    mma_bf16(c1a, ah[mt], bh[2], bh[3]);
                    mma_bf16(c0a, ah[mt], bl[0], bl[1]);
                    mma_bf16(c1a, ah[mt], bl[2], bl[3]);
                    mma_bf16(c0a, al[mt], bh[0], bh[1]);
                    mma_bf16(c1a, al[mt], bh[2], bh[3]);
                }
            }
        }
        __syncthreads();
    }

    int b = z >> 4, h = z & 15;
    int crow = lane >> 2, cc = (lane & 3) * 2;
#pragma unroll
    for (int mt = 0; mt < 2; mt++) {
#pragma unroll
        for (int t8 = 0; t8 < 4; t8++) {
            const float* c = acc[mt * 4 + t8];
            int d = warp_n * 32 + t8 * 8 + cc;
            int s0 = i0 + warp_m * 32 + mt * 16 + crow;
            float* p0 = ctx + (size_t)(b * S_DIM + s0) * E_DIM + h * DH_DIM + d;
            float* p1 = ctx + (size_t)(b * S_DIM + s0 + 8) * E_DIM + h * DH_DIM + d;
            *(float2*)p0 = make_float2(c[0], c[1]);
            *(float2*)p1 = make_float2(c[2], c[3]);
        }
    }
}

// ---------------------------------------------------------------------------

extern "C" void kernel_launch(void* const* d_in, const int* in_sizes, int n_in,
                              void* d_out, int out_size)
{
    const float* features = (const float*)d_in[0];
    const float* mask     = (const float*)d_in[1];
    const float* Wq = (const float*)d_in[2];
    const float* bq = (const float*)d_in[3];
    const float* Wk = (const float*)d_in[4];
    const float* bk = (const float*)d_in[5];
    const float* Wv = (const float*)d_in[6];
    const float* bv = (const float*)d_in[7];
    const float* Wo = (const float*)d_in[8];
    const float* bo = (const float*)d_in[9];
    float* out = (float*)d_out;

    float *q, *k, *v, *ctx, *attn_scratch, *partial, *invl;
    cudaGetSymbolAddress((void**)&q, g_q);
    cudaGetSymbolAddress((void**)&k, g_k);
    cudaGetSymbolAddress((void**)&v, g_v);
    cudaGetSymbolAddress((void**)&ctx, g_ctx);
    cudaGetSymbolAddress((void**)&attn_scratch, g_attn);
    cudaGetSymbolAddress((void**)&partial, g_partial);
    cudaGetSymbolAddress((void**)&invl, g_invl);

    const long long OUT_ELEMS  = (long long)M_ROWS * E_DIM;
    const long long ATTN_ELEMS = (long long)BH_NUM * S_DIM * S_DIM;
    float* attn = ((long long)out_size >= OUT_ELEMS + ATTN_ELEMS)
                      ? (out + OUT_ELEMS) : attn_scratch;

    cudaFuncSetAttribute(proj_mma, cudaFuncAttributeMaxDynamicSharedMemorySize, PROJ_SMEM);
    cudaFuncSetAttribute(logits_mma, cudaFuncAttributeMaxDynamicSharedMemorySize, LOG_SMEM);
    cudaFuncSetAttribute(ctx_mma, cudaFuncAttributeMaxDynamicSharedMemorySize, CTX_SMEM);
    cudaFuncSetAttribute(proj_mma, cudaFuncAttributePreferredSharedMemoryCarveout, 100);
    cudaFuncSetAttribute(logits_mma, cudaFuncAttributePreferredSharedMemoryCarveout, 100);
    cudaFuncSetAttribute(ctx_mma, cudaFuncAttributePreferredSharedMemoryCarveout, 100);

    dim3 blk(256);
    proj_mma<<<dim3(8, 32, 3), blk, PROJ_SMEM>>>(features, Wq, Wk, Wv, bq, bk, bv, q, k, v, 0);
    logits_mma<<<dim3(16, 16, 32), blk, LOG_SMEM>>>(q, k, mask, attn, partial);
    reduce_inv<<<256, blk>>>(partial, invl);
    ctx_mma<<<dim3(16, 32), blk, CTX_SMEM>>>(attn, v, invl, ctx);
    proj_mma<<<dim3(8, 32, 1), blk, PROJ_SMEM>>>(ctx, Wo, Wo, Wo, bo, bo, bo, out, out, out, 2);
}

// round 7
// speedup vs baseline: 1.0298x; 1.0298x over previous
#include <cuda_runtime.h>
#include <cuda_bf16.h>
#include <cstdint>
#include <cstddef>

#define S_DIM 2048
#define E_DIM 1024
#define H_NUM 16
#define DH_DIM 64
#define B_NUM 2
#define BH_NUM (B_NUM * H_NUM)     // 32
#define M_ROWS (B_NUM * S_DIM)     // 4096
#define NROWS ((size_t)BH_NUM * S_DIM)  // 65536
#define NSEG 4

__device__ float g_q[(size_t)BH_NUM * S_DIM * DH_DIM];
__device__ float g_k[(size_t)BH_NUM * S_DIM * DH_DIM];
__device__ float g_v[(size_t)BH_NUM * S_DIM * DH_DIM];
__device__ float g_ctx[(size_t)M_ROWS * E_DIM];
__device__ float g_attn[(size_t)BH_NUM * S_DIM * S_DIM];   // fallback
__device__ float g_partial[32 * NROWS];                    // per-jblock row sums
__device__ float g_invl[NROWS];
__device__ float g_cpart[(size_t)NSEG * BH_NUM * S_DIM * DH_DIM];  // ctx split-K partials

// ---------------------------------------------------------------------------
// helpers
// ---------------------------------------------------------------------------
__device__ __forceinline__ uint32_t smem_u32(const void* p) {
    uint32_t a;
    asm("{ .reg .u64 t; cvta.to.shared.u64 t, %1; cvt.u32.u64 %0, t; }" : "=r"(a) : "l"(p));
    return a;
}
__device__ __forceinline__ void ldm4(uint32_t* r, uint32_t a) {
    asm volatile("ldmatrix.sync.aligned.m8n8.x4.shared.b16 {%0,%1,%2,%3}, [%4];"
        : "=r"(r[0]), "=r"(r[1]), "=r"(r[2]), "=r"(r[3]) : "r"(a));
}
__device__ __forceinline__ void ldm4t(uint32_t* r, uint32_t a) {
    asm volatile("ldmatrix.sync.aligned.m8n8.x4.trans.shared.b16 {%0,%1,%2,%3}, [%4];"
        : "=r"(r[0]), "=r"(r[1]), "=r"(r[2]), "=r"(r[3]) : "r"(a));
}
__device__ __forceinline__ void mma_bf16(float* c, const uint32_t* a, uint32_t b0, uint32_t b1) {
    asm volatile(
        "mma.sync.aligned.m16n8k16.row.col.f32.bf16.bf16.f32 "
        "{%0,%1,%2,%3}, {%4,%5,%6,%7}, {%8,%9}, {%0,%1,%2,%3};"
        : "+f"(c[0]), "+f"(c[1]), "+f"(c[2]), "+f"(c[3])
        : "r"(a[0]), "r"(a[1]), "r"(a[2]), "r"(a[3]), "r"(b0), "r"(b1));
}
__device__ __forceinline__ uint32_t swp128(int row, int c2) { return (uint32_t)(row * 128 + c2) ^ ((row & 7) << 4); }
__device__ __forceinline__ uint32_t swp64 (int row, int c2) { return (uint32_t)(row * 64  + c2) ^ (((row >> 1) & 3) << 4); }
__device__ __forceinline__ uint32_t swp256(int row, int c2) { return (uint32_t)(row * 256 + c2) ^ ((row & 7) << 4); }

__device__ __forceinline__ void split8(const float* v, uint32_t* hi, uint32_t* lo) {
#pragma unroll
    for (int q = 0; q < 4; q++) {
        __nv_bfloat16 h0 = __float2bfloat16(v[2*q]);
        __nv_bfloat16 h1 = __float2bfloat16(v[2*q+1]);
        __nv_bfloat16 l0 = __float2bfloat16(v[2*q]   - __bfloat162float(h0));
        __nv_bfloat16 l1 = __float2bfloat16(v[2*q+1] - __bfloat162float(h1));
        hi[q] = (uint32_t)__bfloat16_as_ushort(h0) | ((uint32_t)__bfloat16_as_ushort(h1) << 16);
        lo[q] = (uint32_t)__bfloat16_as_ushort(l0) | ((uint32_t)__bfloat16_as_ushort(l1) << 16);
    }
}

// ---------------------------------------------------------------------------
// loaders
// ---------------------------------------------------------------------------
// 128 rows x 64 cols, pitch 128
__device__ __forceinline__ void load_t128_64(const float* g, int ld, char* sm,
                                             int ohi, int olo, int tid) {
    int row = tid >> 1, c0 = (tid & 1) * 32;
    const float* p = g + (size_t)row * ld + c0;
#pragma unroll
    for (int gi = 0; gi < 4; gi++) {
        float v[8];
        *(float4*)(v)     = *(const float4*)(p + gi * 8);
        *(float4*)(v + 4) = *(const float4*)(p + gi * 8 + 4);
        uint32_t hi[4], lo[4];
        split8(v, hi, lo);
        uint32_t sw = swp128(row, (c0 + gi * 8) * 2);
        *(uint4*)(sm + ohi + sw) = make_uint4(hi[0], hi[1], hi[2], hi[3]);
        *(uint4*)(sm + olo + sw) = make_uint4(lo[0], lo[1], lo[2], lo[3]);
    }
}
// 64 rows x 64 cols, pitch 128
__device__ __forceinline__ void load_t64_64(const float* g, int ld, char* sm,
                                            int ohi, int olo, int tid) {
    int row = tid >> 2, c0 = (tid & 3) * 16;
    const float* p = g + (size_t)row * ld + c0;
#pragma unroll
    for (int gi = 0; gi < 2; gi++) {
        float v[8];
        *(float4*)(v)     = *(const float4*)(p + gi * 8);
        *(float4*)(v + 4) = *(const float4*)(p + gi * 8 + 4);
        uint32_t hi[4], lo[4];
        split8(v, hi, lo);
        uint32_t sw = swp128(row, (c0 + gi * 8) * 2);
        *(uint4*)(sm + ohi + sw) = make_uint4(hi[0], hi[1], hi[2], hi[3]);
        *(uint4*)(sm + olo + sw) = make_uint4(lo[0], lo[1], lo[2], lo[3]);
    }
}
// 128 rows x 32 cols, pitch 64 (proj A tile)
__device__ __forceinline__ void load_t128_32(const float* g, int ld, char* sm,
                                             int ohi, int olo, int tid) {
    int row = tid >> 1, c0 = (tid & 1) * 16;
    const float* p = g + (size_t)row * ld + c0;
#pragma unroll
    for (int gi = 0; gi < 2; gi++) {
        float v[8];
        *(float4*)(v)     = *(const float4*)(p + gi * 8);
        *(float4*)(v + 4) = *(const float4*)(p + gi * 8 + 4);
        uint32_t hi[4], lo[4];
        split8(v, hi, lo);
        uint32_t sw = swp64(row, (c0 + gi * 8) * 2);
        *(uint4*)(sm + ohi + sw) = make_uint4(hi[0], hi[1], hi[2], hi[3]);
        *(uint4*)(sm + olo + sw) = make_uint4(lo[0], lo[1], lo[2], lo[3]);
    }
}
// 128x32 p tile: scale, write back normalized, stage hi/lo
__device__ __forceinline__ void load_p32(float* g, int ld, float scale, char* sm,
                                         int ohi, int olo, int tid) {
    int row = tid >> 1, c0 = (tid & 1) * 16;
    float* p = g + (size_t)row * ld + c0;
#pragma unroll
    for (int gi = 0; gi < 2; gi++) {
        float v[8];
        *(float4*)(v)     = *(const float4*)(p + gi * 8);
        *(float4*)(v + 4) = *(const float4*)(p + gi * 8 + 4);
#pragma unroll
        for (int q = 0; q < 8; q++) v[q] *= scale;
        *(float4*)(p + gi * 8)     = *(float4*)(v);
        *(float4*)(p + gi * 8 + 4) = *(float4*)(v + 4);
        uint32_t hi[4], lo[4];
        split8(v, hi, lo);
        uint32_t sw = swp64(row, (c0 + gi * 8) * 2);
        *(uint4*)(sm + ohi + sw) = make_uint4(hi[0], hi[1], hi[2], hi[3]);
        *(uint4*)(sm + olo + sw) = make_uint4(lo[0], lo[1], lo[2], lo[3]);
    }
}
// W chunk: 32 k-rows x 128 n-cols, pitch 256
__device__ __forceinline__ void load_w32(const float* W, int n0, int k0, char* sm,
                                         int ohi, int olo, int tid) {
    int krow = tid >> 3, nseg = (tid & 7) * 16;
    const float* p = W + (size_t)(k0 + krow) * E_DIM + n0 + nseg;
#pragma unroll
    for (int gi = 0; gi < 2; gi++) {
        float v[8];
        *(float4*)(v)     = *(const float4*)(p + gi * 8);
        *(float4*)(v + 4) = *(const float4*)(p + gi * 8 + 4);
        uint32_t hi[4], lo[4];
        split8(v, hi, lo);
        uint32_t sw = swp256(krow, (nseg + gi * 8) * 2);
        *(uint4*)(sm + ohi + sw) = make_uint4(hi[0], hi[1], hi[2], hi[3]);
        *(uint4*)(sm + olo + sw) = make_uint4(lo[0], lo[1], lo[2], lo[3]);
    }
}
// V chunk: 32 j-rows x 64 d-cols, pitch 128
__device__ __forceinline__ void load_v32(const float* V, char* sm,
                                         int ohi, int olo, int tid) {
    int row = tid >> 3, c0 = (tid & 7) * 8;
    const float* p = V + (size_t)row * DH_DIM + c0;
    float v[8];
    *(float4*)(v)     = *(const float4*)(p);
    *(float4*)(v + 4) = *(const float4*)(p + 4);
    uint32_t hi[4], lo[4];
    split8(v, hi, lo);
    uint32_t sw = swp128(row, c0 * 2);
    *(uint4*)(sm + ohi + sw) = make_uint4(hi[0], hi[1], hi[2], hi[3]);
    *(uint4*)(sm + olo + sw) = make_uint4(lo[0], lo[1], lo[2], lo[3]);
}

// ---------------------------------------------------------------------------
// Projection GEMM (as R6): QKV fused via blockIdx.z. KC=32, 64KB double-buffered.
// ---------------------------------------------------------------------------
#define PROJ_SMEM 65536
__global__ void __launch_bounds__(256) proj_mma(
    const float* __restrict__ A,
    const float* __restrict__ W0, const float* __restrict__ W1, const float* __restrict__ W2,
    const float* __restrict__ b0p, const float* __restrict__ b1p, const float* __restrict__ b2p,
    float* __restrict__ o0, float* __restrict__ o1, float* __restrict__ o2, int mode)
{
    extern __shared__ char sm[];
    uint32_t sb = smem_u32(sm);
    int zz = blockIdx.z;
    const float* W    = zz == 0 ? W0 : (zz == 1 ? W1 : W2);
    const float* bias = zz == 0 ? b0p : (zz == 1 ? b1p : b2p);
    float* out        = zz == 0 ? o0 : (zz == 1 ? o1 : o2);

    int tid = threadIdx.x, lane = tid & 31, wid = tid >> 5;
    int warp_m = wid & 3, warp_n = wid >> 2;
    int n0 = blockIdx.x * 128, m0 = blockIdx.y * 128;
    int lrow = lane & 7, grp = lane >> 3;

    float acc[16][4] = {};
    load_t128_32(A + (size_t)m0 * E_DIM, E_DIM, sm, 0, 8192, tid);
    load_w32(W, n0, 0, sm, 16384, 24576, tid);
    __syncthreads();

    for (int c = 0; c < 32; c++) {
        int cur = (c & 1) * 32768;
        if (c < 31) {
            int nb = ((c + 1) & 1) * 32768;
            load_t128_32(A + (size_t)m0 * E_DIM + (c + 1) * 32, E_DIM, sm, nb, nb + 8192, tid);
            load_w32(W, n0, (c + 1) * 32, sm, nb + 16384, nb + 24576, tid);
        }
        uint32_t sa_hi = sb + cur, sa_lo = sb + cur + 8192;
        uint32_t sw_hi = sb + cur + 16384, sw_lo = sb + cur + 24576;
#pragma unroll
        for (int ks = 0; ks < 2; ks++) {
            int k = ks * 16;
            uint32_t ah[2][4], al[2][4];
#pragma unroll
            for (int mt = 0; mt < 2; mt++) {
                int row = warp_m * 32 + mt * 16 + lrow + (grp & 1) * 8;
                uint32_t off = swp64(row, (k + (grp >> 1) * 8) * 2);
                ldm4(ah[mt], sa_hi + off);
                ldm4(al[mt], sa_lo + off);
            }
#pragma unroll
            for (int nh = 0; nh < 4; nh++) {
                int krow = k + (lane & 15);
                int ncol = warp_n * 64 + nh * 16 + (lane >> 4) * 8;
                uint32_t offb = swp256(krow, ncol * 2);
                uint32_t bh[4], bl[4];
                ldm4t(bh, sw_hi + offb);
                ldm4t(bl, sw_lo + offb);
#pragma unroll
                for (int mt = 0; mt < 2; mt++) {
                    float* c0a = acc[mt * 8 + nh * 2];
                    float* c1a = acc[mt * 8 + nh * 2 + 1];
                    mma_bf16(c0a, ah[mt], bh[0], bh[1]);
                    mma_bf16(c1a, ah[mt], bh[2], bh[3]);
                    mma_bf16(c0a, ah[mt], bl[0], bl[1]);
                    mma_bf16(c1a, ah[mt], bl[2], bl[3]);
                    mma_bf16(c0a, al[mt], bh[0], bh[1]);
                    mma_bf16(c1a, al[mt], bh[2], bh[3]);
                }
            }
        }
        __syncthreads();
    }

    int crow = lane >> 2, cc = (lane & 3) * 2;
#pragma unroll
    for (int mt = 0; mt < 2; mt++) {
#pragma unroll
        for (int t8 = 0; t8 < 8; t8++) {
            const float* c = acc[mt * 8 + t8];
            int n = n0 + warp_n * 64 + t8 * 8 + cc;
            int r0 = m0 + warp_m * 32 + mt * 16 + crow;
            float bb0 = bias[n], bb1 = bias[n + 1];
            if (mode == 2) {
                *(float2*)(out + (size_t)r0 * E_DIM + n)       = make_float2(c[0] + bb0, c[1] + bb1);
                *(float2*)(out + (size_t)(r0 + 8) * E_DIM + n) = make_float2(c[2] + bb0, c[3] + bb1);
            } else {
                int h = n >> 6, d = n & 63;
#pragma unroll
                for (int rr = 0; rr < 2; rr++) {
                    int m = r0 + rr * 8;
                    int b = m >> 11, s = m & (S_DIM - 1);
                    float* p = out + (((size_t)(b * H_NUM + h) * S_DIM + s) << 6) + d;
                    *(float2*)p = make_float2(c[2 * rr] + bb0, c[2 * rr + 1] + bb1);
                }
            }
        }
    }
}

// ---------------------------------------------------------------------------
// Logits + exp + partial row sums. CTA tile 128(i) x 64(j) to cut regs/smem.
// grid (32, 16, 32): (j-block, i-block, z). 256 threads.
// ---------------------------------------------------------------------------
#define LOG_SMEM (49152 + 1024)
__global__ void __launch_bounds__(256) logits_mma(
    const float* __restrict__ Q, const float* __restrict__ Kmat,
    const float* __restrict__ mask, float* __restrict__ attn,
    float* __restrict__ partial)
{
    extern __shared__ char sm[];
    uint32_t sb = smem_u32(sm);
    float* sums = (float*)(sm + 49152);   // [128][2]
    int tid = threadIdx.x, lane = tid & 31, wid = tid >> 5;
    int warp_m = wid & 3, warp_n = wid >> 2;   // warp_n in {0,1}
    int z = blockIdx.z;
    int i0 = blockIdx.y * 128, j0 = blockIdx.x * 64;
    const float* Qb = Q + (size_t)z * S_DIM * DH_DIM;
    const float* Kb = Kmat + (size_t)z * S_DIM * DH_DIM;
    const float* mb = mask + (size_t)(z >> 4) * S_DIM;
    int lrow = lane & 7, grp = lane >> 3;

    load_t128_64(Qb + (size_t)i0 * DH_DIM, DH_DIM, sm, 0, 16384, tid);
    load_t64_64(Kb + (size_t)j0 * DH_DIM, DH_DIM, sm, 32768, 40960, tid);
    __syncthreads();

    float acc[8][4] = {};
    {
        uint32_t sa_hi = sb, sa_lo = sb + 16384, sk_hi = sb + 32768, sk_lo = sb + 40960;
#pragma unroll
        for (int ks = 0; ks < 4; ks++) {
            int k = ks * 16;
            uint32_t ah[2][4], al[2][4];
#pragma unroll
            for (int mt = 0; mt < 2; mt++) {
                int row = warp_m * 32 + mt * 16 + lrow + (grp & 1) * 8;
                uint32_t off = swp128(row, (k + (grp >> 1) * 8) * 2);
                ldm4(ah[mt], sa_hi + off);
                ldm4(al[mt], sa_lo + off);
            }
#pragma unroll
            for (int nh = 0; nh < 2; nh++) {
                int rowb = warp_n * 32 + nh * 16 + lrow + ((grp >> 1) & 1) * 8;
                uint32_t offb = swp128(rowb, (k + (grp & 1) * 8) * 2);
                uint32_t bh[4], bl[4];
                ldm4(bh, sk_hi + offb);
                ldm4(bl, sk_lo + offb);
#pragma unroll
                for (int mt = 0; mt < 2; mt++) {
                    float* c0a = acc[mt * 4 + nh * 2];
                    float* c1a = acc[mt * 4 + nh * 2 + 1];
                    mma_bf16(c0a, ah[mt], bh[0], bh[1]);
                    mma_bf16(c1a, ah[mt], bh[2], bh[3]);
                    mma_bf16(c0a, ah[mt], bl[0], bl[1]);
                    mma_bf16(c1a, ah[mt], bl[2], bl[3]);
                    mma_bf16(c0a, al[mt], bh[0], bh[1]);
                    mma_bf16(c1a, al[mt], bh[2], bh[3]);
                }
            }
        }
    }

    int crow = lane >> 2, cc = (lane & 3) * 2;
    float rsum[4] = {0.f, 0.f, 0.f, 0.f};
#pragma unroll
    for (int mt = 0; mt < 2; mt++) {
#pragma unroll
        for (int t8 = 0; t8 < 4; t8++) {
            float* c = acc[mt * 4 + t8];
            int j = j0 + warp_n * 32 + t8 * 8 + cc;
            int i = i0 + warp_m * 32 + mt * 16 + crow;
            float m0v = 1e9f * mb[j], m1v = 1e9f * mb[j + 1];
            float p00 = __expf(c[0] * 0.125f - m0v);
            float p01 = __expf(c[1] * 0.125f - m1v);
            float p10 = __expf(c[2] * 0.125f - m0v);
            float p11 = __expf(c[3] * 0.125f - m1v);
            *(float2*)(attn + ((size_t)z * S_DIM + i) * S_DIM + j)     = make_float2(p00, p01);
            *(float2*)(attn + ((size_t)z * S_DIM + i + 8) * S_DIM + j) = make_float2(p10, p11);
            rsum[mt * 2]     += p00 + p01;
            rsum[mt * 2 + 1] += p10 + p11;
        }
    }
#pragma unroll
    for (int q = 0; q < 4; q++) {
        rsum[q] += __shfl_xor_sync(0xFFFFFFFFu, rsum[q], 1);
        rsum[q] += __shfl_xor_sync(0xFFFFFFFFu, rsum[q], 2);
    }
    if ((lane & 3) == 0) {
#pragma unroll
        for (int q = 0; q < 4; q++) {
            int lr = warp_m * 32 + (q >> 1) * 16 + crow + (q & 1) * 8;
            sums[lr * 2 + warp_n] = rsum[q];
        }
    }
    __syncthreads();
    if (tid < 128) {
        float s = sums[tid * 2] + sums[tid * 2 + 1];
        partial[(size_t)blockIdx.x * NROWS + ((size_t)z << 11) + i0 + tid] = s;
    }
}

// inv_l[r] = 1 / sum_jb partial[jb][r]
__global__ void __launch_bounds__(256) reduce_inv(const float* __restrict__ partial,
                                                  float* __restrict__ invl)
{
    int r = blockIdx.x * 256 + threadIdx.x;
    float s = 0.f;
#pragma unroll
    for (int jb = 0; jb < 32; jb++) s += partial[(size_t)jb * NROWS + r];
    invl[r] = 1.0f / s;
}

// ---------------------------------------------------------------------------
// ctx split-K: grid (16 i-blk, 4 seg, 32 z). Each CTA K-range = seg*512..+512.
// Normalizes its j-range of attn (write-back) and emits partial [seg][z][s][d].
// ---------------------------------------------------------------------------
#define CTX_SMEM 49152
__global__ void __launch_bounds__(256) ctx_mma(
    float* __restrict__ attn, const float* __restrict__ V,
    const float* __restrict__ invl, float* __restrict__ cpart)
{
    extern __shared__ char sm[];
    uint32_t sb = smem_u32(sm);
    int tid = threadIdx.x, lane = tid & 31, wid = tid >> 5;
    int warp_m = wid & 3, warp_n = wid >> 2;
    int z = blockIdx.z, i0 = blockIdx.x * 128, seg = blockIdx.y;
    float* Ab = attn + ((size_t)z * S_DIM + i0) * S_DIM + seg * 512;
    const float* Vb = V + ((size_t)z * S_DIM + seg * 512) * DH_DIM;
    int lrow = lane & 7, grp = lane >> 3;
    float scale = invl[((size_t)z << 11) + i0 + (tid >> 1)];

    float acc[8][4] = {};
    load_p32(Ab, S_DIM, scale, sm, 0, 8192, tid);
    load_v32(Vb, sm, 16384, 20480, tid);
    __syncthreads();

    for (int c = 0; c < 16; c++) {
        int cur = (c & 1) * 24576;
        if (c < 15) {
            int nb = ((c + 1) & 1) * 24576;
            load_p32(Ab + (c + 1) * 32, S_DIM, scale, sm, nb, nb + 8192, tid);
            load_v32(Vb + (size_t)(c + 1) * 32 * DH_DIM, sm, nb + 16384, nb + 20480, tid);
        }
        uint32_t sa_hi = sb + cur, sa_lo = sb + cur + 8192;
        uint32_t sv_hi = sb + cur + 16384, sv_lo = sb + cur + 20480;
#pragma unroll
        for (int ks = 0; ks < 2; ks++) {
            int k = ks * 16;
            uint32_t ah[2][4], al[2][4];
#pragma unroll
            for (int mt = 0; mt < 2; mt++) {
                int row = warp_m * 32 + mt * 16 + lrow + (grp & 1) * 8;
                uint32_t off = swp64(row, (k + (grp >> 1) * 8) * 2);
                ldm4(ah[mt], sa_hi + off);
                ldm4(al[mt], sa_lo + off);
            }
#pragma unroll
            for (int nh = 0; nh < 2; nh++) {
                int krow = k + (lane & 15);
                int ncol = warp_n * 32 + nh * 16 + (lane >> 4) * 8;
                uint32_t offb = swp128(krow, ncol * 2);
                uint32_t bh[4], bl[4];
                ldm4t(bh, sv_hi + offb);
                ldm4t(bl, sv_lo + offb);
#pragma unroll
                for (int mt = 0; mt < 2; mt++) {
                    float* c0a = acc[mt * 4 + nh * 2];
                    float* c1a = acc[mt * 4 + nh * 2 + 1];
                    mma_bf16(c0a, ah[mt], bh[0], bh[1]);
                    mma_bf16(c1a, ah[mt], bh[2], bh[3]);
                    mma_bf16(c0a, ah[mt], bl[0], bl[1]);
                    mma_bf16(c1a, ah[mt], bl[2], bl[3]);
                    mma_bf16(c0a, al[mt], bh[0], bh[1]);
                    mma_bf16(c1a, al[mt], bh[2], bh[3]);
                }
            }
        }
        __syncthreads();
    }

    float* outp = cpart + (((size_t)seg * BH_NUM + z) * S_DIM) * DH_DIM;
    int crow = lane >> 2, cc = (lane & 3) * 2;
#pragma unroll
    for (int mt = 0; mt < 2; mt++) {
#pragma unroll
        for (int t8 = 0; t8 < 4; t8++) {
            const float* c = acc[mt * 4 + t8];
            int d = warp_n * 32 + t8 * 8 + cc;
            int s0 = i0 + warp_m * 32 + mt * 16 + crow;
            *(float2*)(outp + (size_t)s0 * DH_DIM + d)       = make_float2(c[0], c[1]);
            *(float2*)(outp + (size_t)(s0 + 8) * DH_DIM + d) = make_float2(c[2], c[3]);
        }
    }
}

// ctx[b,s,h*64+d] = sum_seg cpart[seg][z][s][d]
__global__ void __launch_bounds__(256) reduce_ctx(const float* __restrict__ cpart,
                                                   float* __restrict__ ctx)
{
    size_t id = (size_t)blockIdx.x * 256 + threadIdx.x;   // over 4M elems
    int z = (int)(id >> 17);
    int rem = (int)(id & 0x1FFFF);
    int s = rem >> 6, d = rem & 63;
    const size_t stride = (size_t)BH_NUM * S_DIM * DH_DIM;
    size_t off = id;
    float v = cpart[off] + cpart[off + stride] + cpart[off + 2 * stride] + cpart[off + 3 * stride];
    int b = z >> 4, h = z & 15;
    ctx[(size_t)(b * S_DIM + s) * E_DIM + h * DH_DIM + d] = v;
}

// ---------------------------------------------------------------------------

extern "C" void kernel_launch(void* const* d_in, const int* in_sizes, int n_in,
                              void* d_out, int out_size)
{
    const float* features = (const float*)d_in[0];
    const float* mask     = (const float*)d_in[1];
    const float* Wq = (const float*)d_in[2];
    const float* bq = (const float*)d_in[3];
    const float* Wk = (const float*)d_in[4];
    const float* bk = (const float*)d_in[5];
    const float* Wv = (const float*)d_in[6];
    const float* bv = (const float*)d_in[7];
    const float* Wo = (const float*)d_in[8];
    const float* bo = (const float*)d_in[9];
    float* out = (float*)d_out;

    float *q, *k, *v, *ctx, *attn_scratch, *partial, *invl, *cpart;
    cudaGetSymbolAddress((void**)&q, g_q);
    cudaGetSymbolAddress((void**)&k, g_k);
    cudaGetSymbolAddress((void**)&v, g_v);
    cudaGetSymbolAddress((void**)&ctx, g_ctx);
    cudaGetSymbolAddress((void**)&attn_scratch, g_attn);
    cudaGetSymbolAddress((void**)&partial, g_partial);
    cudaGetSymbolAddress((void**)&invl, g_invl);
    cudaGetSymbolAddress((void**)&cpart, g_cpart);

    const long long OUT_ELEMS  = (long long)M_ROWS * E_DIM;
    const long long ATTN_ELEMS = (long long)BH_NUM * S_DIM * S_DIM;
    float* attn = ((long long)out_size >= OUT_ELEMS + ATTN_ELEMS)
                      ? (out + OUT_ELEMS) : attn_scratch;

    cudaFuncSetAttribute(proj_mma, cudaFuncAttributeMaxDynamicSharedMemorySize, PROJ_SMEM);
    cudaFuncSetAttribute(logits_mma, cudaFuncAttributeMaxDynamicSharedMemorySize, LOG_SMEM);
    cudaFuncSetAttribute(ctx_mma, cudaFuncAttributeMaxDynamicSharedMemorySize, CTX_SMEM);
    cudaFuncSetAttribute(proj_mma, cudaFuncAttributePreferredSharedMemoryCarveout, 100);
    cudaFuncSetAttribute(logits_mma, cudaFuncAttributePreferredSharedMemoryCarveout, 100);
    cudaFuncSetAttribute(ctx_mma, cudaFuncAttributePreferredSharedMemoryCarveout, 100);

    dim3 blk(256);
    proj_mma<<<dim3(8, 32, 3), blk, PROJ_SMEM>>>(features, Wq, Wk, Wv, bq, bk, bv, q, k, v, 0);
    logits_mma<<<dim3(32, 16, 32), blk, LOG_SMEM>>>(q, k, mask, attn, partial);
    reduce_inv<<<256, blk>>>(partial, invl);
    ctx_mma<<<dim3(16, NSEG, 32), blk, CTX_SMEM>>>(attn, v, invl, cpart);
    reduce_ctx<<<16384, blk>>>(cpart, ctx);
    proj_mma<<<dim3(8, 32, 1), blk, PROJ_SMEM>>>(ctx, Wo, Wo, Wo, bo, bo, bo, out, out, out, 2);
}

// round 8
// speedup vs baseline: 1.1790x; 1.1449x over previous
#include <cuda_runtime.h>
#include <cuda_bf16.h>
#include <cstdint>
#include <cstddef>

#define S_DIM 2048
#define E_DIM 1024
#define H_NUM 16
#define DH_DIM 64
#define B_NUM 2
#define BH_NUM (B_NUM * H_NUM)     // 32
#define M_ROWS (B_NUM * S_DIM)     // 4096

__device__ float g_q[(size_t)BH_NUM * S_DIM * DH_DIM];
__device__ float g_k[(size_t)BH_NUM * S_DIM * DH_DIM];
__device__ float g_v[(size_t)BH_NUM * S_DIM * DH_DIM];
__device__ float g_ctx[(size_t)M_ROWS * E_DIM];
__device__ float g_attn[(size_t)BH_NUM * S_DIM * S_DIM];   // fallback

// ---------------------------------------------------------------------------
// helpers
// ---------------------------------------------------------------------------
__device__ __forceinline__ uint32_t smem_u32(const void* p) {
    uint32_t a;
    asm("{ .reg .u64 t; cvta.to.shared.u64 t, %1; cvt.u32.u64 %0, t; }" : "=r"(a) : "l"(p));
    return a;
}
__device__ __forceinline__ void ldm4(uint32_t* r, uint32_t a) {
    asm volatile("ldmatrix.sync.aligned.m8n8.x4.shared.b16 {%0,%1,%2,%3}, [%4];"
        : "=r"(r[0]), "=r"(r[1]), "=r"(r[2]), "=r"(r[3]) : "r"(a));
}
__device__ __forceinline__ void ldm4t(uint32_t* r, uint32_t a) {
    asm volatile("ldmatrix.sync.aligned.m8n8.x4.trans.shared.b16 {%0,%1,%2,%3}, [%4];"
        : "=r"(r[0]), "=r"(r[1]), "=r"(r[2]), "=r"(r[3]) : "r"(a));
}
__device__ __forceinline__ void mma_bf16(float* c, const uint32_t* a, uint32_t b0, uint32_t b1) {
    asm volatile(
        "mma.sync.aligned.m16n8k16.row.col.f32.bf16.bf16.f32 "
        "{%0,%1,%2,%3}, {%4,%5,%6,%7}, {%8,%9}, {%0,%1,%2,%3};"
        : "+f"(c[0]), "+f"(c[1]), "+f"(c[2]), "+f"(c[3])
        : "r"(a[0]), "r"(a[1]), "r"(a[2]), "r"(a[3]), "r"(b0), "r"(b1));
}
__device__ __forceinline__ uint32_t swp128(int row, int c2) { return (uint32_t)(row * 128 + c2) ^ ((row & 7) << 4); }
__device__ __forceinline__ uint32_t swp64 (int row, int c2) { return (uint32_t)(row * 64  + c2) ^ (((row >> 1) & 3) << 4); }
__device__ __forceinline__ uint32_t swp256(int row, int c2) { return (uint32_t)(row * 256 + c2) ^ ((row & 7) << 4); }

__device__ __forceinline__ void split8(const float* v, uint32_t* hi, uint32_t* lo) {
#pragma unroll
    for (int q = 0; q < 4; q++) {
        __nv_bfloat16 h0 = __float2bfloat16(v[2*q]);
        __nv_bfloat16 h1 = __float2bfloat16(v[2*q+1]);
        __nv_bfloat16 l0 = __float2bfloat16(v[2*q]   - __bfloat162float(h0));
        __nv_bfloat16 l1 = __float2bfloat16(v[2*q+1] - __bfloat162float(h1));
        hi[q] = (uint32_t)__bfloat16_as_ushort(h0) | ((uint32_t)__bfloat16_as_ushort(h1) << 16);
        lo[q] = (uint32_t)__bfloat16_as_ushort(l0) | ((uint32_t)__bfloat16_as_ushort(l1) << 16);
    }
}
__device__ __forceinline__ uint32_t pack_hilo(float a, float b, uint32_t& lo) {
    __nv_bfloat16 ha = __float2bfloat16(a), hb = __float2bfloat16(b);
    __nv_bfloat16 la = __float2bfloat16(a - __bfloat162float(ha));
    __nv_bfloat16 lb = __float2bfloat16(b - __bfloat162float(hb));
    lo = (uint32_t)__bfloat16_as_ushort(la) | ((uint32_t)__bfloat16_as_ushort(lb) << 16);
    return (uint32_t)__bfloat16_as_ushort(ha) | ((uint32_t)__bfloat16_as_ushort(hb) << 16);
}

// ---------------------------------------------------------------------------
// loaders (fp32 gmem -> bf16 hi/lo swizzled smem)
// ---------------------------------------------------------------------------
// 128 rows x 64 cols, pitch 128
__device__ __forceinline__ void load_t128_64(const float* g, int ld, char* sm,
                                             int ohi, int olo, int tid) {
    int row = tid >> 1, c0 = (tid & 1) * 32;
    const float* p = g + (size_t)row * ld + c0;
#pragma unroll
    for (int gi = 0; gi < 4; gi++) {
        float v[8];
        *(float4*)(v)     = *(const float4*)(p + gi * 8);
        *(float4*)(v + 4) = *(const float4*)(p + gi * 8 + 4);
        uint32_t hi[4], lo[4];
        split8(v, hi, lo);
        uint32_t sw = swp128(row, (c0 + gi * 8) * 2);
        *(uint4*)(sm + ohi + sw) = make_uint4(hi[0], hi[1], hi[2], hi[3]);
        *(uint4*)(sm + olo + sw) = make_uint4(lo[0], lo[1], lo[2], lo[3]);
    }
}
// 64 rows x 64 cols, pitch 128
__device__ __forceinline__ void load_t64_64(const float* g, int ld, char* sm,
                                            int ohi, int olo, int tid) {
    int row = tid >> 2, c0 = (tid & 3) * 16;
    const float* p = g + (size_t)row * ld + c0;
#pragma unroll
    for (int gi = 0; gi < 2; gi++) {
        float v[8];
        *(float4*)(v)     = *(const float4*)(p + gi * 8);
        *(float4*)(v + 4) = *(const float4*)(p + gi * 8 + 4);
        uint32_t hi[4], lo[4];
        split8(v, hi, lo);
        uint32_t sw = swp128(row, (c0 + gi * 8) * 2);
        *(uint4*)(sm + ohi + sw) = make_uint4(hi[0], hi[1], hi[2], hi[3]);
        *(uint4*)(sm + olo + sw) = make_uint4(lo[0], lo[1], lo[2], lo[3]);
    }
}
// 128 rows x 32 cols, pitch 64 (proj A tile)
__device__ __forceinline__ void load_t128_32(const float* g, int ld, char* sm,
                                             int ohi, int olo, int tid) {
    int row = tid >> 1, c0 = (tid & 1) * 16;
    const float* p = g + (size_t)row * ld + c0;
#pragma unroll
    for (int gi = 0; gi < 2; gi++) {
        float v[8];
        *(float4*)(v)     = *(const float4*)(p + gi * 8);
        *(float4*)(v + 4) = *(const float4*)(p + gi * 8 + 4);
        uint32_t hi[4], lo[4];
        split8(v, hi, lo);
        uint32_t sw = swp64(row, (c0 + gi * 8) * 2);
        *(uint4*)(sm + ohi + sw) = make_uint4(hi[0], hi[1], hi[2], hi[3]);
        *(uint4*)(sm + olo + sw) = make_uint4(lo[0], lo[1], lo[2], lo[3]);
    }
}
// W chunk: 32 k-rows x 128 n-cols, pitch 256
__device__ __forceinline__ void load_w32(const float* W, int n0, int k0, char* sm,
                                         int ohi, int olo, int tid) {
    int krow = tid >> 3, nseg = (tid & 7) * 16;
    const float* p = W + (size_t)(k0 + krow) * E_DIM + n0 + nseg;
#pragma unroll
    for (int gi = 0; gi < 2; gi++) {
        float v[8];
        *(float4*)(v)     = *(const float4*)(p + gi * 8);
        *(float4*)(v + 4) = *(const float4*)(p + gi * 8 + 4);
        uint32_t hi[4], lo[4];
        split8(v, hi, lo);
        uint32_t sw = swp256(krow, (nseg + gi * 8) * 2);
        *(uint4*)(sm + ohi + sw) = make_uint4(hi[0], hi[1], hi[2], hi[3]);
        *(uint4*)(sm + olo + sw) = make_uint4(lo[0], lo[1], lo[2], lo[3]);
    }
}

// ---------------------------------------------------------------------------
// Projection GEMM: QKV fused via blockIdx.z. KC=32, 64KB double-buffered.
// ---------------------------------------------------------------------------
#define PROJ_SMEM 65536
__global__ void __launch_bounds__(256) proj_mma(
    const float* __restrict__ A,
    const float* __restrict__ W0, const float* __restrict__ W1, const float* __restrict__ W2,
    const float* __restrict__ b0p, const float* __restrict__ b1p, const float* __restrict__ b2p,
    float* __restrict__ o0, float* __restrict__ o1, float* __restrict__ o2, int mode)
{
    extern __shared__ char sm[];
    uint32_t sb = smem_u32(sm);
    int zz = blockIdx.z;
    const float* W    = zz == 0 ? W0 : (zz == 1 ? W1 : W2);
    const float* bias = zz == 0 ? b0p : (zz == 1 ? b1p : b2p);
    float* out        = zz == 0 ? o0 : (zz == 1 ? o1 : o2);

    int tid = threadIdx.x, lane = tid & 31, wid = tid >> 5;
    int warp_m = wid & 3, warp_n = wid >> 2;
    int n0 = blockIdx.x * 128, m0 = blockIdx.y * 128;
    int lrow = lane & 7, grp = lane >> 3;

    float acc[16][4] = {};
    load_t128_32(A + (size_t)m0 * E_DIM, E_DIM, sm, 0, 8192, tid);
    load_w32(W, n0, 0, sm, 16384, 24576, tid);
    __syncthreads();

    for (int c = 0; c < 32; c++) {
        int cur = (c & 1) * 32768;
        if (c < 31) {
            int nb = ((c + 1) & 1) * 32768;
            load_t128_32(A + (size_t)m0 * E_DIM + (c + 1) * 32, E_DIM, sm, nb, nb + 8192, tid);
            load_w32(W, n0, (c + 1) * 32, sm, nb + 16384, nb + 24576, tid);
        }
        uint32_t sa_hi = sb + cur, sa_lo = sb + cur + 8192;
        uint32_t sw_hi = sb + cur + 16384, sw_lo = sb + cur + 24576;
#pragma unroll
        for (int ks = 0; ks < 2; ks++) {
            int k = ks * 16;
            uint32_t ah[2][4], al[2][4];
#pragma unroll
            for (int mt = 0; mt < 2; mt++) {
                int row = warp_m * 32 + mt * 16 + lrow + (grp & 1) * 8;
                uint32_t off = swp64(row, (k + (grp >> 1) * 8) * 2);
                ldm4(ah[mt], sa_hi + off);
                ldm4(al[mt], sa_lo + off);
            }
#pragma unroll
            for (int nh = 0; nh < 4; nh++) {
                int krow = k + (lane & 15);
                int ncol = warp_n * 64 + nh * 16 + (lane >> 4) * 8;
                uint32_t offb = swp256(krow, ncol * 2);
                uint32_t bh[4], bl[4];
                ldm4t(bh, sw_hi + offb);
                ldm4t(bl, sw_lo + offb);
#pragma unroll
                for (int mt = 0; mt < 2; mt++) {
                    float* c0a = acc[mt * 8 + nh * 2];
                    float* c1a = acc[mt * 8 + nh * 2 + 1];
                    mma_bf16(c0a, ah[mt], bh[0], bh[1]);
                    mma_bf16(c1a, ah[mt], bh[2], bh[3]);
                    mma_bf16(c0a, ah[mt], bl[0], bl[1]);
                    mma_bf16(c1a, ah[mt], bl[2], bl[3]);
                    mma_bf16(c0a, al[mt], bh[0], bh[1]);
                    mma_bf16(c1a, al[mt], bh[2], bh[3]);
                }
            }
        }
        __syncthreads();
    }

    int crow = lane >> 2, cc = (lane & 3) * 2;
#pragma unroll
    for (int mt = 0; mt < 2; mt++) {
#pragma unroll
        for (int t8 = 0; t8 < 8; t8++) {
            const float* c = acc[mt * 8 + t8];
            int n = n0 + warp_n * 64 + t8 * 8 + cc;
            int r0 = m0 + warp_m * 32 + mt * 16 + crow;
            float bb0 = bias[n], bb1 = bias[n + 1];
            if (mode == 2) {
                *(float2*)(out + (size_t)r0 * E_DIM + n)       = make_float2(c[0] + bb0, c[1] + bb1);
                *(float2*)(out + (size_t)(r0 + 8) * E_DIM + n) = make_float2(c[2] + bb0, c[3] + bb1);
            } else {
                int h = n >> 6, d = n & 63;
#pragma unroll
                for (int rr = 0; rr < 2; rr++) {
                    int m = r0 + rr * 8;
                    int b = m >> 11, s = m & (S_DIM - 1);
                    float* p = out + (((size_t)(b * H_NUM + h) * S_DIM + s) << 6) + d;
                    *(float2*)p = make_float2(c[2 * rr] + bb0, c[2 * rr + 1] + bb1);
                }
            }
        }
    }
}

// ---------------------------------------------------------------------------
// Fused attention: per (i-block 128, z). Two passes over j (chunks of 64).
// Pass 1: S=QK^T, exp, row sums (registers only).
// Pass 2: recompute S, p = exp*inv_l, write attn (final), ctx += p @ V.
// Each warp owns 16 i-rows. 8 warps = 128 rows. grid (16, 32), 256 thr.
// smem: [0,64KB) K/V double buffers (Q staged at start), [64KB,72KB) -1e9*mask.
// ---------------------------------------------------------------------------
#define FA_SMEM (65536 + 8192)
__global__ void __launch_bounds__(256) fused_attn(
    const float* __restrict__ Q, const float* __restrict__ Kmat,
    const float* __restrict__ V, const float* __restrict__ mask,
    float* __restrict__ attn, float* __restrict__ ctx)
{
    extern __shared__ char sm[];
    uint32_t sb = smem_u32(sm);
    float* mrow = (float*)(sm + 65536);
    int tid = threadIdx.x, lane = tid & 31, wid = tid >> 5;
    int z = blockIdx.y, i0 = blockIdx.x * 128;
    const float* Qb = Q + ((size_t)z * S_DIM + i0) * DH_DIM;
    const float* Kb = Kmat + (size_t)z * S_DIM * DH_DIM;
    const float* Vb = V + (size_t)z * S_DIM * DH_DIM;
    const float* mb = mask + (size_t)(z >> 4) * S_DIM;
    int lrow = lane & 7, grp = lane >> 3;
    int g = lane >> 2, cc = (lane & 3) * 2;

    for (int t = tid; t < S_DIM; t += 256) mrow[t] = -1e9f * mb[t];
    load_t128_64(Qb, DH_DIM, sm, 0, 16384, tid);
    __syncthreads();

    // Q fragments (A operand), rows wid*16..+16, 4 k16 chunks
    uint32_t qh[4][4], ql[4][4];
#pragma unroll
    for (int t = 0; t < 4; t++) {
        int row = wid * 16 + lrow + (grp & 1) * 8;
        uint32_t off = swp128(row, (t * 16 + (grp >> 1) * 8) * 2);
        ldm4(qh[t], sb + off);
        ldm4(ql[t], sb + 16384 + off);
    }
    __syncthreads();

    // ---------------- pass 1: row sums ----------------
    float rsum0 = 0.f, rsum1 = 0.f;
    load_t64_64(Kb, DH_DIM, sm, 0, 8192, tid);
    __syncthreads();
    for (int c = 0; c < 32; c++) {
        int cur = (c & 1) * 32768;
        if (c < 31) {
            int nb = ((c + 1) & 1) * 32768;
            load_t64_64(Kb + (size_t)(c + 1) * 64 * DH_DIM, DH_DIM, sm, nb, nb + 8192, tid);
        }
        uint32_t kh_base = sb + cur, kl_base = sb + cur + 8192;
        float sc[8][4] = {};
#pragma unroll
        for (int t = 0; t < 4; t++) {
#pragma unroll
            for (int nt = 0; nt < 4; nt++) {
                int rowb = nt * 16 + lrow + ((grp >> 1) & 1) * 8;
                uint32_t offb = swp128(rowb, (t * 16 + (grp & 1) * 8) * 2);
                uint32_t bh[4], bl[4];
                ldm4(bh, kh_base + offb);
                ldm4(bl, kl_base + offb);
                float* c0a = sc[nt * 2];
                float* c1a = sc[nt * 2 + 1];
                mma_bf16(c0a, qh[t], bh[0], bh[1]);
                mma_bf16(c1a, qh[t], bh[2], bh[3]);
                mma_bf16(c0a, qh[t], bl[0], bl[1]);
                mma_bf16(c1a, qh[t], bl[2], bl[3]);
                mma_bf16(c0a, ql[t], bh[0], bh[1]);
                mma_bf16(c1a, ql[t], bh[2], bh[3]);
            }
        }
        int jb = c * 64;
#pragma unroll
        for (int t8 = 0; t8 < 8; t8++) {
            int j = jb + t8 * 8 + cc;
            float m0 = mrow[j], m1 = mrow[j + 1];
            rsum0 += __expf(sc[t8][0] * 0.125f + m0) + __expf(sc[t8][1] * 0.125f + m1);
            rsum1 += __expf(sc[t8][2] * 0.125f + m0) + __expf(sc[t8][3] * 0.125f + m1);
        }
        __syncthreads();
    }
    rsum0 += __shfl_xor_sync(0xFFFFFFFFu, rsum0, 1);
    rsum0 += __shfl_xor_sync(0xFFFFFFFFu, rsum0, 2);
    rsum1 += __shfl_xor_sync(0xFFFFFFFFu, rsum1, 1);
    rsum1 += __shfl_xor_sync(0xFFFFFFFFu, rsum1, 2);
    float inv0 = 1.0f / rsum0;
    float inv1 = 1.0f / rsum1;

    // ---------------- pass 2: attn + ctx ----------------
    int iRow = i0 + wid * 16 + g;
    float* attn0 = attn + ((size_t)z * S_DIM + iRow) * S_DIM;
    float* attn1 = attn0 + 8 * S_DIM;
    float cacc[8][4] = {};

    load_t64_64(Kb, DH_DIM, sm, 0, 8192, tid);
    load_t64_64(Vb, DH_DIM, sm, 16384, 24576, tid);
    __syncthreads();
    for (int c = 0; c < 32; c++) {
        int cur = (c & 1) * 32768;
        if (c < 31) {
            int nb = ((c + 1) & 1) * 32768;
            load_t64_64(Kb + (size_t)(c + 1) * 64 * DH_DIM, DH_DIM, sm, nb, nb + 8192, tid);
            load_t64_64(Vb + (size_t)(c + 1) * 64 * DH_DIM, DH_DIM, sm, nb + 16384, nb + 24576, tid);
        }
        uint32_t kh_base = sb + cur, kl_base = sb + cur + 8192;
        uint32_t vh_base = sb + cur + 16384, vl_base = sb + cur + 24576;
        float sc[8][4] = {};
#pragma unroll
        for (int t = 0; t < 4; t++) {
#pragma unroll
            for (int nt = 0; nt < 4; nt++) {
                int rowb = nt * 16 + lrow + ((grp >> 1) & 1) * 8;
                uint32_t offb = swp128(rowb, (t * 16 + (grp & 1) * 8) * 2);
                uint32_t bh[4], bl[4];
                ldm4(bh, kh_base + offb);
                ldm4(bl, kl_base + offb);
                float* c0a = sc[nt * 2];
                float* c1a = sc[nt * 2 + 1];
                mma_bf16(c0a, qh[t], bh[0], bh[1]);
                mma_bf16(c1a, qh[t], bh[2], bh[3]);
                mma_bf16(c0a, qh[t], bl[0], bl[1]);
                mma_bf16(c1a, qh[t], bl[2], bl[3]);
                mma_bf16(c0a, ql[t], bh[0], bh[1]);
                mma_bf16(c1a, ql[t], bh[2], bh[3]);
            }
        }
        // exp, normalize, write attn, pack p into A fragments
        uint32_t pah[4][4], pal[4][4];
        int jb = c * 64;
#pragma unroll
        for (int t8 = 0; t8 < 8; t8++) {
            int j = jb + t8 * 8 + cc;
            float m0 = mrow[j], m1 = mrow[j + 1];
            float p0 = __expf(sc[t8][0] * 0.125f + m0) * inv0;
            float p1 = __expf(sc[t8][1] * 0.125f + m1) * inv0;
            float p2 = __expf(sc[t8][2] * 0.125f + m0) * inv1;
            float p3 = __expf(sc[t8][3] * 0.125f + m1) * inv1;
            *(float2*)(attn0 + j) = make_float2(p0, p1);
            *(float2*)(attn1 + j) = make_float2(p2, p3);
            int t = t8 >> 1, hf = (t8 & 1) * 2;
            pah[t][hf]     = pack_hilo(p0, p1, pal[t][hf]);
            pah[t][hf + 1] = pack_hilo(p2, p3, pal[t][hf + 1]);
        }
        // ctx += p @ V
#pragma unroll
        for (int t = 0; t < 4; t++) {
#pragma unroll
            for (int dt = 0; dt < 4; dt++) {
                int krow = t * 16 + (lane & 15);
                int ncol = dt * 16 + (lane >> 4) * 8;
                uint32_t offb = swp128(krow, ncol * 2);
                uint32_t vh[4], vl[4];
                ldm4t(vh, vh_base + offb);
                ldm4t(vl, vl_base + offb);
                float* c0a = cacc[dt * 2];
                float* c1a = cacc[dt * 2 + 1];
                mma_bf16(c0a, pah[t], vh[0], vh[1]);
                mma_bf16(c1a, pah[t], vh[2], vh[3]);
                mma_bf16(c0a, pah[t], vl[0], vl[1]);
                mma_bf16(c1a, pah[t], vl[2], vl[3]);
                mma_bf16(c0a, pal[t], vh[0], vh[1]);
                mma_bf16(c1a, pal[t], vh[2], vh[3]);
            }
        }
        __syncthreads();
    }

    // ctx epilogue
    int b = z >> 4, h = z & 15;
#pragma unroll
    for (int t8 = 0; t8 < 8; t8++) {
        int d = t8 * 8 + cc;
        float* p0 = ctx + (size_t)(b * S_DIM + iRow) * E_DIM + h * DH_DIM + d;
        float* p1 = ctx + (size_t)(b * S_DIM + iRow + 8) * E_DIM + h * DH_DIM + d;
        *(float2*)p0 = make_float2(cacc[t8][0], cacc[t8][1]);
        *(float2*)p1 = make_float2(cacc[t8][2], cacc[t8][3]);
    }
}

// ---------------------------------------------------------------------------

extern "C" void kernel_launch(void* const* d_in, const int* in_sizes, int n_in,
                              void* d_out, int out_size)
{
    const float* features = (const float*)d_in[0];
    const float* mask     = (const float*)d_in[1];
    const float* Wq = (const float*)d_in[2];
    const float* bq = (const float*)d_in[3];
    const float* Wk = (const float*)d_in[4];
    const float* bk = (const float*)d_in[5];
    const float* Wv = (const float*)d_in[6];
    const float* bv = (const float*)d_in[7];
    const float* Wo = (const float*)d_in[8];
    const float* bo = (const float*)d_in[9];
    float* out = (float*)d_out;

    float *q, *k, *v, *ctx, *attn_scratch;
    cudaGetSymbolAddress((void**)&q, g_q);
    cudaGetSymbolAddress((void**)&k, g_k);
    cudaGetSymbolAddress((void**)&v, g_v);
    cudaGetSymbolAddress((void**)&ctx, g_ctx);
    cudaGetSymbolAddress((void**)&attn_scratch, g_attn);

    const long long OUT_ELEMS  = (long long)M_ROWS * E_DIM;
    const long long ATTN_ELEMS = (long long)BH_NUM * S_DIM * S_DIM;
    float* attn = ((long long)out_size >= OUT_ELEMS + ATTN_ELEMS)
                      ? (out + OUT_ELEMS) : attn_scratch;

    cudaFuncSetAttribute(proj_mma, cudaFuncAttributeMaxDynamicSharedMemorySize, PROJ_SMEM);
    cudaFuncSetAttribute(fused_attn, cudaFuncAttributeMaxDynamicSharedMemorySize, FA_SMEM);
    cudaFuncSetAttribute(proj_mma, cudaFuncAttributePreferredSharedMemoryCarveout, 100);
    cudaFuncSetAttribute(fused_attn, cudaFuncAttributePreferredSharedMemoryCarveout, 100);

    dim3 blk(256);
    proj_mma<<<dim3(8, 32, 3), blk, PROJ_SMEM>>>(features, Wq, Wk, Wv, bq, bk, bv, q, k, v, 0);
    fused_attn<<<dim3(16, 32), blk, FA_SMEM>>>(q, k, v, mask, attn, ctx);
    proj_mma<<<dim3(8, 32, 1), blk, PROJ_SMEM>>>(ctx, Wo, Wo, Wo, bo, bo, bo, out, out, out, 2);
}

// round 9
// speedup vs baseline: 1.9011x; 1.6125x over previous
#include <cuda_runtime.h>
#include <cuda_bf16.h>
#include <cstdint>
#include <cstddef>

#define S_DIM 2048
#define E_DIM 1024
#define H_NUM 16
#define DH_DIM 64
#define B_NUM 2
#define BH_NUM (B_NUM * H_NUM)     // 32
#define M_ROWS (B_NUM * S_DIM)     // 4096

// tiled bf16 hi/lo operand images (each tile = 8KB hi plane + 8KB lo plane)
__device__ __align__(16) unsigned char g_A2[(size_t)32 * 32 * 16384];        // features tiled [mb][kc]
__device__ __align__(16) unsigned char g_W2[(size_t)4 * 8 * 32 * 16384];     // 4 weights [w][nb][kc]
__device__ __align__(16) unsigned char g_qkv2[(size_t)3 * 32 * 32 * 16384];  // q/k/v [which][z][t]
__device__ __align__(16) unsigned char g_ctx2[(size_t)32 * 32 * 16384];      // ctx tiled [mb][kc]
__device__ float g_attn[(size_t)BH_NUM * S_DIM * S_DIM];                     // fallback

// ---------------------------------------------------------------------------
// helpers
// ---------------------------------------------------------------------------
__device__ __forceinline__ uint32_t smem_u32(const void* p) {
    uint32_t a;
    asm("{ .reg .u64 t; cvta.to.shared.u64 t, %1; cvt.u32.u64 %0, t; }" : "=r"(a) : "l"(p));
    return a;
}
__device__ __forceinline__ void ldm4(uint32_t* r, uint32_t a) {
    asm volatile("ldmatrix.sync.aligned.m8n8.x4.shared.b16 {%0,%1,%2,%3}, [%4];"
        : "=r"(r[0]), "=r"(r[1]), "=r"(r[2]), "=r"(r[3]) : "r"(a));
}
__device__ __forceinline__ void ldm4t(uint32_t* r, uint32_t a) {
    asm volatile("ldmatrix.sync.aligned.m8n8.x4.trans.shared.b16 {%0,%1,%2,%3}, [%4];"
        : "=r"(r[0]), "=r"(r[1]), "=r"(r[2]), "=r"(r[3]) : "r"(a));
}
__device__ __forceinline__ void mma_bf16(float* c, const uint32_t* a, uint32_t b0, uint32_t b1) {
    asm volatile(
        "mma.sync.aligned.m16n8k16.row.col.f32.bf16.bf16.f32 "
        "{%0,%1,%2,%3}, {%4,%5,%6,%7}, {%8,%9}, {%0,%1,%2,%3};"
        : "+f"(c[0]), "+f"(c[1]), "+f"(c[2]), "+f"(c[3])
        : "r"(a[0]), "r"(a[1]), "r"(a[2]), "r"(a[3]), "r"(b0), "r"(b1));
}
__device__ __forceinline__ void cpa16(uint32_t s, const void* g) {
    asm volatile("cp.async.cg.shared.global [%0], [%1], 16;" :: "r"(s), "l"(g));
}
#define CPA_COMMIT() asm volatile("cp.async.commit_group;" ::: "memory")
#define CPA_WAIT0()  asm volatile("cp.async.wait_group 0;" ::: "memory")
#define CPA_WAIT1()  asm volatile("cp.async.wait_group 1;" ::: "memory")

__device__ __forceinline__ uint32_t swp128(int row, int c2) { return (uint32_t)(row * 128 + c2) ^ ((row & 7) << 4); }
__device__ __forceinline__ uint32_t swp64 (int row, int c2) { return (uint32_t)(row * 64  + c2) ^ (((row >> 1) & 3) << 4); }
__device__ __forceinline__ uint32_t swp256(int row, int c2) { return (uint32_t)(row * 256 + c2) ^ ((row & 7) << 4); }

__device__ __forceinline__ void split8(const float* v, uint32_t* hi, uint32_t* lo) {
#pragma unroll
    for (int q = 0; q < 4; q++) {
        __nv_bfloat16 h0 = __float2bfloat16(v[2*q]);
        __nv_bfloat16 h1 = __float2bfloat16(v[2*q+1]);
        __nv_bfloat16 l0 = __float2bfloat16(v[2*q]   - __bfloat162float(h0));
        __nv_bfloat16 l1 = __float2bfloat16(v[2*q+1] - __bfloat162float(h1));
        hi[q] = (uint32_t)__bfloat16_as_ushort(h0) | ((uint32_t)__bfloat16_as_ushort(h1) << 16);
        lo[q] = (uint32_t)__bfloat16_as_ushort(l0) | ((uint32_t)__bfloat16_as_ushort(l1) << 16);
    }
}
__device__ __forceinline__ uint32_t pack_hilo(float a, float b, uint32_t& lo) {
    __nv_bfloat16 ha = __float2bfloat16(a), hb = __float2bfloat16(b);
    __nv_bfloat16 la = __float2bfloat16(a - __bfloat162float(ha));
    __nv_bfloat16 lb = __float2bfloat16(b - __bfloat162float(hb));
    lo = (uint32_t)__bfloat16_as_ushort(la) | ((uint32_t)__bfloat16_as_ushort(lb) << 16);
    return (uint32_t)__bfloat16_as_ushort(ha) | ((uint32_t)__bfloat16_as_ushort(hb) << 16);
}
// copy one 16KB tile (hi+lo planes) gmem->smem, 256 threads
__device__ __forceinline__ void cp_tile16(uint32_t sdst, const unsigned char* gsrc, int tid) {
#pragma unroll
    for (int i = 0; i < 4; i++)
        cpa16(sdst + tid * 16 + i * 4096, gsrc + tid * 16 + i * 4096);
}

// ---------------------------------------------------------------------------
// conversion kernels (run once, cheap)
// ---------------------------------------------------------------------------
// A [4096,1024] fp32 -> tiles [mb][kc]: 128 rows x 32 cols, pitch-64 swizzle
__global__ void __launch_bounds__(256) convA(const float* __restrict__ src,
                                             unsigned char* __restrict__ dst)
{
    int kc = blockIdx.x, mb = blockIdx.y;
    int tid = threadIdx.x;
    int row = tid >> 1, c0 = (tid & 1) * 16;
    const float* p = src + (size_t)(mb * 128 + row) * E_DIM + kc * 32 + c0;
    unsigned char* base = dst + ((size_t)(mb * 32 + kc)) * 16384;
#pragma unroll
    for (int gi = 0; gi < 2; gi++) {
        float v[8];
        *(float4*)(v)     = *(const float4*)(p + gi * 8);
        *(float4*)(v + 4) = *(const float4*)(p + gi * 8 + 4);
        uint32_t hi[4], lo[4];
        split8(v, hi, lo);
        uint32_t sw = swp64(row, (c0 + gi * 8) * 2);
        *(uint4*)(base + sw)        = make_uint4(hi[0], hi[1], hi[2], hi[3]);
        *(uint4*)(base + 8192 + sw) = make_uint4(lo[0], lo[1], lo[2], lo[3]);
    }
}
// W [1024,1024] fp32 -> tiles [nb][kc]: 32 k-rows x 128 n-cols, pitch-256 swizzle
__global__ void __launch_bounds__(256) convW(
    const float* __restrict__ Wq, const float* __restrict__ Wk,
    const float* __restrict__ Wv, const float* __restrict__ Wo,
    unsigned char* __restrict__ dst)
{
    int kc = blockIdx.x, nb = blockIdx.y, w = blockIdx.z;
    const float* W = w == 0 ? Wq : (w == 1 ? Wk : (w == 2 ? Wv : Wo));
    int tid = threadIdx.x;
    int krow = tid >> 3, nseg = (tid & 7) * 16;
    const float* p = W + (size_t)(kc * 32 + krow) * E_DIM + nb * 128 + nseg;
    unsigned char* base = dst + ((size_t)w * 8 * 32 + (size_t)(nb * 32 + kc)) * 16384;
#pragma unroll
    for (int gi = 0; gi < 2; gi++) {
        float v[8];
        *(float4*)(v)     = *(const float4*)(p + gi * 8);
        *(float4*)(v + 4) = *(const float4*)(p + gi * 8 + 4);
        uint32_t hi[4], lo[4];
        split8(v, hi, lo);
        uint32_t sw = swp256(krow, (nseg + gi * 8) * 2);
        *(uint4*)(base + sw)        = make_uint4(hi[0], hi[1], hi[2], hi[3]);
        *(uint4*)(base + 8192 + sw) = make_uint4(lo[0], lo[1], lo[2], lo[3]);
    }
}

// ---------------------------------------------------------------------------
// Projection GEMM from pre-tiled operands, cp.async double-buffered.
// mode 0: epilogue writes bf16 hi/lo tiles [z][t] (64x64 pitch-128) to qkvout+zz*16MB.
// mode 2: epilogue writes fp32 row-major out + bias.
// grid (8, 32, nz), 256 thr, smem 64KB.
// ---------------------------------------------------------------------------
#define PROJ_SMEM 65536
__global__ void __launch_bounds__(256, 2) proj_mma(
    const unsigned char* __restrict__ A2, const unsigned char* __restrict__ W2,
    const float* __restrict__ b0p, const float* __restrict__ b1p, const float* __restrict__ b2p,
    unsigned char* __restrict__ qkvout, float* __restrict__ fout, int mode)
{
    extern __shared__ char sm[];
    uint32_t sb = smem_u32(sm);
    int zz = blockIdx.z;
    const float* bias = zz == 0 ? b0p : (zz == 1 ? b1p : b2p);
    const unsigned char* Wsel = W2 + (size_t)zz * 8 * 32 * 16384;

    int tid = threadIdx.x, lane = tid & 31, wid = tid >> 5;
    int warp_m = wid & 3, warp_n = wid >> 2;
    int n0 = blockIdx.x * 128, m0 = blockIdx.y * 128;
    int lrow = lane & 7, grp = lane >> 3;
    const unsigned char* Abase = A2 + ((size_t)(m0 >> 7) * 32) * 16384;
    const unsigned char* Wbase = Wsel + ((size_t)(n0 >> 7) * 32) * 16384;

    float acc[16][4] = {};
    cp_tile16(sb, Abase, tid);
    cp_tile16(sb + 16384, Wbase, tid);
    CPA_COMMIT();

    for (int c = 0; c < 32; c++) {
        int cur = (c & 1) * 32768;
        if (c < 31) {
            int nb = ((c + 1) & 1) * 32768;
            cp_tile16(sb + nb, Abase + (size_t)(c + 1) * 16384, tid);
            cp_tile16(sb + nb + 16384, Wbase + (size_t)(c + 1) * 16384, tid);
            CPA_COMMIT();
            CPA_WAIT1();
        } else {
            CPA_WAIT0();
        }
        __syncthreads();
        uint32_t sa_hi = sb + cur, sa_lo = sb + cur + 8192;
        uint32_t sw_hi = sb + cur + 16384, sw_lo = sb + cur + 24576;
#pragma unroll
        for (int ks = 0; ks < 2; ks++) {
            int k = ks * 16;
            uint32_t ah[2][4], al[2][4];
#pragma unroll
            for (int mt = 0; mt < 2; mt++) {
                int row = warp_m * 32 + mt * 16 + lrow + (grp & 1) * 8;
                uint32_t off = swp64(row, (k + (grp >> 1) * 8) * 2);
                ldm4(ah[mt], sa_hi + off);
                ldm4(al[mt], sa_lo + off);
            }
#pragma unroll
            for (int nh = 0; nh < 4; nh++) {
                int krow = k + (lane & 15);
                int ncol = warp_n * 64 + nh * 16 + (lane >> 4) * 8;
                uint32_t offb = swp256(krow, ncol * 2);
                uint32_t bh[4], bl[4];
                ldm4t(bh, sw_hi + offb);
                ldm4t(bl, sw_lo + offb);
#pragma unroll
                for (int mt = 0; mt < 2; mt++) {
                    float* c0a = acc[mt * 8 + nh * 2];
                    float* c1a = acc[mt * 8 + nh * 2 + 1];
                    mma_bf16(c0a, ah[mt], bh[0], bh[1]);
                    mma_bf16(c1a, ah[mt], bh[2], bh[3]);
                    mma_bf16(c0a, ah[mt], bl[0], bl[1]);
                    mma_bf16(c1a, ah[mt], bl[2], bl[3]);
                    mma_bf16(c0a, al[mt], bh[0], bh[1]);
                    mma_bf16(c1a, al[mt], bh[2], bh[3]);
                }
            }
        }
        __syncthreads();
    }

    int crow = lane >> 2, cc = (lane & 3) * 2;
    unsigned char* qb = qkvout + (size_t)zz * 32 * 32 * 16384;
#pragma unroll
    for (int mt = 0; mt < 2; mt++) {
#pragma unroll
        for (int t8 = 0; t8 < 8; t8++) {
            const float* c = acc[mt * 8 + t8];
            int n = n0 + warp_n * 64 + t8 * 8 + cc;
            int r0 = m0 + warp_m * 32 + mt * 16 + crow;
            float bb0 = bias[n], bb1 = bias[n + 1];
            if (mode == 2) {
                *(float2*)(fout + (size_t)r0 * E_DIM + n)       = make_float2(c[0] + bb0, c[1] + bb1);
                *(float2*)(fout + (size_t)(r0 + 8) * E_DIM + n) = make_float2(c[2] + bb0, c[3] + bb1);
            } else {
                int h = n >> 6, d = n & 63;
#pragma unroll
                for (int rr = 0; rr < 2; rr++) {
                    int m = r0 + rr * 8;
                    int b = m >> 11, s = m & (S_DIM - 1);
                    int z = b * H_NUM + h;
                    uint32_t lo;
                    uint32_t hi = pack_hilo(c[2 * rr] + bb0, c[2 * rr + 1] + bb1, lo);
                    unsigned char* tb = qb + ((size_t)(z * 32 + (s >> 6))) * 16384;
                    uint32_t sw = swp128(s & 63, d * 2);
                    *(uint32_t*)(tb + sw)        = hi;
                    *(uint32_t*)(tb + 8192 + sw) = lo;
                }
            }
        }
    }
}

// ---------------------------------------------------------------------------
// Fused attention from pre-tiled bf16 q/k/v. Two passes over j.
// Writes final normalized attn (fp32) and ctx as tiled bf16 hi/lo (for O-proj).
// grid (16, 32), 256 thr, smem 72KB.
// ---------------------------------------------------------------------------
#define FA_SMEM (65536 + 8192)
__global__ void __launch_bounds__(256) fused_attn(
    const unsigned char* __restrict__ q2, const unsigned char* __restrict__ k2,
    const unsigned char* __restrict__ v2, const float* __restrict__ mask,
    float* __restrict__ attn, unsigned char* __restrict__ ctx2)
{
    extern __shared__ char sm[];
    uint32_t sb = smem_u32(sm);
    float* mrow = (float*)(sm + 65536);
    int tid = threadIdx.x, lane = tid & 31, wid = tid >> 5;
    int z = blockIdx.y, i0 = blockIdx.x * 128;
    const unsigned char* Kb = k2 + ((size_t)z * 32) * 16384;
    const unsigned char* Vb = v2 + ((size_t)z * 32) * 16384;
    const float* mb = mask + (size_t)(z >> 4) * S_DIM;
    int lrow = lane & 7, grp = lane >> 3;
    int g = lane >> 2, cc = (lane & 3) * 2;

    for (int t = tid; t < S_DIM; t += 256) mrow[t] = -1e9f * mb[t];
    // stage Q (two tiles, 32KB verbatim)
    {
        const unsigned char* qg = q2 + ((size_t)(z * 32 + (i0 >> 6))) * 16384;
#pragma unroll
        for (int i = 0; i < 8; i++)
            cpa16(sb + tid * 16 + i * 4096, qg + tid * 16 + i * 4096);
        CPA_COMMIT();
        CPA_WAIT0();
    }
    __syncthreads();

    uint32_t qh[4][4], ql[4][4];
#pragma unroll
    for (int t = 0; t < 4; t++) {
        int row = wid * 16 + lrow + (grp & 1) * 8;
        uint32_t off = (uint32_t)(row >> 6) * 16384 + swp128(row & 63, (t * 16 + (grp >> 1) * 8) * 2);
        ldm4(qh[t], sb + off);
        ldm4(ql[t], sb + 8192 + off);
    }
    __syncthreads();

    // ---------------- pass 1: row sums (K only) ----------------
    float rsum0 = 0.f, rsum1 = 0.f;
    cp_tile16(sb, Kb, tid);
    CPA_COMMIT();
    for (int c = 0; c < 32; c++) {
        int cur = (c & 1) * 32768;
        if (c < 31) {
            cp_tile16(sb + (((c + 1) & 1) * 32768), Kb + (size_t)(c + 1) * 16384, tid);
            CPA_COMMIT();
            CPA_WAIT1();
        } else {
            CPA_WAIT0();
        }
        __syncthreads();
        uint32_t kh_base = sb + cur, kl_base = sb + cur + 8192;
        float sc[8][4] = {};
#pragma unroll
        for (int t = 0; t < 4; t++) {
#pragma unroll
            for (int nt = 0; nt < 4; nt++) {
                int rowb = nt * 16 + lrow + ((grp >> 1) & 1) * 8;
                uint32_t offb = swp128(rowb, (t * 16 + (grp & 1) * 8) * 2);
                uint32_t bh[4], bl[4];
                ldm4(bh, kh_base + offb);
                ldm4(bl, kl_base + offb);
                float* c0a = sc[nt * 2];
                float* c1a = sc[nt * 2 + 1];
                mma_bf16(c0a, qh[t], bh[0], bh[1]);
                mma_bf16(c1a, qh[t], bh[2], bh[3]);
                mma_bf16(c0a, qh[t], bl[0], bl[1]);
                mma_bf16(c1a, qh[t], bl[2], bl[3]);
                mma_bf16(c0a, ql[t], bh[0], bh[1]);
                mma_bf16(c1a, ql[t], bh[2], bh[3]);
            }
        }
        int jb = c * 64;
#pragma unroll
        for (int t8 = 0; t8 < 8; t8++) {
            int j = jb + t8 * 8 + cc;
            float m0 = mrow[j], m1 = mrow[j + 1];
            rsum0 += __expf(sc[t8][0] * 0.125f + m0) + __expf(sc[t8][1] * 0.125f + m1);
            rsum1 += __expf(sc[t8][2] * 0.125f + m0) + __expf(sc[t8][3] * 0.125f + m1);
        }
        __syncthreads();
    }
    rsum0 += __shfl_xor_sync(0xFFFFFFFFu, rsum0, 1);
    rsum0 += __shfl_xor_sync(0xFFFFFFFFu, rsum0, 2);
    rsum1 += __shfl_xor_sync(0xFFFFFFFFu, rsum1, 1);
    rsum1 += __shfl_xor_sync(0xFFFFFFFFu, rsum1, 2);
    float inv0 = 1.0f / rsum0;
    float inv1 = 1.0f / rsum1;

    // ---------------- pass 2: attn + ctx ----------------
    int iRow = i0 + wid * 16 + g;
    float* attn0 = attn + ((size_t)z * S_DIM + iRow) * S_DIM;
    float* attn1 = attn0 + 8 * S_DIM;
    float cacc[8][4] = {};

    cp_tile16(sb, Kb, tid);
    cp_tile16(sb + 16384, Vb, tid);
    CPA_COMMIT();
    for (int c = 0; c < 32; c++) {
        int cur = (c & 1) * 32768;
        if (c < 31) {
            int nb = ((c + 1) & 1) * 32768;
            cp_tile16(sb + nb, Kb + (size_t)(c + 1) * 16384, tid);
            cp_tile16(sb + nb + 16384, Vb + (size_t)(c + 1) * 16384, tid);
            CPA_COMMIT();
            CPA_WAIT1();
        } else {
            CPA_WAIT0();
        }
        __syncthreads();
        uint32_t kh_base = sb + cur, kl_base = sb + cur + 8192;
        uint32_t vh_base = sb + cur + 16384, vl_base = sb + cur + 24576;
        float sc[8][4] = {};
#pragma unroll
        for (int t = 0; t < 4; t++) {
#pragma unroll
            for (int nt = 0; nt < 4; nt++) {
                int rowb = nt * 16 + lrow + ((grp >> 1) & 1) * 8;
                uint32_t offb = swp128(rowb, (t * 16 + (grp & 1) * 8) * 2);
                uint32_t bh[4], bl[4];
                ldm4(bh, kh_base + offb);
                ldm4(bl, kl_base + offb);
                float* c0a = sc[nt * 2];
                float* c1a = sc[nt * 2 + 1];
                mma_bf16(c0a, qh[t], bh[0], bh[1]);
                mma_bf16(c1a, qh[t], bh[2], bh[3]);
                mma_bf16(c0a, qh[t], bl[0], bl[1]);
                mma_bf16(c1a, qh[t], bl[2], bl[3]);
                mma_bf16(c0a, ql[t], bh[0], bh[1]);
                mma_bf16(c1a, ql[t], bh[2], bh[3]);
            }
        }
        uint32_t pah[4][4], pal[4][4];
        int jb = c * 64;
#pragma unroll
        for (int t8 = 0; t8 < 8; t8++) {
            int j = jb + t8 * 8 + cc;
            float m0 = mrow[j], m1 = mrow[j + 1];
            float p0 = __expf(sc[t8][0] * 0.125f + m0) * inv0;
            float p1 = __expf(sc[t8][1] * 0.125f + m1) * inv0;
            float p2 = __expf(sc[t8][2] * 0.125f + m0) * inv1;
            float p3 = __expf(sc[t8][3] * 0.125f + m1) * inv1;
            *(float2*)(attn0 + j) = make_float2(p0, p1);
            *(float2*)(attn1 + j) = make_float2(p2, p3);
            int t = t8 >> 1, hf = (t8 & 1) * 2;
            pah[t][hf]     = pack_hilo(p0, p1, pal[t][hf]);
            pah[t][hf + 1] = pack_hilo(p2, p3, pal[t][hf + 1]);
        }
#pragma unroll
        for (int t = 0; t < 4; t++) {
#pragma unroll
            for (int dt = 0; dt < 4; dt++) {
                int krow = t * 16 + (lane & 15);
                int ncol = dt * 16 + (lane >> 4) * 8;
                uint32_t offb = swp128(krow, ncol * 2);
                uint32_t vh[4], vl[4];
                ldm4t(vh, vh_base + offb);
                ldm4t(vl, vl_base + offb);
                float* c0a = cacc[dt * 2];
                float* c1a = cacc[dt * 2 + 1];
                mma_bf16(c0a, pah[t], vh[0], vh[1]);
                mma_bf16(c1a, pah[t], vh[2], vh[3]);
                mma_bf16(c0a, pah[t], vl[0], vl[1]);
                mma_bf16(c1a, pah[t], vl[2], vl[3]);
                mma_bf16(c0a, pal[t], vh[0], vh[1]);
                mma_bf16(c1a, pal[t], vh[2], vh[3]);
            }
        }
        __syncthreads();
    }

    // ctx epilogue: write tiled bf16 hi/lo for O-proj A operand
    int b = z >> 4, h = z & 15;
    int mb2 = (b * S_DIM + i0) >> 7;
    int r = wid * 16 + g;
#pragma unroll
    for (int t8 = 0; t8 < 8; t8++) {
        int d0 = t8 * 8 + cc;
        int n = h * DH_DIM + d0;
        int kc = n >> 5, col = n & 31;
        unsigned char* base = ctx2 + ((size_t)(mb2 * 32 + kc)) * 16384;
        uint32_t lo0, lo1;
        uint32_t hi0 = pack_hilo(cacc[t8][0], cacc[t8][1], lo0);
        uint32_t hi1 = pack_hilo(cacc[t8][2], cacc[t8][3], lo1);
        uint32_t a0 = swp64(r, col * 2);
        uint32_t a1 = swp64(r + 8, col * 2);
        *(uint32_t*)(base + a0)        = hi0;
        *(uint32_t*)(base + 8192 + a0) = lo0;
        *(uint32_t*)(base + a1)        = hi1;
        *(uint32_t*)(base + 8192 + a1) = lo1;
    }
}

// ---------------------------------------------------------------------------

extern "C" void kernel_launch(void* const* d_in, const int* in_sizes, int n_in,
                              void* d_out, int out_size)
{
    const float* features = (const float*)d_in[0];
    const float* mask     = (const float*)d_in[1];
    const float* Wq = (const float*)d_in[2];
    const float* bq = (const float*)d_in[3];
    const float* Wk = (const float*)d_in[4];
    const float* bk = (const float*)d_in[5];
    const float* Wv = (const float*)d_in[6];
    const float* bv = (const float*)d_in[7];
    const float* Wo = (const float*)d_in[8];
    const float* bo = (const float*)d_in[9];
    float* out = (float*)d_out;

    unsigned char *A2, *W2, *qkv2, *ctx2;
    float* attn_scratch;
    cudaGetSymbolAddress((void**)&A2, g_A2);
    cudaGetSymbolAddress((void**)&W2, g_W2);
    cudaGetSymbolAddress((void**)&qkv2, g_qkv2);
    cudaGetSymbolAddress((void**)&ctx2, g_ctx2);
    cudaGetSymbolAddress((void**)&attn_scratch, g_attn);

    const long long OUT_ELEMS  = (long long)M_ROWS * E_DIM;
    const long long ATTN_ELEMS = (long long)BH_NUM * S_DIM * S_DIM;
    float* attn = ((long long)out_size >= OUT_ELEMS + ATTN_ELEMS)
                      ? (out + OUT_ELEMS) : attn_scratch;

    cudaFuncSetAttribute(proj_mma, cudaFuncAttributeMaxDynamicSharedMemorySize, PROJ_SMEM);
    cudaFuncSetAttribute(fused_attn, cudaFuncAttributeMaxDynamicSharedMemorySize, FA_SMEM);
    cudaFuncSetAttribute(proj_mma, cudaFuncAttributePreferredSharedMemoryCarveout, 100);
    cudaFuncSetAttribute(fused_attn, cudaFuncAttributePreferredSharedMemoryCarveout, 100);

    dim3 blk(256);
    convA<<<dim3(32, 32), blk>>>(features, A2);
    convW<<<dim3(32, 8, 4), blk>>>(Wq, Wk, Wv, Wo, W2);
    proj_mma<<<dim3(8, 32, 3), blk, PROJ_SMEM>>>(A2, W2, bq, bk, bv, qkv2, nullptr, 0);
    fused_attn<<<dim3(16, 32), blk, FA_SMEM>>>(
        qkv2, qkv2 + (size_t)32 * 32 * 16384, qkv2 + (size_t)2 * 32 * 32 * 16384,
        mask, attn, ctx2);
    proj_mma<<<dim3(8, 32, 1), blk, PROJ_SMEM>>>(
        ctx2, W2 + (size_t)3 * 8 * 32 * 16384, bo, bo, bo, nullptr, out, 2);
}

// round 10
// speedup vs baseline: 1.9348x; 1.0178x over previous
#include <cuda_runtime.h>
#include <cuda_bf16.h>
#include <cstdint>
#include <cstddef>

#define S_DIM 2048
#define E_DIM 1024
#define H_NUM 16
#define DH_DIM 64
#define B_NUM 2
#define BH_NUM (B_NUM * H_NUM)     // 32
#define M_ROWS (B_NUM * S_DIM)     // 4096

// tiled bf16 hi/lo operand images (each tile = 8KB hi plane + 8KB lo plane)
__device__ __align__(16) unsigned char g_A2[(size_t)32 * 32 * 16384];        // features tiled [mb][kc]
__device__ __align__(16) unsigned char g_W2[(size_t)4 * 8 * 32 * 16384];     // 4 weights [w][nb][kc]
__device__ __align__(16) unsigned char g_qkv2[(size_t)3 * 32 * 32 * 16384];  // q/k/v [which][z][t]
__device__ __align__(16) unsigned char g_ctx2[(size_t)32 * 32 * 16384];      // ctx tiled [mb][kc]
__device__ float g_attn[(size_t)BH_NUM * S_DIM * S_DIM];                     // fallback

// ---------------------------------------------------------------------------
// helpers
// ---------------------------------------------------------------------------
__device__ __forceinline__ uint32_t smem_u32(const void* p) {
    uint32_t a;
    asm("{ .reg .u64 t; cvta.to.shared.u64 t, %1; cvt.u32.u64 %0, t; }" : "=r"(a) : "l"(p));
    return a;
}
__device__ __forceinline__ void ldm4(uint32_t* r, uint32_t a) {
    asm volatile("ldmatrix.sync.aligned.m8n8.x4.shared.b16 {%0,%1,%2,%3}, [%4];"
        : "=r"(r[0]), "=r"(r[1]), "=r"(r[2]), "=r"(r[3]) : "r"(a));
}
__device__ __forceinline__ void ldm4t(uint32_t* r, uint32_t a) {
    asm volatile("ldmatrix.sync.aligned.m8n8.x4.trans.shared.b16 {%0,%1,%2,%3}, [%4];"
        : "=r"(r[0]), "=r"(r[1]), "=r"(r[2]), "=r"(r[3]) : "r"(a));
}
__device__ __forceinline__ void mma_bf16(float* c, const uint32_t* a, uint32_t b0, uint32_t b1) {
    asm volatile(
        "mma.sync.aligned.m16n8k16.row.col.f32.bf16.bf16.f32 "
        "{%0,%1,%2,%3}, {%4,%5,%6,%7}, {%8,%9}, {%0,%1,%2,%3};"
        : "+f"(c[0]), "+f"(c[1]), "+f"(c[2]), "+f"(c[3])
        : "r"(a[0]), "r"(a[1]), "r"(a[2]), "r"(a[3]), "r"(b0), "r"(b1));
}
__device__ __forceinline__ void cpa16(uint32_t s, const void* g) {
    asm volatile("cp.async.cg.shared.global [%0], [%1], 16;" :: "r"(s), "l"(g));
}
#define CPA_COMMIT() asm volatile("cp.async.commit_group;" ::: "memory")
#define CPA_WAIT0()  asm volatile("cp.async.wait_group 0;" ::: "memory")
#define CPA_WAIT1()  asm volatile("cp.async.wait_group 1;" ::: "memory")

__device__ __forceinline__ uint32_t swp128(int row, int c2) { return (uint32_t)(row * 128 + c2) ^ ((row & 7) << 4); }
__device__ __forceinline__ uint32_t swp64 (int row, int c2) { return (uint32_t)(row * 64  + c2) ^ (((row >> 1) & 3) << 4); }
__device__ __forceinline__ uint32_t swp256(int row, int c2) { return (uint32_t)(row * 256 + c2) ^ ((row & 7) << 4); }

__device__ __forceinline__ void split8(const float* v, uint32_t* hi, uint32_t* lo) {
#pragma unroll
    for (int q = 0; q < 4; q++) {
        __nv_bfloat16 h0 = __float2bfloat16(v[2*q]);
        __nv_bfloat16 h1 = __float2bfloat16(v[2*q+1]);
        __nv_bfloat16 l0 = __float2bfloat16(v[2*q]   - __bfloat162float(h0));
        __nv_bfloat16 l1 = __float2bfloat16(v[2*q+1] - __bfloat162float(h1));
        hi[q] = (uint32_t)__bfloat16_as_ushort(h0) | ((uint32_t)__bfloat16_as_ushort(h1) << 16);
        lo[q] = (uint32_t)__bfloat16_as_ushort(l0) | ((uint32_t)__bfloat16_as_ushort(l1) << 16);
    }
}
__device__ __forceinline__ uint32_t pack_hilo(float a, float b, uint32_t& lo) {
    __nv_bfloat16 ha = __float2bfloat16(a), hb = __float2bfloat16(b);
    __nv_bfloat16 la = __float2bfloat16(a - __bfloat162float(ha));
    __nv_bfloat16 lb = __float2bfloat16(b - __bfloat162float(hb));
    lo = (uint32_t)__bfloat16_as_ushort(la) | ((uint32_t)__bfloat16_as_ushort(lb) << 16);
    return (uint32_t)__bfloat16_as_ushort(ha) | ((uint32_t)__bfloat16_as_ushort(hb) << 16);
}
// copy one 16KB tile (hi+lo planes) gmem->smem, 256 threads
__device__ __forceinline__ void cp_tile16(uint32_t sdst, const unsigned char* gsrc, int tid) {
#pragma unroll
    for (int i = 0; i < 4; i++)
        cpa16(sdst + tid * 16 + i * 4096, gsrc + tid * 16 + i * 4096);
}

// ---------------------------------------------------------------------------
// conversion kernels (run once, cheap)
// ---------------------------------------------------------------------------
__global__ void __launch_bounds__(256) convA(const float* __restrict__ src,
                                             unsigned char* __restrict__ dst)
{
    int kc = blockIdx.x, mb = blockIdx.y;
    int tid = threadIdx.x;
    int row = tid >> 1, c0 = (tid & 1) * 16;
    const float* p = src + (size_t)(mb * 128 + row) * E_DIM + kc * 32 + c0;
    unsigned char* base = dst + ((size_t)(mb * 32 + kc)) * 16384;
#pragma unroll
    for (int gi = 0; gi < 2; gi++) {
        float v[8];
        *(float4*)(v)     = *(const float4*)(p + gi * 8);
        *(float4*)(v + 4) = *(const float4*)(p + gi * 8 + 4);
        uint32_t hi[4], lo[4];
        split8(v, hi, lo);
        uint32_t sw = swp64(row, (c0 + gi * 8) * 2);
        *(uint4*)(base + sw)        = make_uint4(hi[0], hi[1], hi[2], hi[3]);
        *(uint4*)(base + 8192 + sw) = make_uint4(lo[0], lo[1], lo[2], lo[3]);
    }
}
__global__ void __launch_bounds__(256) convW(
    const float* __restrict__ Wq, const float* __restrict__ Wk,
    const float* __restrict__ Wv, const float* __restrict__ Wo,
    unsigned char* __restrict__ dst)
{
    int kc = blockIdx.x, nb = blockIdx.y, w = blockIdx.z;
    const float* W = w == 0 ? Wq : (w == 1 ? Wk : (w == 2 ? Wv : Wo));
    int tid = threadIdx.x;
    int krow = tid >> 3, nseg = (tid & 7) * 16;
    const float* p = W + (size_t)(kc * 32 + krow) * E_DIM + nb * 128 + nseg;
    unsigned char* base = dst + ((size_t)w * 8 * 32 + (size_t)(nb * 32 + kc)) * 16384;
#pragma unroll
    for (int gi = 0; gi < 2; gi++) {
        float v[8];
        *(float4*)(v)     = *(const float4*)(p + gi * 8);
        *(float4*)(v + 4) = *(const float4*)(p + gi * 8 + 4);
        uint32_t hi[4], lo[4];
        split8(v, hi, lo);
        uint32_t sw = swp256(krow, (nseg + gi * 8) * 2);
        *(uint4*)(base + sw)        = make_uint4(hi[0], hi[1], hi[2], hi[3]);
        *(uint4*)(base + 8192 + sw) = make_uint4(lo[0], lo[1], lo[2], lo[3]);
    }
}

// ---------------------------------------------------------------------------
// Projection GEMM from pre-tiled operands, cp.async double-buffered.
// ---------------------------------------------------------------------------
#define PROJ_SMEM 65536
__global__ void __launch_bounds__(256, 2) proj_mma(
    const unsigned char* __restrict__ A2, const unsigned char* __restrict__ W2,
    const float* __restrict__ b0p, const float* __restrict__ b1p, const float* __restrict__ b2p,
    unsigned char* __restrict__ qkvout, float* __restrict__ fout, int mode)
{
    extern __shared__ char sm[];
    uint32_t sb = smem_u32(sm);
    int zz = blockIdx.z;
    const float* bias = zz == 0 ? b0p : (zz == 1 ? b1p : b2p);
    const unsigned char* Wsel = W2 + (size_t)zz * 8 * 32 * 16384;

    int tid = threadIdx.x, lane = tid & 31, wid = tid >> 5;
    int warp_m = wid & 3, warp_n = wid >> 2;
    int n0 = blockIdx.x * 128, m0 = blockIdx.y * 128;
    int lrow = lane & 7, grp = lane >> 3;
    const unsigned char* Abase = A2 + ((size_t)(m0 >> 7) * 32) * 16384;
    const unsigned char* Wbase = Wsel + ((size_t)(n0 >> 7) * 32) * 16384;

    float acc[16][4] = {};
    cp_tile16(sb, Abase, tid);
    cp_tile16(sb + 16384, Wbase, tid);
    CPA_COMMIT();

    for (int c = 0; c < 32; c++) {
        int cur = (c & 1) * 32768;
        if (c < 31) {
            int nb = ((c + 1) & 1) * 32768;
            cp_tile16(sb + nb, Abase + (size_t)(c + 1) * 16384, tid);
            cp_tile16(sb + nb + 16384, Wbase + (size_t)(c + 1) * 16384, tid);
            CPA_COMMIT();
            CPA_WAIT1();
        } else {
            CPA_WAIT0();
        }
        __syncthreads();
        uint32_t sa_hi = sb + cur, sa_lo = sb + cur + 8192;
        uint32_t sw_hi = sb + cur + 16384, sw_lo = sb + cur + 24576;
#pragma unroll
        for (int ks = 0; ks < 2; ks++) {
            int k = ks * 16;
            uint32_t ah[2][4], al[2][4];
#pragma unroll
            for (int mt = 0; mt < 2; mt++) {
                int row = warp_m * 32 + mt * 16 + lrow + (grp & 1) * 8;
                uint32_t off = swp64(row, (k + (grp >> 1) * 8) * 2);
                ldm4(ah[mt], sa_hi + off);
                ldm4(al[mt], sa_lo + off);
            }
#pragma unroll
            for (int nh = 0; nh < 4; nh++) {
                int krow = k + (lane & 15);
                int ncol = warp_n * 64 + nh * 16 + (lane >> 4) * 8;
                uint32_t offb = swp256(krow, ncol * 2);
                uint32_t bh[4], bl[4];
                ldm4t(bh, sw_hi + offb);
                ldm4t(bl, sw_lo + offb);
#pragma unroll
                for (int mt = 0; mt < 2; mt++) {
                    float* c0a = acc[mt * 8 + nh * 2];
                    float* c1a = acc[mt * 8 + nh * 2 + 1];
                    mma_bf16(c0a, ah[mt], bh[0], bh[1]);
                    mma_bf16(c1a, ah[mt], bh[2], bh[3]);
                    mma_bf16(c0a, ah[mt], bl[0], bl[1]);
                    mma_bf16(c1a, ah[mt], bl[2], bl[3]);
                    mma_bf16(c0a, al[mt], bh[0], bh[1]);
                    mma_bf16(c1a, al[mt], bh[2], bh[3]);
                }
            }
        }
        __syncthreads();
    }

    int crow = lane >> 2, cc = (lane & 3) * 2;
    unsigned char* qb = qkvout + (size_t)zz * 32 * 32 * 16384;
#pragma unroll
    for (int mt = 0; mt < 2; mt++) {
#pragma unroll
        for (int t8 = 0; t8 < 8; t8++) {
            const float* c = acc[mt * 8 + t8];
            int n = n0 + warp_n * 64 + t8 * 8 + cc;
            int r0 = m0 + warp_m * 32 + mt * 16 + crow;
            float bb0 = bias[n], bb1 = bias[n + 1];
            if (mode == 2) {
                *(float2*)(fout + (size_t)r0 * E_DIM + n)       = make_float2(c[0] + bb0, c[1] + bb1);
                *(float2*)(fout + (size_t)(r0 + 8) * E_DIM + n) = make_float2(c[2] + bb0, c[3] + bb1);
            } else {
                int h = n >> 6, d = n & 63;
#pragma unroll
                for (int rr = 0; rr < 2; rr++) {
                    int m = r0 + rr * 8;
                    int b = m >> 11, s = m & (S_DIM - 1);
                    int z = b * H_NUM + h;
                    uint32_t lo;
                    uint32_t hi = pack_hilo(c[2 * rr] + bb0, c[2 * rr + 1] + bb1, lo);
                    unsigned char* tb = qb + ((size_t)(z * 32 + (s >> 6))) * 16384;
                    uint32_t sw = swp128(s & 63, d * 2);
                    *(uint32_t*)(tb + sw)        = hi;
                    *(uint32_t*)(tb + 8192 + sw) = lo;
                }
            }
        }
    }
}

// ---------------------------------------------------------------------------
// Fused attention, 2 CTAs/SM. Pass 1: row sums. Pass 2: attn + ctx, with
// exp/pack/PV interleaved per k16-step to keep p-fragment live range at 8 regs.
// ---------------------------------------------------------------------------
#define FA_SMEM (65536 + 8192)
__global__ void __launch_bounds__(256, 2) fused_attn(
    const unsigned char* __restrict__ q2, const unsigned char* __restrict__ k2,
    const unsigned char* __restrict__ v2, const float* __restrict__ mask,
    float* __restrict__ attn, unsigned char* __restrict__ ctx2)
{
    extern __shared__ char sm[];
    uint32_t sb = smem_u32(sm);
    float* mrow = (float*)(sm + 65536);
    int tid = threadIdx.x, lane = tid & 31, wid = tid >> 5;
    int z = blockIdx.y, i0 = blockIdx.x * 128;
    const unsigned char* Kb = k2 + ((size_t)z * 32) * 16384;
    const unsigned char* Vb = v2 + ((size_t)z * 32) * 16384;
    const float* mb = mask + (size_t)(z >> 4) * S_DIM;
    int lrow = lane & 7, grp = lane >> 3;
    int g = lane >> 2, cc = (lane & 3) * 2;

    for (int t = tid; t < S_DIM; t += 256) mrow[t] = -1e9f * mb[t];
    {
        const unsigned char* qg = q2 + ((size_t)(z * 32 + (i0 >> 6))) * 16384;
#pragma unroll
        for (int i = 0; i < 8; i++)
            cpa16(sb + tid * 16 + i * 4096, qg + tid * 16 + i * 4096);
        CPA_COMMIT();
        CPA_WAIT0();
    }
    __syncthreads();

    uint32_t qh[4][4], ql[4][4];
#pragma unroll
    for (int t = 0; t < 4; t++) {
        int row = wid * 16 + lrow + (grp & 1) * 8;
        uint32_t off = (uint32_t)(row >> 6) * 16384 + swp128(row & 63, (t * 16 + (grp >> 1) * 8) * 2);
        ldm4(qh[t], sb + off);
        ldm4(ql[t], sb + 8192 + off);
    }
    __syncthreads();

    // ---------------- pass 1: row sums (K only) ----------------
    float rsum0 = 0.f, rsum1 = 0.f;
    cp_tile16(sb, Kb, tid);
    CPA_COMMIT();
    for (int c = 0; c < 32; c++) {
        int cur = (c & 1) * 32768;
        if (c < 31) {
            cp_tile16(sb + (((c + 1) & 1) * 32768), Kb + (size_t)(c + 1) * 16384, tid);
            CPA_COMMIT();
            CPA_WAIT1();
        } else {
            CPA_WAIT0();
        }
        __syncthreads();
        uint32_t kh_base = sb + cur, kl_base = sb + cur + 8192;
        float sc[8][4] = {};
#pragma unroll
        for (int t = 0; t < 4; t++) {
#pragma unroll
            for (int nt = 0; nt < 4; nt++) {
                int rowb = nt * 16 + lrow + ((grp >> 1) & 1) * 8;
                uint32_t offb = swp128(rowb, (t * 16 + (grp & 1) * 8) * 2);
                uint32_t bh[4], bl[4];
                ldm4(bh, kh_base + offb);
                ldm4(bl, kl_base + offb);
                float* c0a = sc[nt * 2];
                float* c1a = sc[nt * 2 + 1];
                mma_bf16(c0a, qh[t], bh[0], bh[1]);
                mma_bf16(c1a, qh[t], bh[2], bh[3]);
                mma_bf16(c0a, qh[t], bl[0], bl[1]);
                mma_bf16(c1a, qh[t], bl[2], bl[3]);
                mma_bf16(c0a, ql[t], bh[0], bh[1]);
                mma_bf16(c1a, ql[t], bh[2], bh[3]);
            }
        }
        int jb = c * 64;
#pragma unroll
        for (int t8 = 0; t8 < 8; t8++) {
            int j = jb + t8 * 8 + cc;
            float m0 = mrow[j], m1 = mrow[j + 1];
            rsum0 += __expf(sc[t8][0] * 0.125f + m0) + __expf(sc[t8][1] * 0.125f + m1);
            rsum1 += __expf(sc[t8][2] * 0.125f + m0) + __expf(sc[t8][3] * 0.125f + m1);
        }
        __syncthreads();
    }
    rsum0 += __shfl_xor_sync(0xFFFFFFFFu, rsum0, 1);
    rsum0 += __shfl_xor_sync(0xFFFFFFFFu, rsum0, 2);
    rsum1 += __shfl_xor_sync(0xFFFFFFFFu, rsum1, 1);
    rsum1 += __shfl_xor_sync(0xFFFFFFFFu, rsum1, 2);
    float inv0 = 1.0f / rsum0;
    float inv1 = 1.0f / rsum1;

    // ---------------- pass 2: attn + ctx ----------------
    int iRow = i0 + wid * 16 + g;
    float* attn0 = attn + ((size_t)z * S_DIM + iRow) * S_DIM;
    float* attn1 = attn0 + 8 * S_DIM;
    float cacc[8][4] = {};

    cp_tile16(sb, Kb, tid);
    cp_tile16(sb + 16384, Vb, tid);
    CPA_COMMIT();
    for (int c = 0; c < 32; c++) {
        int cur = (c & 1) * 32768;
        if (c < 31) {
            int nb = ((c + 1) & 1) * 32768;
            cp_tile16(sb + nb, Kb + (size_t)(c + 1) * 16384, tid);
            cp_tile16(sb + nb + 16384, Vb + (size_t)(c + 1) * 16384, tid);
            CPA_COMMIT();
            CPA_WAIT1();
        } else {
            CPA_WAIT0();
        }
        __syncthreads();
        uint32_t kh_base = sb + cur, kl_base = sb + cur + 8192;
        uint32_t vh_base = sb + cur + 16384, vl_base = sb + cur + 24576;
        float sc[8][4] = {};
#pragma unroll
        for (int t = 0; t < 4; t++) {
#pragma unroll
            for (int nt = 0; nt < 4; nt++) {
                int rowb = nt * 16 + lrow + ((grp >> 1) & 1) * 8;
                uint32_t offb = swp128(rowb, (t * 16 + (grp & 1) * 8) * 2);
                uint32_t bh[4], bl[4];
                ldm4(bh, kh_base + offb);
                ldm4(bl, kl_base + offb);
                float* c0a = sc[nt * 2];
                float* c1a = sc[nt * 2 + 1];
                mma_bf16(c0a, qh[t], bh[0], bh[1]);
                mma_bf16(c1a, qh[t], bh[2], bh[3]);
                mma_bf16(c0a, qh[t], bl[0], bl[1]);
                mma_bf16(c1a, qh[t], bl[2], bl[3]);
                mma_bf16(c0a, ql[t], bh[0], bh[1]);
                mma_bf16(c1a, ql[t], bh[2], bh[3]);
            }
        }
        // per k16-step: exp/normalize/write/pack then PV — p frags live 8 regs
        int jb = c * 64;
#pragma unroll
        for (int t = 0; t < 4; t++) {
            uint32_t pah[4], pal[4];
#pragma unroll
            for (int h2 = 0; h2 < 2; h2++) {
                int t8 = t * 2 + h2;
                int j = jb + t8 * 8 + cc;
                float m0 = mrow[j], m1 = mrow[j + 1];
                float p0 = __expf(sc[t8][0] * 0.125f + m0) * inv0;
                float p1 = __expf(sc[t8][1] * 0.125f + m1) * inv0;
                float p2 = __expf(sc[t8][2] * 0.125f + m0) * inv1;
                float p3 = __expf(sc[t8][3] * 0.125f + m1) * inv1;
                *(float2*)(attn0 + j) = make_float2(p0, p1);
                *(float2*)(attn1 + j) = make_float2(p2, p3);
                pah[h2 * 2]     = pack_hilo(p0, p1, pal[h2 * 2]);
                pah[h2 * 2 + 1] = pack_hilo(p2, p3, pal[h2 * 2 + 1]);
            }
#pragma unroll
            for (int dt = 0; dt < 4; dt++) {
                int krow = t * 16 + (lane & 15);
                int ncol = dt * 16 + (lane >> 4) * 8;
                uint32_t offb = swp128(krow, ncol * 2);
                uint32_t vh[4], vl[4];
                ldm4t(vh, vh_base + offb);
                ldm4t(vl, vl_base + offb);
                float* c0a = cacc[dt * 2];
                float* c1a = cacc[dt * 2 + 1];
                mma_bf16(c0a, pah, vh[0], vh[1]);
                mma_bf16(c1a, pah, vh[2], vh[3]);
                mma_bf16(c0a, pah, vl[0], vl[1]);
                mma_bf16(c1a, pah, vl[2], vl[3]);
                mma_bf16(c0a, pal, vh[0], vh[1]);
                mma_bf16(c1a, pal, vh[2], vh[3]);
            }
        }
        __syncthreads();
    }

    // ctx epilogue: write tiled bf16 hi/lo for O-proj A operand
    int b = z >> 4, h = z & 15;
    int mb2 = (b * S_DIM + i0) >> 7;
    int r = wid * 16 + g;
#pragma unroll
    for (int t8 = 0; t8 < 8; t8++) {
        int d0 = t8 * 8 + cc;
        int n = h * DH_DIM + d0;
        int kc = n >> 5, col = n & 31;
        unsigned char* base = ctx2 + ((size_t)(mb2 * 32 + kc)) * 16384;
        uint32_t lo0, lo1;
        uint32_t hi0 = pack_hilo(cacc[t8][0], cacc[t8][1], lo0);
        uint32_t hi1 = pack_hilo(cacc[t8][2], cacc[t8][3], lo1);
        uint32_t a0 = swp64(r, col * 2);
        uint32_t a1 = swp64(r + 8, col * 2);
        *(uint32_t*)(base + a0)        = hi0;
        *(uint32_t*)(base + 8192 + a0) = lo0;
        *(uint32_t*)(base + a1)        = hi1;
        *(uint32_t*)(base + 8192 + a1) = lo1;
    }
}

// ---------------------------------------------------------------------------

extern "C" void kernel_launch(void* const* d_in, const int* in_sizes, int n_in,
                              void* d_out, int out_size)
{
    const float* features = (const float*)d_in[0];
    const float* mask     = (const float*)d_in[1];
    const float* Wq = (const float*)d_in[2];
    const float* bq = (const float*)d_in[3];
    const float* Wk = (const float*)d_in[4];
    const float* bk = (const float*)d_in[5];
    const float* Wv = (const float*)d_in[6];
    const float* bv = (const float*)d_in[7];
    const float* Wo = (const float*)d_in[8];
    const float* bo = (const float*)d_in[9];
    float* out = (float*)d_out;

    unsigned char *A2, *W2, *qkv2, *ctx2;
    float* attn_scratch;
    cudaGetSymbolAddress((void**)&A2, g_A2);
    cudaGetSymbolAddress((void**)&W2, g_W2);
    cudaGetSymbolAddress((void**)&qkv2, g_qkv2);
    cudaGetSymbolAddress((void**)&ctx2, g_ctx2);
    cudaGetSymbolAddress((void**)&attn_scratch, g_attn);

    const long long OUT_ELEMS  = (long long)M_ROWS * E_DIM;
    const long long ATTN_ELEMS = (long long)BH_NUM * S_DIM * S_DIM;
    float* attn = ((long long)out_size >= OUT_ELEMS + ATTN_ELEMS)
                      ? (out + OUT_ELEMS) : attn_scratch;

    cudaFuncSetAttribute(proj_mma, cudaFuncAttributeMaxDynamicSharedMemorySize, PROJ_SMEM);
    cudaFuncSetAttribute(fused_attn, cudaFuncAttributeMaxDynamicSharedMemorySize, FA_SMEM);
    cudaFuncSetAttribute(proj_mma, cudaFuncAttributePreferredSharedMemoryCarveout, 100);
    cudaFuncSetAttribute(fused_attn, cudaFuncAttributePreferredSharedMemoryCarveout, 100);

    dim3 blk(256);
    convA<<<dim3(32, 32), blk>>>(features, A2);
    convW<<<dim3(32, 8, 4), blk>>>(Wq, Wk, Wv, Wo, W2);
    proj_mma<<<dim3(8, 32, 3), blk, PROJ_SMEM>>>(A2, W2, bq, bk, bv, qkv2, nullptr, 0);
    fused_attn<<<dim3(16, 32), blk, FA_SMEM>>>(
        qkv2, qkv2 + (size_t)32 * 32 * 16384, qkv2 + (size_t)2 * 32 * 32 * 16384,
        mask, attn, ctx2);
    proj_mma<<<dim3(8, 32, 1), blk, PROJ_SMEM>>>(
        ctx2, W2 + (size_t)3 * 8 * 32 * 16384, bo, bo, bo, nullptr, out, 2);
}

// round 11
// speedup vs baseline: 2.1853x; 1.1294x over previous
#include <cuda_runtime.h>
#include <cuda_bf16.h>
#include <cuda_fp16.h>
#include <cstdint>
#include <cstddef>

#define S_DIM 2048
#define E_DIM 1024
#define H_NUM 16
#define DH_DIM 64
#define B_NUM 2
#define BH_NUM (B_NUM * H_NUM)     // 32
#define M_ROWS (B_NUM * S_DIM)     // 4096

// tiled 16-bit hi/lo operand images (each tile = 8KB hi plane + 8KB lo plane)
// A2/W2/ctx2 are bf16 pairs; qkv2 are fp16 pairs.
__device__ __align__(16) unsigned char g_A2[(size_t)32 * 32 * 16384];        // features tiled [mb][kc]
__device__ __align__(16) unsigned char g_W2[(size_t)4 * 8 * 32 * 16384];     // 4 weights [w][nb][kc]
__device__ __align__(16) unsigned char g_qkv2[(size_t)3 * 32 * 32 * 16384];  // q/k/v [which][z][t] (fp16)
__device__ __align__(16) unsigned char g_ctx2[(size_t)32 * 32 * 16384];      // ctx tiled [mb][kc]
__device__ float g_attn[(size_t)BH_NUM * S_DIM * S_DIM];                     // fallback

// ---------------------------------------------------------------------------
// helpers
// ---------------------------------------------------------------------------
__device__ __forceinline__ uint32_t smem_u32(const void* p) {
    uint32_t a;
    asm("{ .reg .u64 t; cvta.to.shared.u64 t, %1; cvt.u32.u64 %0, t; }" : "=r"(a) : "l"(p));
    return a;
}
__device__ __forceinline__ void ldm4(uint32_t* r, uint32_t a) {
    asm volatile("ldmatrix.sync.aligned.m8n8.x4.shared.b16 {%0,%1,%2,%3}, [%4];"
        : "=r"(r[0]), "=r"(r[1]), "=r"(r[2]), "=r"(r[3]) : "r"(a));
}
__device__ __forceinline__ void ldm4t(uint32_t* r, uint32_t a) {
    asm volatile("ldmatrix.sync.aligned.m8n8.x4.trans.shared.b16 {%0,%1,%2,%3}, [%4];"
        : "=r"(r[0]), "=r"(r[1]), "=r"(r[2]), "=r"(r[3]) : "r"(a));
}
__device__ __forceinline__ void mma_bf16(float* c, const uint32_t* a, uint32_t b0, uint32_t b1) {
    asm volatile(
        "mma.sync.aligned.m16n8k16.row.col.f32.bf16.bf16.f32 "
        "{%0,%1,%2,%3}, {%4,%5,%6,%7}, {%8,%9}, {%0,%1,%2,%3};"
        : "+f"(c[0]), "+f"(c[1]), "+f"(c[2]), "+f"(c[3])
        : "r"(a[0]), "r"(a[1]), "r"(a[2]), "r"(a[3]), "r"(b0), "r"(b1));
}
__device__ __forceinline__ void mma_f16(float* c, const uint32_t* a, uint32_t b0, uint32_t b1) {
    asm volatile(
        "mma.sync.aligned.m16n8k16.row.col.f32.f16.f16.f32 "
        "{%0,%1,%2,%3}, {%4,%5,%6,%7}, {%8,%9}, {%0,%1,%2,%3};"
        : "+f"(c[0]), "+f"(c[1]), "+f"(c[2]), "+f"(c[3])
        : "r"(a[0]), "r"(a[1]), "r"(a[2]), "r"(a[3]), "r"(b0), "r"(b1));
}
__device__ __forceinline__ void cpa16(uint32_t s, const void* g) {
    asm volatile("cp.async.cg.shared.global [%0], [%1], 16;" :: "r"(s), "l"(g));
}
#define CPA_COMMIT() asm volatile("cp.async.commit_group;" ::: "memory")
#define CPA_WAIT0()  asm volatile("cp.async.wait_group 0;" ::: "memory")
#define CPA_WAIT1()  asm volatile("cp.async.wait_group 1;" ::: "memory")

__device__ __forceinline__ uint32_t swp128(int row, int c2) { return (uint32_t)(row * 128 + c2) ^ ((row & 7) << 4); }
__device__ __forceinline__ uint32_t swp64 (int row, int c2) { return (uint32_t)(row * 64  + c2) ^ (((row >> 1) & 3) << 4); }
__device__ __forceinline__ uint32_t swp256(int row, int c2) { return (uint32_t)(row * 256 + c2) ^ ((row & 7) << 4); }

__device__ __forceinline__ void split8(const float* v, uint32_t* hi, uint32_t* lo) {
#pragma unroll
    for (int q = 0; q < 4; q++) {
        __nv_bfloat16 h0 = __float2bfloat16(v[2*q]);
        __nv_bfloat16 h1 = __float2bfloat16(v[2*q+1]);
        __nv_bfloat16 l0 = __float2bfloat16(v[2*q]   - __bfloat162float(h0));
        __nv_bfloat16 l1 = __float2bfloat16(v[2*q+1] - __bfloat162float(h1));
        hi[q] = (uint32_t)__bfloat16_as_ushort(h0) | ((uint32_t)__bfloat16_as_ushort(h1) << 16);
        lo[q] = (uint32_t)__bfloat16_as_ushort(l0) | ((uint32_t)__bfloat16_as_ushort(l1) << 16);
    }
}
__device__ __forceinline__ uint32_t pack_hilo(float a, float b, uint32_t& lo) {
    __nv_bfloat16 ha = __float2bfloat16(a), hb = __float2bfloat16(b);
    __nv_bfloat16 la = __float2bfloat16(a - __bfloat162float(ha));
    __nv_bfloat16 lb = __float2bfloat16(b - __bfloat162float(hb));
    lo = (uint32_t)__bfloat16_as_ushort(la) | ((uint32_t)__bfloat16_as_ushort(lb) << 16);
    return (uint32_t)__bfloat16_as_ushort(ha) | ((uint32_t)__bfloat16_as_ushort(hb) << 16);
}
// fp16 hi/lo pack
__device__ __forceinline__ uint32_t pack_f16(float a, float b, uint32_t& lo) {
    __half ha = __float2half_rn(a), hb = __float2half_rn(b);
    __half la = __float2half_rn(a - __half2float(ha));
    __half lb = __float2half_rn(b - __half2float(hb));
    lo = (uint32_t)__half_as_ushort(la) | ((uint32_t)__half_as_ushort(lb) << 16);
    return (uint32_t)__half_as_ushort(ha) | ((uint32_t)__half_as_ushort(hb) << 16);
}
__device__ __forceinline__ uint32_t pack_f16_hi(float a, float b) {
    __half ha = __float2half_rn(a), hb = __float2half_rn(b);
    return (uint32_t)__half_as_ushort(ha) | ((uint32_t)__half_as_ushort(hb) << 16);
}
// copy one 16KB tile (hi+lo planes) gmem->smem, 256 threads
__device__ __forceinline__ void cp_tile16(uint32_t sdst, const unsigned char* gsrc, int tid) {
#pragma unroll
    for (int i = 0; i < 4; i++)
        cpa16(sdst + tid * 16 + i * 4096, gsrc + tid * 16 + i * 4096);
}
// copy only the 8KB hi plane
__device__ __forceinline__ void cp_tile8(uint32_t sdst, const unsigned char* gsrc, int tid) {
#pragma unroll
    for (int i = 0; i < 2; i++)
        cpa16(sdst + tid * 16 + i * 4096, gsrc + tid * 16 + i * 4096);
}

// ---------------------------------------------------------------------------
// conversion kernels (run once, cheap) — bf16 images for proj operands
// ---------------------------------------------------------------------------
__global__ void __launch_bounds__(256) convA(const float* __restrict__ src,
                                             unsigned char* __restrict__ dst)
{
    int kc = blockIdx.x, mb = blockIdx.y;
    int tid = threadIdx.x;
    int row = tid >> 1, c0 = (tid & 1) * 16;
    const float* p = src + (size_t)(mb * 128 + row) * E_DIM + kc * 32 + c0;
    unsigned char* base = dst + ((size_t)(mb * 32 + kc)) * 16384;
#pragma unroll
    for (int gi = 0; gi < 2; gi++) {
        float v[8];
        *(float4*)(v)     = *(const float4*)(p + gi * 8);
        *(float4*)(v + 4) = *(const float4*)(p + gi * 8 + 4);
        uint32_t hi[4], lo[4];
        split8(v, hi, lo);
        uint32_t sw = swp64(row, (c0 + gi * 8) * 2);
        *(uint4*)(base + sw)        = make_uint4(hi[0], hi[1], hi[2], hi[3]);
        *(uint4*)(base + 8192 + sw) = make_uint4(lo[0], lo[1], lo[2], lo[3]);
    }
}
__global__ void __launch_bounds__(256) convW(
    const float* __restrict__ Wq, const float* __restrict__ Wk,
    const float* __restrict__ Wv, const float* __restrict__ Wo,
    unsigned char* __restrict__ dst)
{
    int kc = blockIdx.x, nb = blockIdx.y, w = blockIdx.z;
    const float* W = w == 0 ? Wq : (w == 1 ? Wk : (w == 2 ? Wv : Wo));
    int tid = threadIdx.x;
    int krow = tid >> 3, nseg = (tid & 7) * 16;
    const float* p = W + (size_t)(kc * 32 + krow) * E_DIM + nb * 128 + nseg;
    unsigned char* base = dst + ((size_t)w * 8 * 32 + (size_t)(nb * 32 + kc)) * 16384;
#pragma unroll
    for (int gi = 0; gi < 2; gi++) {
        float v[8];
        *(float4*)(v)     = *(const float4*)(p + gi * 8);
        *(float4*)(v + 4) = *(const float4*)(p + gi * 8 + 4);
        uint32_t hi[4], lo[4];
        split8(v, hi, lo);
        uint32_t sw = swp256(krow, (nseg + gi * 8) * 2);
        *(uint4*)(base + sw)        = make_uint4(hi[0], hi[1], hi[2], hi[3]);
        *(uint4*)(base + 8192 + sw) = make_uint4(lo[0], lo[1], lo[2], lo[3]);
    }
}

// ---------------------------------------------------------------------------
// Projection GEMM from pre-tiled bf16 operands, cp.async double-buffered.
// mode 0: epilogue packs q/k/v as fp16 hi/lo tiles.  mode 2: fp32 out + bias.
// ---------------------------------------------------------------------------
#define PROJ_SMEM 65536
__global__ void __launch_bounds__(256, 2) proj_mma(
    const unsigned char* __restrict__ A2, const unsigned char* __restrict__ W2,
    const float* __restrict__ b0p, const float* __restrict__ b1p, const float* __restrict__ b2p,
    unsigned char* __restrict__ qkvout, float* __restrict__ fout, int mode)
{
    extern __shared__ char sm[];
    uint32_t sb = smem_u32(sm);
    int zz = blockIdx.z;
    const float* bias = zz == 0 ? b0p : (zz == 1 ? b1p : b2p);
    const unsigned char* Wsel = W2 + (size_t)zz * 8 * 32 * 16384;

    int tid = threadIdx.x, lane = tid & 31, wid = tid >> 5;
    int warp_m = wid & 3, warp_n = wid >> 2;
    int n0 = blockIdx.x * 128, m0 = blockIdx.y * 128;
    int lrow = lane & 7, grp = lane >> 3;
    const unsigned char* Abase = A2 + ((size_t)(m0 >> 7) * 32) * 16384;
    const unsigned char* Wbase = Wsel + ((size_t)(n0 >> 7) * 32) * 16384;

    float acc[16][4] = {};
    cp_tile16(sb, Abase, tid);
    cp_tile16(sb + 16384, Wbase, tid);
    CPA_COMMIT();

    for (int c = 0; c < 32; c++) {
        int cur = (c & 1) * 32768;
        if (c < 31) {
            int nb = ((c + 1) & 1) * 32768;
            cp_tile16(sb + nb, Abase + (size_t)(c + 1) * 16384, tid);
            cp_tile16(sb + nb + 16384, Wbase + (size_t)(c + 1) * 16384, tid);
            CPA_COMMIT();
            CPA_WAIT1();
        } else {
            CPA_WAIT0();
        }
        __syncthreads();
        uint32_t sa_hi = sb + cur, sa_lo = sb + cur + 8192;
        uint32_t sw_hi = sb + cur + 16384, sw_lo = sb + cur + 24576;
#pragma unroll
        for (int ks = 0; ks < 2; ks++) {
            int k = ks * 16;
            uint32_t ah[2][4], al[2][4];
#pragma unroll
            for (int mt = 0; mt < 2; mt++) {
                int row = warp_m * 32 + mt * 16 + lrow + (grp & 1) * 8;
                uint32_t off = swp64(row, (k + (grp >> 1) * 8) * 2);
                ldm4(ah[mt], sa_hi + off);
                ldm4(al[mt], sa_lo + off);
            }
#pragma unroll
            for (int nh = 0; nh < 4; nh++) {
                int krow = k + (lane & 15);
                int ncol = warp_n * 64 + nh * 16 + (lane >> 4) * 8;
                uint32_t offb = swp256(krow, ncol * 2);
                uint32_t bh[4], bl[4];
                ldm4t(bh, sw_hi + offb);
                ldm4t(bl, sw_lo + offb);
#pragma unroll
                for (int mt = 0; mt < 2; mt++) {
                    float* c0a = acc[mt * 8 + nh * 2];
                    float* c1a = acc[mt * 8 + nh * 2 + 1];
                    mma_bf16(c0a, ah[mt], bh[0], bh[1]);
                    mma_bf16(c1a, ah[mt], bh[2], bh[3]);
                    mma_bf16(c0a, ah[mt], bl[0], bl[1]);
                    mma_bf16(c1a, ah[mt], bl[2], bl[3]);
                    mma_bf16(c0a, al[mt], bh[0], bh[1]);
                    mma_bf16(c1a, al[mt], bh[2], bh[3]);
                }
            }
        }
        __syncthreads();
    }

    int crow = lane >> 2, cc = (lane & 3) * 2;
    unsigned char* qb = qkvout + (size_t)zz * 32 * 32 * 16384;
#pragma unroll
    for (int mt = 0; mt < 2; mt++) {
#pragma unroll
        for (int t8 = 0; t8 < 8; t8++) {
            const float* c = acc[mt * 8 + t8];
            int n = n0 + warp_n * 64 + t8 * 8 + cc;
            int r0 = m0 + warp_m * 32 + mt * 16 + crow;
            float bb0 = bias[n], bb1 = bias[n + 1];
            if (mode == 2) {
                *(float2*)(fout + (size_t)r0 * E_DIM + n)       = make_float2(c[0] + bb0, c[1] + bb1);
                *(float2*)(fout + (size_t)(r0 + 8) * E_DIM + n) = make_float2(c[2] + bb0, c[3] + bb1);
            } else {
                int h = n >> 6, d = n & 63;
#pragma unroll
                for (int rr = 0; rr < 2; rr++) {
                    int m = r0 + rr * 8;
                    int b = m >> 11, s = m & (S_DIM - 1);
                    int z = b * H_NUM + h;
                    uint32_t lo;
                    uint32_t hi = pack_f16(c[2 * rr] + bb0, c[2 * rr + 1] + bb1, lo);
                    unsigned char* tb = qb + ((size_t)(z * 32 + (s >> 6))) * 16384;
                    uint32_t sw = swp128(s & 63, d * 2);
                    *(uint32_t*)(tb + sw)        = hi;
                    *(uint32_t*)(tb + 8192 + sw) = lo;
                }
            }
        }
    }
}

// ---------------------------------------------------------------------------
// Fused attention, fp16 operands, 2 CTAs/SM.
// Pass 1: row sums, 1-term QK (hi planes only).
// Pass 2: 3-term QK (full precision attn) + 2-term PV (p packed fp16 hi).
// ---------------------------------------------------------------------------
#define FA_SMEM (65536 + 8192)
__global__ void __launch_bounds__(256, 2) fused_attn(
    const unsigned char* __restrict__ q2, const unsigned char* __restrict__ k2,
    const unsigned char* __restrict__ v2, const float* __restrict__ mask,
    float* __restrict__ attn, unsigned char* __restrict__ ctx2)
{
    extern __shared__ char sm[];
    uint32_t sb = smem_u32(sm);
    float* mrow = (float*)(sm + 65536);
    int tid = threadIdx.x, lane = tid & 31, wid = tid >> 5;
    int z = blockIdx.y, i0 = blockIdx.x * 128;
    const unsigned char* Kb = k2 + ((size_t)z * 32) * 16384;
    const unsigned char* Vb = v2 + ((size_t)z * 32) * 16384;
    const float* mb = mask + (size_t)(z >> 4) * S_DIM;
    int lrow = lane & 7, grp = lane >> 3;
    int g = lane >> 2, cc = (lane & 3) * 2;

    for (int t = tid; t < S_DIM; t += 256) mrow[t] = -1e9f * mb[t];
    {
        const unsigned char* qg = q2 + ((size_t)(z * 32 + (i0 >> 6))) * 16384;
#pragma unroll
        for (int i = 0; i < 8; i++)
            cpa16(sb + tid * 16 + i * 4096, qg + tid * 16 + i * 4096);
        CPA_COMMIT();
        CPA_WAIT0();
    }
    __syncthreads();

    uint32_t qh[4][4], ql[4][4];
#pragma unroll
    for (int t = 0; t < 4; t++) {
        int row = wid * 16 + lrow + (grp & 1) * 8;
        uint32_t off = (uint32_t)(row >> 6) * 16384 + swp128(row & 63, (t * 16 + (grp >> 1) * 8) * 2);
        ldm4(qh[t], sb + off);
        ldm4(ql[t], sb + 8192 + off);
    }
    __syncthreads();

    // ---------------- pass 1: row sums (K hi plane only, 1-term QK) ----------------
    float rsum0 = 0.f, rsum1 = 0.f;
    cp_tile8(sb, Kb, tid);
    CPA_COMMIT();
    for (int c = 0; c < 32; c++) {
        int cur = (c & 1) * 32768;
        if (c < 31) {
            cp_tile8(sb + (((c + 1) & 1) * 32768), Kb + (size_t)(c + 1) * 16384, tid);
            CPA_COMMIT();
            CPA_WAIT1();
        } else {
            CPA_WAIT0();
        }
        __syncthreads();
        uint32_t kh_base = sb + cur;
        float sc[8][4] = {};
#pragma unroll
        for (int t = 0; t < 4; t++) {
#pragma unroll
            for (int nt = 0; nt < 4; nt++) {
                int rowb = nt * 16 + lrow + ((grp >> 1) & 1) * 8;
                uint32_t offb = swp128(rowb, (t * 16 + (grp & 1) * 8) * 2);
                uint32_t bh[4];
                ldm4(bh, kh_base + offb);
                mma_f16(sc[nt * 2],     qh[t], bh[0], bh[1]);
                mma_f16(sc[nt * 2 + 1], qh[t], bh[2], bh[3]);
            }
        }
        int jb = c * 64;
#pragma unroll
        for (int t8 = 0; t8 < 8; t8++) {
            int j = jb + t8 * 8 + cc;
            float m0 = mrow[j], m1 = mrow[j + 1];
            rsum0 += __expf(sc[t8][0] * 0.125f + m0) + __expf(sc[t8][1] * 0.125f + m1);
            rsum1 += __expf(sc[t8][2] * 0.125f + m0) + __expf(sc[t8][3] * 0.125f + m1);
        }
        __syncthreads();
    }
    rsum0 += __shfl_xor_sync(0xFFFFFFFFu, rsum0, 1);
    rsum0 += __shfl_xor_sync(0xFFFFFFFFu, rsum0, 2);
    rsum1 += __shfl_xor_sync(0xFFFFFFFFu, rsum1, 1);
    rsum1 += __shfl_xor_sync(0xFFFFFFFFu, rsum1, 2);
    float inv0 = 1.0f / rsum0;
    float inv1 = 1.0f / rsum1;

    // ---------------- pass 2: attn + ctx ----------------
    int iRow = i0 + wid * 16 + g;
    float* attn0 = attn + ((size_t)z * S_DIM + iRow) * S_DIM;
    float* attn1 = attn0 + 8 * S_DIM;
    float cacc[8][4] = {};

    cp_tile16(sb, Kb, tid);
    cp_tile16(sb + 16384, Vb, tid);
    CPA_COMMIT();
    for (int c = 0; c < 32; c++) {
        int cur = (c & 1) * 32768;
        if (c < 31) {
            int nb = ((c + 1) & 1) * 32768;
            cp_tile16(sb + nb, Kb + (size_t)(c + 1) * 16384, tid);
            cp_tile16(sb + nb + 16384, Vb + (size_t)(c + 1) * 16384, tid);
            CPA_COMMIT();
            CPA_WAIT1();
        } else {
            CPA_WAIT0();
        }
        __syncthreads();
        uint32_t kh_base = sb + cur, kl_base = sb + cur + 8192;
        uint32_t vh_base = sb + cur + 16384, vl_base = sb + cur + 24576;
        float sc[8][4] = {};
#pragma unroll
        for (int t = 0; t < 4; t++) {
#pragma unroll
            for (int nt = 0; nt < 4; nt++) {
                int rowb = nt * 16 + lrow + ((grp >> 1) & 1) * 8;
                uint32_t offb = swp128(rowb, (t * 16 + (grp & 1) * 8) * 2);
                uint32_t bh[4], bl[4];
                ldm4(bh, kh_base + offb);
                ldm4(bl, kl_base + offb);
                float* c0a = sc[nt * 2];
                float* c1a = sc[nt * 2 + 1];
                mma_f16(c0a, qh[t], bh[0], bh[1]);
                mma_f16(c1a, qh[t], bh[2], bh[3]);
                mma_f16(c0a, qh[t], bl[0], bl[1]);
                mma_f16(c1a, qh[t], bl[2], bl[3]);
                mma_f16(c0a, ql[t], bh[0], bh[1]);
                mma_f16(c1a, ql[t], bh[2], bh[3]);
            }
        }
        // per k16-step: exp/normalize/write/pack (fp16 hi only) then 2-term PV
        int jb = c * 64;
#pragma unroll
        for (int t = 0; t < 4; t++) {
            uint32_t pah[4];
#pragma unroll
            for (int h2 = 0; h2 < 2; h2++) {
                int t8 = t * 2 + h2;
                int j = jb + t8 * 8 + cc;
                float m0 = mrow[j], m1 = mrow[j + 1];
                float p0 = __expf(sc[t8][0] * 0.125f + m0) * inv0;
                float p1 = __expf(sc[t8][1] * 0.125f + m1) * inv0;
                float p2 = __expf(sc[t8][2] * 0.125f + m0) * inv1;
                float p3 = __expf(sc[t8][3] * 0.125f + m1) * inv1;
                *(float2*)(attn0 + j) = make_float2(p0, p1);
                *(float2*)(attn1 + j) = make_float2(p2, p3);
                pah[h2 * 2]     = pack_f16_hi(p0, p1);
                pah[h2 * 2 + 1] = pack_f16_hi(p2, p3);
            }
#pragma unroll
            for (int dt = 0; dt < 4; dt++) {
                int krow = t * 16 + (lane & 15);
                int ncol = dt * 16 + (lane >> 4) * 8;
                uint32_t offb = swp128(krow, ncol * 2);
                uint32_t vh[4], vl[4];
                ldm4t(vh, vh_base + offb);
                ldm4t(vl, vl_base + offb);
                float* c0a = cacc[dt * 2];
                float* c1a = cacc[dt * 2 + 1];
                mma_f16(c0a, pah, vh[0], vh[1]);
                mma_f16(c1a, pah, vh[2], vh[3]);
                mma_f16(c0a, pah, vl[0], vl[1]);
                mma_f16(c1a, pah, vl[2], vl[3]);
            }
        }
        __syncthreads();
    }

    // ctx epilogue: write tiled bf16 hi/lo for O-proj A operand
    int b = z >> 4, h = z & 15;
    int mb2 = (b * S_DIM + i0) >> 7;
    int r = wid * 16 + g;
#pragma unroll
    for (int t8 = 0; t8 < 8; t8++) {
        int d0 = t8 * 8 + cc;
        int n = h * DH_DIM + d0;
        int kc = n >> 5, col = n & 31;
        unsigned char* base = ctx2 + ((size_t)(mb2 * 32 + kc)) * 16384;
        uint32_t lo0, lo1;
        uint32_t hi0 = pack_hilo(cacc[t8][0], cacc[t8][1], lo0);
        uint32_t hi1 = pack_hilo(cacc[t8][2], cacc[t8][3], lo1);
        uint32_t a0 = swp64(r, col * 2);
        uint32_t a1 = swp64(r + 8, col * 2);
        *(uint32_t*)(base + a0)        = hi0;
        *(uint32_t*)(base + 8192 + a0) = lo0;
        *(uint32_t*)(base + a1)        = hi1;
        *(uint32_t*)(base + 8192 + a1) = lo1;
    }
}

// ---------------------------------------------------------------------------

extern "C" void kernel_launch(void* const* d_in, const int* in_sizes, int n_in,
                              void* d_out, int out_size)
{
    const float* features = (const float*)d_in[0];
    const float* mask     = (const float*)d_in[1];
    const float* Wq = (const float*)d_in[2];
    const float* bq = (const float*)d_in[3];
    const float* Wk = (const float*)d_in[4];
    const float* bk = (const float*)d_in[5];
    const float* Wv = (const float*)d_in[6];
    const float* bv = (const float*)d_in[7];
    const float* Wo = (const float*)d_in[8];
    const float* bo = (const float*)d_in[9];
    float* out = (float*)d_out;

    unsigned char *A2, *W2, *qkv2, *ctx2;
    float* attn_scratch;
    cudaGetSymbolAddress((void**)&A2, g_A2);
    cudaGetSymbolAddress((void**)&W2, g_W2);
    cudaGetSymbolAddress((void**)&qkv2, g_qkv2);
    cudaGetSymbolAddress((void**)&ctx2, g_ctx2);
    cudaGetSymbolAddress((void**)&attn_scratch, g_attn);

    const long long OUT_ELEMS  = (long long)M_ROWS * E_DIM;
    const long long ATTN_ELEMS = (long long)BH_NUM * S_DIM * S_DIM;
    float* attn = ((long long)out_size >= OUT_ELEMS + ATTN_ELEMS)
                      ? (out + OUT_ELEMS) : attn_scratch;

    cudaFuncSetAttribute(proj_mma, cudaFuncAttributeMaxDynamicSharedMemorySize, PROJ_SMEM);
    cudaFuncSetAttribute(fused_attn, cudaFuncAttributeMaxDynamicSharedMemorySize, FA_SMEM);
    cudaFuncSetAttribute(proj_mma, cudaFuncAttributePreferredSharedMemoryCarveout, 100);
    cudaFuncSetAttribute(fused_attn, cudaFuncAttributePreferredSharedMemoryCarveout, 100);

    dim3 blk(256);
    convA<<<dim3(32, 32), blk>>>(features, A2);
    convW<<<dim3(32, 8, 4), blk>>>(Wq, Wk, Wv, Wo, W2);
    proj_mma<<<dim3(8, 32, 3), blk, PROJ_SMEM>>>(A2, W2, bq, bk, bv, qkv2, nullptr, 0);
    fused_attn<<<dim3(16, 32), blk, FA_SMEM>>>(
        qkv2, qkv2 + (size_t)32 * 32 * 16384, qkv2 + (size_t)2 * 32 * 32 * 16384,
        mask, attn, ctx2);
    proj_mma<<<dim3(8, 32, 1), blk, PROJ_SMEM>>>(
        ctx2, W2 + (size_t)3 * 8 * 32 * 16384, bo, bo, bo, nullptr, out, 2);
}

// round 12
// speedup vs baseline: 2.4146x; 1.1049x over previous
#include <cuda_runtime.h>
#include <cuda_bf16.h>
#include <cuda_fp16.h>
#include <cstdint>
#include <cstddef>

#define S_DIM 2048
#define E_DIM 1024
#define H_NUM 16
#define DH_DIM 64
#define B_NUM 2
#define BH_NUM (B_NUM * H_NUM)     // 32
#define M_ROWS (B_NUM * S_DIM)     // 4096

// tiled 16-bit hi/lo operand images (each tile = 8KB hi plane + 8KB lo plane)
// A2/W2/ctx2 are bf16 pairs; qkv2 are fp16 pairs.
__device__ __align__(16) unsigned char g_A2[(size_t)32 * 32 * 16384];        // features tiled [mb][kc]
__device__ __align__(16) unsigned char g_W2[(size_t)4 * 8 * 32 * 16384];     // 4 weights [w][nb][kc]
__device__ __align__(16) unsigned char g_qkv2[(size_t)3 * 32 * 32 * 16384];  // q/k/v [which][z][t] (fp16)
__device__ __align__(16) unsigned char g_ctx2[(size_t)32 * 32 * 16384];      // ctx tiled [mb][kc]
__device__ float g_attn[(size_t)BH_NUM * S_DIM * S_DIM];                     // fallback

// ---------------------------------------------------------------------------
// helpers
// ---------------------------------------------------------------------------
__device__ __forceinline__ uint32_t smem_u32(const void* p) {
    uint32_t a;
    asm("{ .reg .u64 t; cvta.to.shared.u64 t, %1; cvt.u32.u64 %0, t; }" : "=r"(a) : "l"(p));
    return a;
}
__device__ __forceinline__ void ldm4(uint32_t* r, uint32_t a) {
    asm volatile("ldmatrix.sync.aligned.m8n8.x4.shared.b16 {%0,%1,%2,%3}, [%4];"
        : "=r"(r[0]), "=r"(r[1]), "=r"(r[2]), "=r"(r[3]) : "r"(a));
}
__device__ __forceinline__ void ldm4t(uint32_t* r, uint32_t a) {
    asm volatile("ldmatrix.sync.aligned.m8n8.x4.trans.shared.b16 {%0,%1,%2,%3}, [%4];"
        : "=r"(r[0]), "=r"(r[1]), "=r"(r[2]), "=r"(r[3]) : "r"(a));
}
__device__ __forceinline__ void mma_bf16(float* c, const uint32_t* a, uint32_t b0, uint32_t b1) {
    asm volatile(
        "mma.sync.aligned.m16n8k16.row.col.f32.bf16.bf16.f32 "
        "{%0,%1,%2,%3}, {%4,%5,%6,%7}, {%8,%9}, {%0,%1,%2,%3};"
        : "+f"(c[0]), "+f"(c[1]), "+f"(c[2]), "+f"(c[3])
        : "r"(a[0]), "r"(a[1]), "r"(a[2]), "r"(a[3]), "r"(b0), "r"(b1));
}
__device__ __forceinline__ void mma_f16(float* c, const uint32_t* a, uint32_t b0, uint32_t b1) {
    asm volatile(
        "mma.sync.aligned.m16n8k16.row.col.f32.f16.f16.f32 "
        "{%0,%1,%2,%3}, {%4,%5,%6,%7}, {%8,%9}, {%0,%1,%2,%3};"
        : "+f"(c[0]), "+f"(c[1]), "+f"(c[2]), "+f"(c[3])
        : "r"(a[0]), "r"(a[1]), "r"(a[2]), "r"(a[3]), "r"(b0), "r"(b1));
}
__device__ __forceinline__ void cpa16(uint32_t s, const void* g) {
    asm volatile("cp.async.cg.shared.global [%0], [%1], 16;" :: "r"(s), "l"(g));
}
#define CPA_COMMIT() asm volatile("cp.async.commit_group;" ::: "memory")
#define CPA_WAIT0()  asm volatile("cp.async.wait_group 0;" ::: "memory")
#define CPA_WAIT1()  asm volatile("cp.async.wait_group 1;" ::: "memory")

__device__ __forceinline__ uint32_t swp128(int row, int c2) { return (uint32_t)(row * 128 + c2) ^ ((row & 7) << 4); }
__device__ __forceinline__ uint32_t swp64 (int row, int c2) { return (uint32_t)(row * 64  + c2) ^ (((row >> 1) & 3) << 4); }
__device__ __forceinline__ uint32_t swp256(int row, int c2) { return (uint32_t)(row * 256 + c2) ^ ((row & 7) << 4); }

__device__ __forceinline__ void split8(const float* v, uint32_t* hi, uint32_t* lo) {
#pragma unroll
    for (int q = 0; q < 4; q++) {
        __nv_bfloat16 h0 = __float2bfloat16(v[2*q]);
        __nv_bfloat16 h1 = __float2bfloat16(v[2*q+1]);
        __nv_bfloat16 l0 = __float2bfloat16(v[2*q]   - __bfloat162float(h0));
        __nv_bfloat16 l1 = __float2bfloat16(v[2*q+1] - __bfloat162float(h1));
        hi[q] = (uint32_t)__bfloat16_as_ushort(h0) | ((uint32_t)__bfloat16_as_ushort(h1) << 16);
        lo[q] = (uint32_t)__bfloat16_as_ushort(l0) | ((uint32_t)__bfloat16_as_ushort(l1) << 16);
    }
}
__device__ __forceinline__ uint32_t pack_hilo(float a, float b, uint32_t& lo) {
    __nv_bfloat16 ha = __float2bfloat16(a), hb = __float2bfloat16(b);
    __nv_bfloat16 la = __float2bfloat16(a - __bfloat162float(ha));
    __nv_bfloat16 lb = __float2bfloat16(b - __bfloat162float(hb));
    lo = (uint32_t)__bfloat16_as_ushort(la) | ((uint32_t)__bfloat16_as_ushort(lb) << 16);
    return (uint32_t)__bfloat16_as_ushort(ha) | ((uint32_t)__bfloat16_as_ushort(hb) << 16);
}
__device__ __forceinline__ uint32_t pack_f16(float a, float b, uint32_t& lo) {
    __half ha = __float2half_rn(a), hb = __float2half_rn(b);
    __half la = __float2half_rn(a - __half2float(ha));
    __half lb = __float2half_rn(b - __half2float(hb));
    lo = (uint32_t)__half_as_ushort(la) | ((uint32_t)__half_as_ushort(lb) << 16);
    return (uint32_t)__half_as_ushort(ha) | ((uint32_t)__half_as_ushort(hb) << 16);
}
__device__ __forceinline__ uint32_t pack_f16_hi(float a, float b) {
    __half ha = __float2half_rn(a), hb = __float2half_rn(b);
    return (uint32_t)__half_as_ushort(ha) | ((uint32_t)__half_as_ushort(hb) << 16);
}
// copy one 16KB tile (hi+lo planes) gmem->smem, 256 threads
__device__ __forceinline__ void cp_tile16(uint32_t sdst, const unsigned char* gsrc, int tid) {
#pragma unroll
    for (int i = 0; i < 4; i++)
        cpa16(sdst + tid * 16 + i * 4096, gsrc + tid * 16 + i * 4096);
}
// copy only the 8KB hi plane
__device__ __forceinline__ void cp_tile8(uint32_t sdst, const unsigned char* gsrc, int tid) {
#pragma unroll
    for (int i = 0; i < 2; i++)
        cpa16(sdst + tid * 16 + i * 4096, gsrc + tid * 16 + i * 4096);
}

// ---------------------------------------------------------------------------
// conversion kernels (run once, cheap) — bf16 images for proj operands
// ---------------------------------------------------------------------------
__global__ void __launch_bounds__(256) convA(const float* __restrict__ src,
                                             unsigned char* __restrict__ dst)
{
    int kc = blockIdx.x, mb = blockIdx.y;
    int tid = threadIdx.x;
    int row = tid >> 1, c0 = (tid & 1) * 16;
    const float* p = src + (size_t)(mb * 128 + row) * E_DIM + kc * 32 + c0;
    unsigned char* base = dst + ((size_t)(mb * 32 + kc)) * 16384;
#pragma unroll
    for (int gi = 0; gi < 2; gi++) {
        float v[8];
        *(float4*)(v)     = *(const float4*)(p + gi * 8);
        *(float4*)(v + 4) = *(const float4*)(p + gi * 8 + 4);
        uint32_t hi[4], lo[4];
        split8(v, hi, lo);
        uint32_t sw = swp64(row, (c0 + gi * 8) * 2);
        *(uint4*)(base + sw)        = make_uint4(hi[0], hi[1], hi[2], hi[3]);
        *(uint4*)(base + 8192 + sw) = make_uint4(lo[0], lo[1], lo[2], lo[3]);
    }
}
__global__ void __launch_bounds__(256) convW(
    const float* __restrict__ Wq, const float* __restrict__ Wk,
    const float* __restrict__ Wv, const float* __restrict__ Wo,
    unsigned char* __restrict__ dst)
{
    int kc = blockIdx.x, nb = blockIdx.y, w = blockIdx.z;
    const float* W = w == 0 ? Wq : (w == 1 ? Wk : (w == 2 ? Wv : Wo));
    int tid = threadIdx.x;
    int krow = tid >> 3, nseg = (tid & 7) * 16;
    const float* p = W + (size_t)(kc * 32 + krow) * E_DIM + nb * 128 + nseg;
    unsigned char* base = dst + ((size_t)w * 8 * 32 + (size_t)(nb * 32 + kc)) * 16384;
#pragma unroll
    for (int gi = 0; gi < 2; gi++) {
        float v[8];
        *(float4*)(v)     = *(const float4*)(p + gi * 8);
        *(float4*)(v + 4) = *(const float4*)(p + gi * 8 + 4);
        uint32_t hi[4], lo[4];
        split8(v, hi, lo);
        uint32_t sw = swp256(krow, (nseg + gi * 8) * 2);
        *(uint4*)(base + sw)        = make_uint4(hi[0], hi[1], hi[2], hi[3]);
        *(uint4*)(base + 8192 + sw) = make_uint4(lo[0], lo[1], lo[2], lo[3]);
    }
}

// ---------------------------------------------------------------------------
// Projection GEMM from pre-tiled bf16 operands, cp.async double-buffered.
// mode 0: epilogue packs q/k/v as fp16 hi/lo tiles.  mode 2: fp32 out + bias.
// ---------------------------------------------------------------------------
#define PROJ_SMEM 65536
__global__ void __launch_bounds__(256, 2) proj_mma(
    const unsigned char* __restrict__ A2, const unsigned char* __restrict__ W2,
    const float* __restrict__ b0p, const float* __restrict__ b1p, const float* __restrict__ b2p,
    unsigned char* __restrict__ qkvout, float* __restrict__ fout, int mode)
{
    extern __shared__ char sm[];
    uint32_t sb = smem_u32(sm);
    int zz = blockIdx.z;
    const float* bias = zz == 0 ? b0p : (zz == 1 ? b1p : b2p);
    const unsigned char* Wsel = W2 + (size_t)zz * 8 * 32 * 16384;

    int tid = threadIdx.x, lane = tid & 31, wid = tid >> 5;
    int warp_m = wid & 3, warp_n = wid >> 2;
    int n0 = blockIdx.x * 128, m0 = blockIdx.y * 128;
    int lrow = lane & 7, grp = lane >> 3;
    const unsigned char* Abase = A2 + ((size_t)(m0 >> 7) * 32) * 16384;
    const unsigned char* Wbase = Wsel + ((size_t)(n0 >> 7) * 32) * 16384;

    float acc[16][4] = {};
    cp_tile16(sb, Abase, tid);
    cp_tile16(sb + 16384, Wbase, tid);
    CPA_COMMIT();

    for (int c = 0; c < 32; c++) {
        int cur = (c & 1) * 32768;
        if (c < 31) {
            int nb = ((c + 1) & 1) * 32768;
            cp_tile16(sb + nb, Abase + (size_t)(c + 1) * 16384, tid);
            cp_tile16(sb + nb + 16384, Wbase + (size_t)(c + 1) * 16384, tid);
            CPA_COMMIT();
            CPA_WAIT1();
        } else {
            CPA_WAIT0();
        }
        __syncthreads();
        uint32_t sa_hi = sb + cur, sa_lo = sb + cur + 8192;
        uint32_t sw_hi = sb + cur + 16384, sw_lo = sb + cur + 24576;
#pragma unroll
        for (int ks = 0; ks < 2; ks++) {
            int k = ks * 16;
            uint32_t ah[2][4], al[2][4];
#pragma unroll
            for (int mt = 0; mt < 2; mt++) {
                int row = warp_m * 32 + mt * 16 + lrow + (grp & 1) * 8;
                uint32_t off = swp64(row, (k + (grp >> 1) * 8) * 2);
                ldm4(ah[mt], sa_hi + off);
                ldm4(al[mt], sa_lo + off);
            }
#pragma unroll
            for (int nh = 0; nh < 4; nh++) {
                int krow = k + (lane & 15);
                int ncol = warp_n * 64 + nh * 16 + (lane >> 4) * 8;
                uint32_t offb = swp256(krow, ncol * 2);
                uint32_t bh[4], bl[4];
                ldm4t(bh, sw_hi + offb);
                ldm4t(bl, sw_lo + offb);
#pragma unroll
                for (int mt = 0; mt < 2; mt++) {
                    float* c0a = acc[mt * 8 + nh * 2];
                    float* c1a = acc[mt * 8 + nh * 2 + 1];
                    mma_bf16(c0a, ah[mt], bh[0], bh[1]);
                    mma_bf16(c1a, ah[mt], bh[2], bh[3]);
                    mma_bf16(c0a, ah[mt], bl[0], bl[1]);
                    mma_bf16(c1a, ah[mt], bl[2], bl[3]);
                    mma_bf16(c0a, al[mt], bh[0], bh[1]);
                    mma_bf16(c1a, al[mt], bh[2], bh[3]);
                }
            }
        }
        __syncthreads();
    }

    int crow = lane >> 2, cc = (lane & 3) * 2;
    unsigned char* qb = qkvout + (size_t)zz * 32 * 32 * 16384;
#pragma unroll
    for (int mt = 0; mt < 2; mt++) {
#pragma unroll
        for (int t8 = 0; t8 < 8; t8++) {
            const float* c = acc[mt * 8 + t8];
            int n = n0 + warp_n * 64 + t8 * 8 + cc;
            int r0 = m0 + warp_m * 32 + mt * 16 + crow;
            float bb0 = bias[n], bb1 = bias[n + 1];
            if (mode == 2) {
                *(float2*)(fout + (size_t)r0 * E_DIM + n)       = make_float2(c[0] + bb0, c[1] + bb1);
                *(float2*)(fout + (size_t)(r0 + 8) * E_DIM + n) = make_float2(c[2] + bb0, c[3] + bb1);
            } else {
                int h = n >> 6, d = n & 63;
#pragma unroll
                for (int rr = 0; rr < 2; rr++) {
                    int m = r0 + rr * 8;
                    int b = m >> 11, s = m & (S_DIM - 1);
                    int z = b * H_NUM + h;
                    uint32_t lo;
                    uint32_t hi = pack_f16(c[2 * rr] + bb0, c[2 * rr + 1] + bb1, lo);
                    unsigned char* tb = qb + ((size_t)(z * 32 + (s >> 6))) * 16384;
                    uint32_t sw = swp128(s & 63, d * 2);
                    *(uint32_t*)(tb + sw)        = hi;
                    *(uint32_t*)(tb + 8192 + sw) = lo;
                }
            }
        }
    }
}

// ---------------------------------------------------------------------------
// Fused attention, fp16 operands, 2 CTAs/SM.
// Pass 1: row sums, 1-term QK (K hi plane only).
// Pass 2: 2-term QK ((qh+ql)·kh — K lo dropped) + 2-term PV (p_hi · (vh+vl)).
// Pass-2 staging: K hi 8KB + V hi/lo 16KB = 24KB per chunk, double-buffered.
// ---------------------------------------------------------------------------
#define FA_SMEM (65536 + 8192)
__global__ void __launch_bounds__(256, 2) fused_attn(
    const unsigned char* __restrict__ q2, const unsigned char* __restrict__ k2,
    const unsigned char* __restrict__ v2, const float* __restrict__ mask,
    float* __restrict__ attn, unsigned char* __restrict__ ctx2)
{
    extern __shared__ char sm[];
    uint32_t sb = smem_u32(sm);
    float* mrow = (float*)(sm + 65536);
    int tid = threadIdx.x, lane = tid & 31, wid = tid >> 5;
    int z = blockIdx.y, i0 = blockIdx.x * 128;
    const unsigned char* Kb = k2 + ((size_t)z * 32) * 16384;
    const unsigned char* Vb = v2 + ((size_t)z * 32) * 16384;
    const float* mb = mask + (size_t)(z >> 4) * S_DIM;
    int lrow = lane & 7, grp = lane >> 3;
    int g = lane >> 2, cc = (lane & 3) * 2;

    for (int t = tid; t < S_DIM; t += 256) mrow[t] = -1e9f * mb[t];
    {
        const unsigned char* qg = q2 + ((size_t)(z * 32 + (i0 >> 6))) * 16384;
#pragma unroll
        for (int i = 0; i < 8; i++)
            cpa16(sb + tid * 16 + i * 4096, qg + tid * 16 + i * 4096);
        CPA_COMMIT();
        CPA_WAIT0();
    }
    __syncthreads();

    uint32_t qh[4][4], ql[4][4];
#pragma unroll
    for (int t = 0; t < 4; t++) {
        int row = wid * 16 + lrow + (grp & 1) * 8;
        uint32_t off = (uint32_t)(row >> 6) * 16384 + swp128(row & 63, (t * 16 + (grp >> 1) * 8) * 2);
        ldm4(qh[t], sb + off);
        ldm4(ql[t], sb + 8192 + off);
    }
    __syncthreads();

    // ---------------- pass 1: row sums (K hi plane only, 1-term QK) ----------------
    float rsum0 = 0.f, rsum1 = 0.f;
    cp_tile8(sb, Kb, tid);
    CPA_COMMIT();
    for (int c = 0; c < 32; c++) {
        int cur = (c & 1) * 32768;
        if (c < 31) {
            cp_tile8(sb + (((c + 1) & 1) * 32768), Kb + (size_t)(c + 1) * 16384, tid);
            CPA_COMMIT();
            CPA_WAIT1();
        } else {
            CPA_WAIT0();
        }
        __syncthreads();
        uint32_t kh_base = sb + cur;
        float sc[8][4] = {};
#pragma unroll
        for (int t = 0; t < 4; t++) {
#pragma unroll
            for (int nt = 0; nt < 4; nt++) {
                int rowb = nt * 16 + lrow + ((grp >> 1) & 1) * 8;
                uint32_t offb = swp128(rowb, (t * 16 + (grp & 1) * 8) * 2);
                uint32_t bh[4];
                ldm4(bh, kh_base + offb);
                mma_f16(sc[nt * 2],     qh[t], bh[0], bh[1]);
                mma_f16(sc[nt * 2 + 1], qh[t], bh[2], bh[3]);
            }
        }
        int jb = c * 64;
#pragma unroll
        for (int t8 = 0; t8 < 8; t8++) {
            int j = jb + t8 * 8 + cc;
            float m0 = mrow[j], m1 = mrow[j + 1];
            rsum0 += __expf(sc[t8][0] * 0.125f + m0) + __expf(sc[t8][1] * 0.125f + m1);
            rsum1 += __expf(sc[t8][2] * 0.125f + m0) + __expf(sc[t8][3] * 0.125f + m1);
        }
        __syncthreads();
    }
    rsum0 += __shfl_xor_sync(0xFFFFFFFFu, rsum0, 1);
    rsum0 += __shfl_xor_sync(0xFFFFFFFFu, rsum0, 2);
    rsum1 += __shfl_xor_sync(0xFFFFFFFFu, rsum1, 1);
    rsum1 += __shfl_xor_sync(0xFFFFFFFFu, rsum1, 2);
    float inv0 = 1.0f / rsum0;
    float inv1 = 1.0f / rsum1;

    // ---------------- pass 2: attn + ctx (K hi + V hi/lo, 24KB/chunk) ----------------
    int iRow = i0 + wid * 16 + g;
    float* attn0 = attn + ((size_t)z * S_DIM + iRow) * S_DIM;
    float* attn1 = attn0 + 8 * S_DIM;
    float cacc[8][4] = {};

    cp_tile8(sb, Kb, tid);
    cp_tile16(sb + 8192, Vb, tid);
    CPA_COMMIT();
    for (int c = 0; c < 32; c++) {
        int cur = (c & 1) * 24576;
        if (c < 31) {
            int nb = ((c + 1) & 1) * 24576;
            cp_tile8(sb + nb, Kb + (size_t)(c + 1) * 16384, tid);
            cp_tile16(sb + nb + 8192, Vb + (size_t)(c + 1) * 16384, tid);
            CPA_COMMIT();
            CPA_WAIT1();
        } else {
            CPA_WAIT0();
        }
        __syncthreads();
        uint32_t kh_base = sb + cur;
        uint32_t vh_base = sb + cur + 8192, vl_base = sb + cur + 16384;
        float sc[8][4] = {};
#pragma unroll
        for (int t = 0; t < 4; t++) {
#pragma unroll
            for (int nt = 0; nt < 4; nt++) {
                int rowb = nt * 16 + lrow + ((grp >> 1) & 1) * 8;
                uint32_t offb = swp128(rowb, (t * 16 + (grp & 1) * 8) * 2);
                uint32_t bh[4];
                ldm4(bh, kh_base + offb);
                float* c0a = sc[nt * 2];
                float* c1a = sc[nt * 2 + 1];
                mma_f16(c0a, qh[t], bh[0], bh[1]);
                mma_f16(c1a, qh[t], bh[2], bh[3]);
                mma_f16(c0a, ql[t], bh[0], bh[1]);
                mma_f16(c1a, ql[t], bh[2], bh[3]);
            }
        }
        // per k16-step: exp/normalize/write/pack (fp16 hi only) then 2-term PV
        int jb = c * 64;
#pragma unroll
        for (int t = 0; t < 4; t++) {
            uint32_t pah[4];
#pragma unroll
            for (int h2 = 0; h2 < 2; h2++) {
                int t8 = t * 2 + h2;
                int j = jb + t8 * 8 + cc;
                float m0 = mrow[j], m1 = mrow[j + 1];
                float p0 = __expf(sc[t8][0] * 0.125f + m0) * inv0;
                float p1 = __expf(sc[t8][1] * 0.125f + m1) * inv0;
                float p2 = __expf(sc[t8][2] * 0.125f + m0) * inv1;
                float p3 = __expf(sc[t8][3] * 0.125f + m1) * inv1;
                *(float2*)(attn0 + j) = make_float2(p0, p1);
                *(float2*)(attn1 + j) = make_float2(p2, p3);
                pah[h2 * 2]     = pack_f16_hi(p0, p1);
                pah[h2 * 2 + 1] = pack_f16_hi(p2, p3);
            }
#pragma unroll
            for (int dt = 0; dt < 4; dt++) {
                int krow = t * 16 + (lane & 15);
                int ncol = dt * 16 + (lane >> 4) * 8;
                uint32_t offb = swp128(krow, ncol * 2);
                uint32_t vh[4], vl[4];
                ldm4t(vh, vh_base + offb);
                ldm4t(vl, vl_base + offb);
                float* c0a = cacc[dt * 2];
                float* c1a = cacc[dt * 2 + 1];
                mma_f16(c0a, pah, vh[0], vh[1]);
                mma_f16(c1a, pah, vh[2], vh[3]);
                mma_f16(c0a, pah, vl[0], vl[1]);
                mma_f16(c1a, pah, vl[2], vl[3]);
            }
        }
        __syncthreads();
    }

    // ctx epilogue: write tiled bf16 hi/lo for O-proj A operand
    int b = z >> 4, h = z & 15;
    int mb2 = (b * S_DIM + i0) >> 7;
    int r = wid * 16 + g;
#pragma unroll
    for (int t8 = 0; t8 < 8; t8++) {
        int d0 = t8 * 8 + cc;
        int n = h * DH_DIM + d0;
        int kc = n >> 5, col = n & 31;
        unsigned char* base = ctx2 + ((size_t)(mb2 * 32 + kc)) * 16384;
        uint32_t lo0, lo1;
        uint32_t hi0 = pack_hilo(cacc[t8][0], cacc[t8][1], lo0);
        uint32_t hi1 = pack_hilo(cacc[t8][2], cacc[t8][3], lo1);
        uint32_t a0 = swp64(r, col * 2);
        uint32_t a1 = swp64(r + 8, col * 2);
        *(uint32_t*)(base + a0)        = hi0;
        *(uint32_t*)(base + 8192 + a0) = lo0;
        *(uint32_t*)(base + a1)        = hi1;
        *(uint32_t*)(base + 8192 + a1) = lo1;
    }
}

// ---------------------------------------------------------------------------

extern "C" void kernel_launch(void* const* d_in, const int* in_sizes, int n_in,
                              void* d_out, int out_size)
{
    const float* features = (const float*)d_in[0];
    const float* mask     = (const float*)d_in[1];
    const float* Wq = (const float*)d_in[2];
    const float* bq = (const float*)d_in[3];
    const float* Wk = (const float*)d_in[4];
    const float* bk = (const float*)d_in[5];
    const float* Wv = (const float*)d_in[6];
    const float* bv = (const float*)d_in[7];
    const float* Wo = (const float*)d_in[8];
    const float* bo = (const float*)d_in[9];
    float* out = (float*)d_out;

    unsigned char *A2, *W2, *qkv2, *ctx2;
    float* attn_scratch;
    cudaGetSymbolAddress((void**)&A2, g_A2);
    cudaGetSymbolAddress((void**)&W2, g_W2);
    cudaGetSymbolAddress((void**)&qkv2, g_qkv2);
    cudaGetSymbolAddress((void**)&ctx2, g_ctx2);
    cudaGetSymbolAddress((void**)&attn_scratch, g_attn);

    const long long OUT_ELEMS  = (long long)M_ROWS * E_DIM;
    const long long ATTN_ELEMS = (long long)BH_NUM * S_DIM * S_DIM;
    float* attn = ((long long)out_size >= OUT_ELEMS + ATTN_ELEMS)
                      ? (out + OUT_ELEMS) : attn_scratch;

    cudaFuncSetAttribute(proj_mma, cudaFuncAttributeMaxDynamicSharedMemorySize, PROJ_SMEM);
    cudaFuncSetAttribute(fused_attn, cudaFuncAttributeMaxDynamicSharedMemorySize, FA_SMEM);
    cudaFuncSetAttribute(proj_mma, cudaFuncAttributePreferredSharedMemoryCarveout, 100);
    cudaFuncSetAttribute(fused_attn, cudaFuncAttributePreferredSharedMemoryCarveout, 100);

    dim3 blk(256);
    convA<<<dim3(32, 32), blk>>>(features, A2);
    convW<<<dim3(32, 8, 4), blk>>>(Wq, Wk, Wv, Wo, W2);
    proj_mma<<<dim3(8, 32, 3), blk, PROJ_SMEM>>>(A2, W2, bq, bk, bv, qkv2, nullptr, 0);
    fused_attn<<<dim3(16, 32), blk, FA_SMEM>>>(
        qkv2, qkv2 + (size_t)32 * 32 * 16384, qkv2 + (size_t)2 * 32 * 32 * 16384,
        mask, attn, ctx2);
    proj_mma<<<dim3(8, 32, 1), blk, PROJ_SMEM>>>(
        ctx2, W2 + (size_t)3 * 8 * 32 * 16384, bo, bo, bo, nullptr, out, 2);
}

// round 13
// speedup vs baseline: 2.6473x; 1.0964x over previous
#include <cuda_runtime.h>
#include <cuda_bf16.h>
#include <cuda_fp16.h>
#include <cstdint>
#include <cstddef>

#define S_DIM 2048
#define E_DIM 1024
#define H_NUM 16
#define DH_DIM 64
#define B_NUM 2
#define BH_NUM (B_NUM * H_NUM)     // 32
#define M_ROWS (B_NUM * S_DIM)     // 4096

// tiled 16-bit hi/lo operand images (each tile = 8KB hi plane + 8KB lo plane)
// A2/W2/ctx2 are bf16 pairs; qkv2 are fp16 pairs.
__device__ __align__(16) unsigned char g_A2[(size_t)32 * 32 * 16384];        // features tiled [mb][kc]
__device__ __align__(16) unsigned char g_W2[(size_t)4 * 8 * 32 * 16384];     // 4 weights [w][nb][kc]
__device__ __align__(16) unsigned char g_qkv2[(size_t)3 * 32 * 32 * 16384];  // q/k/v [which][z][t] (fp16)
__device__ __align__(16) unsigned char g_ctx2[(size_t)32 * 32 * 16384];      // ctx tiled [mb][kc]
__device__ float g_attn[(size_t)BH_NUM * S_DIM * S_DIM];                     // fallback

// ---------------------------------------------------------------------------
// helpers
// ---------------------------------------------------------------------------
__device__ __forceinline__ uint32_t smem_u32(const void* p) {
    uint32_t a;
    asm("{ .reg .u64 t; cvta.to.shared.u64 t, %1; cvt.u32.u64 %0, t; }" : "=r"(a) : "l"(p));
    return a;
}
__device__ __forceinline__ void ldm4(uint32_t* r, uint32_t a) {
    asm volatile("ldmatrix.sync.aligned.m8n8.x4.shared.b16 {%0,%1,%2,%3}, [%4];"
        : "=r"(r[0]), "=r"(r[1]), "=r"(r[2]), "=r"(r[3]) : "r"(a));
}
__device__ __forceinline__ void ldm4t(uint32_t* r, uint32_t a) {
    asm volatile("ldmatrix.sync.aligned.m8n8.x4.trans.shared.b16 {%0,%1,%2,%3}, [%4];"
        : "=r"(r[0]), "=r"(r[1]), "=r"(r[2]), "=r"(r[3]) : "r"(a));
}
__device__ __forceinline__ void mma_bf16(float* c, const uint32_t* a, uint32_t b0, uint32_t b1) {
    asm volatile(
        "mma.sync.aligned.m16n8k16.row.col.f32.bf16.bf16.f32 "
        "{%0,%1,%2,%3}, {%4,%5,%6,%7}, {%8,%9}, {%0,%1,%2,%3};"
        : "+f"(c[0]), "+f"(c[1]), "+f"(c[2]), "+f"(c[3])
        : "r"(a[0]), "r"(a[1]), "r"(a[2]), "r"(a[3]), "r"(b0), "r"(b1));
}
__device__ __forceinline__ void mma_f16(float* c, const uint32_t* a, uint32_t b0, uint32_t b1) {
    asm volatile(
        "mma.sync.aligned.m16n8k16.row.col.f32.f16.f16.f32 "
        "{%0,%1,%2,%3}, {%4,%5,%6,%7}, {%8,%9}, {%0,%1,%2,%3};"
        : "+f"(c[0]), "+f"(c[1]), "+f"(c[2]), "+f"(c[3])
        : "r"(a[0]), "r"(a[1]), "r"(a[2]), "r"(a[3]), "r"(b0), "r"(b1));
}
__device__ __forceinline__ void cpa16(uint32_t s, const void* g) {
    asm volatile("cp.async.cg.shared.global [%0], [%1], 16;" :: "r"(s), "l"(g));
}
#define CPA_COMMIT() asm volatile("cp.async.commit_group;" ::: "memory")
#define CPA_WAIT0()  asm volatile("cp.async.wait_group 0;" ::: "memory")
#define CPA_WAIT1()  asm volatile("cp.async.wait_group 1;" ::: "memory")

__device__ __forceinline__ uint32_t swp128(int row, int c2) { return (uint32_t)(row * 128 + c2) ^ ((row & 7) << 4); }
__device__ __forceinline__ uint32_t swp64 (int row, int c2) { return (uint32_t)(row * 64  + c2) ^ (((row >> 1) & 3) << 4); }
__device__ __forceinline__ uint32_t swp256(int row, int c2) { return (uint32_t)(row * 256 + c2) ^ ((row & 7) << 4); }

__device__ __forceinline__ void split8(const float* v, uint32_t* hi, uint32_t* lo) {
#pragma unroll
    for (int q = 0; q < 4; q++) {
        __nv_bfloat16 h0 = __float2bfloat16(v[2*q]);
        __nv_bfloat16 h1 = __float2bfloat16(v[2*q+1]);
        __nv_bfloat16 l0 = __float2bfloat16(v[2*q]   - __bfloat162float(h0));
        __nv_bfloat16 l1 = __float2bfloat16(v[2*q+1] - __bfloat162float(h1));
        hi[q] = (uint32_t)__bfloat16_as_ushort(h0) | ((uint32_t)__bfloat16_as_ushort(h1) << 16);
        lo[q] = (uint32_t)__bfloat16_as_ushort(l0) | ((uint32_t)__bfloat16_as_ushort(l1) << 16);
    }
}
__device__ __forceinline__ uint32_t pack_hilo(float a, float b, uint32_t& lo) {
    __nv_bfloat16 ha = __float2bfloat16(a), hb = __float2bfloat16(b);
    __nv_bfloat16 la = __float2bfloat16(a - __bfloat162float(ha));
    __nv_bfloat16 lb = __float2bfloat16(b - __bfloat162float(hb));
    lo = (uint32_t)__bfloat16_as_ushort(la) | ((uint32_t)__bfloat16_as_ushort(lb) << 16);
    return (uint32_t)__bfloat16_as_ushort(ha) | ((uint32_t)__bfloat16_as_ushort(hb) << 16);
}
__device__ __forceinline__ uint32_t pack_f16(float a, float b, uint32_t& lo) {
    __half ha = __float2half_rn(a), hb = __float2half_rn(b);
    __half la = __float2half_rn(a - __half2float(ha));
    __half lb = __float2half_rn(b - __half2float(hb));
    lo = (uint32_t)__half_as_ushort(la) | ((uint32_t)__half_as_ushort(lb) << 16);
    return (uint32_t)__half_as_ushort(ha) | ((uint32_t)__half_as_ushort(hb) << 16);
}
__device__ __forceinline__ uint32_t pack_f16_hi(float a, float b) {
    __half ha = __float2half_rn(a), hb = __float2half_rn(b);
    return (uint32_t)__half_as_ushort(ha) | ((uint32_t)__half_as_ushort(hb) << 16);
}
// copy one 16KB tile (hi+lo planes) gmem->smem, 256 threads
__device__ __forceinline__ void cp_tile16(uint32_t sdst, const unsigned char* gsrc, int tid) {
#pragma unroll
    for (int i = 0; i < 4; i++)
        cpa16(sdst + tid * 16 + i * 4096, gsrc + tid * 16 + i * 4096);
}
// copy only the 8KB hi plane
__device__ __forceinline__ void cp_tile8(uint32_t sdst, const unsigned char* gsrc, int tid) {
#pragma unroll
    for (int i = 0; i < 2; i++)
        cpa16(sdst + tid * 16 + i * 4096, gsrc + tid * 16 + i * 4096);
}

// ---------------------------------------------------------------------------
// conversion kernels (run once, cheap) — bf16 images for proj operands
// ---------------------------------------------------------------------------
__global__ void __launch_bounds__(256) convA(const float* __restrict__ src,
                                             unsigned char* __restrict__ dst)
{
    int kc = blockIdx.x, mb = blockIdx.y;
    int tid = threadIdx.x;
    int row = tid >> 1, c0 = (tid & 1) * 16;
    const float* p = src + (size_t)(mb * 128 + row) * E_DIM + kc * 32 + c0;
    unsigned char* base = dst + ((size_t)(mb * 32 + kc)) * 16384;
#pragma unroll
    for (int gi = 0; gi < 2; gi++) {
        float v[8];
        *(float4*)(v)     = *(const float4*)(p + gi * 8);
        *(float4*)(v + 4) = *(const float4*)(p + gi * 8 + 4);
        uint32_t hi[4], lo[4];
        split8(v, hi, lo);
        uint32_t sw = swp64(row, (c0 + gi * 8) * 2);
        *(uint4*)(base + sw)        = make_uint4(hi[0], hi[1], hi[2], hi[3]);
        *(uint4*)(base + 8192 + sw) = make_uint4(lo[0], lo[1], lo[2], lo[3]);
    }
}
__global__ void __launch_bounds__(256) convW(
    const float* __restrict__ Wq, const float* __restrict__ Wk,
    const float* __restrict__ Wv, const float* __restrict__ Wo,
    unsigned char* __restrict__ dst)
{
    int kc = blockIdx.x, nb = blockIdx.y, w = blockIdx.z;
    const float* W = w == 0 ? Wq : (w == 1 ? Wk : (w == 2 ? Wv : Wo));
    int tid = threadIdx.x;
    int krow = tid >> 3, nseg = (tid & 7) * 16;
    const float* p = W + (size_t)(kc * 32 + krow) * E_DIM + nb * 128 + nseg;
    unsigned char* base = dst + ((size_t)w * 8 * 32 + (size_t)(nb * 32 + kc)) * 16384;
#pragma unroll
    for (int gi = 0; gi < 2; gi++) {
        float v[8];
        *(float4*)(v)     = *(const float4*)(p + gi * 8);
        *(float4*)(v + 4) = *(const float4*)(p + gi * 8 + 4);
        uint32_t hi[4], lo[4];
        split8(v, hi, lo);
        uint32_t sw = swp256(krow, (nseg + gi * 8) * 2);
        *(uint4*)(base + sw)        = make_uint4(hi[0], hi[1], hi[2], hi[3]);
        *(uint4*)(base + 8192 + sw) = make_uint4(lo[0], lo[1], lo[2], lo[3]);
    }
}

// ---------------------------------------------------------------------------
// Projection GEMM from pre-tiled bf16 operands, cp.async double-buffered.
// mode 0: epilogue packs q/k/v as fp16 hi/lo tiles.  mode 2: fp32 out + bias.
// ---------------------------------------------------------------------------
#define PROJ_SMEM 65536
__global__ void __launch_bounds__(256, 2) proj_mma(
    const unsigned char* __restrict__ A2, const unsigned char* __restrict__ W2,
    const float* __restrict__ b0p, const float* __restrict__ b1p, const float* __restrict__ b2p,
    unsigned char* __restrict__ qkvout, float* __restrict__ fout, int mode)
{
    extern __shared__ char sm[];
    uint32_t sb = smem_u32(sm);
    int zz = blockIdx.z;
    const float* bias = zz == 0 ? b0p : (zz == 1 ? b1p : b2p);
    const unsigned char* Wsel = W2 + (size_t)zz * 8 * 32 * 16384;

    int tid = threadIdx.x, lane = tid & 31, wid = tid >> 5;
    int warp_m = wid & 3, warp_n = wid >> 2;
    int n0 = blockIdx.x * 128, m0 = blockIdx.y * 128;
    int lrow = lane & 7, grp = lane >> 3;
    const unsigned char* Abase = A2 + ((size_t)(m0 >> 7) * 32) * 16384;
    const unsigned char* Wbase = Wsel + ((size_t)(n0 >> 7) * 32) * 16384;

    float acc[16][4] = {};
    cp_tile16(sb, Abase, tid);
    cp_tile16(sb + 16384, Wbase, tid);
    CPA_COMMIT();

    for (int c = 0; c < 32; c++) {
        int cur = (c & 1) * 32768;
        if (c < 31) {
            int nb = ((c + 1) & 1) * 32768;
            cp_tile16(sb + nb, Abase + (size_t)(c + 1) * 16384, tid);
            cp_tile16(sb + nb + 16384, Wbase + (size_t)(c + 1) * 16384, tid);
            CPA_COMMIT();
            CPA_WAIT1();
        } else {
            CPA_WAIT0();
        }
        __syncthreads();
        uint32_t sa_hi = sb + cur, sa_lo = sb + cur + 8192;
        uint32_t sw_hi = sb + cur + 16384, sw_lo = sb + cur + 24576;
#pragma unroll
        for (int ks = 0; ks < 2; ks++) {
            int k = ks * 16;
            uint32_t ah[2][4], al[2][4];
#pragma unroll
            for (int mt = 0; mt < 2; mt++) {
                int row = warp_m * 32 + mt * 16 + lrow + (grp & 1) * 8;
                uint32_t off = swp64(row, (k + (grp >> 1) * 8) * 2);
                ldm4(ah[mt], sa_hi + off);
                ldm4(al[mt], sa_lo + off);
            }
#pragma unroll
            for (int nh = 0; nh < 4; nh++) {
                int krow = k + (lane & 15);
                int ncol = warp_n * 64 + nh * 16 + (lane >> 4) * 8;
                uint32_t offb = swp256(krow, ncol * 2);
                uint32_t bh[4], bl[4];
                ldm4t(bh, sw_hi + offb);
                ldm4t(bl, sw_lo + offb);
#pragma unroll
                for (int mt = 0; mt < 2; mt++) {
                    float* c0a = acc[mt * 8 + nh * 2];
                    float* c1a = acc[mt * 8 + nh * 2 + 1];
                    mma_bf16(c0a, ah[mt], bh[0], bh[1]);
                    mma_bf16(c1a, ah[mt], bh[2], bh[3]);
                    mma_bf16(c0a, ah[mt], bl[0], bl[1]);
                    mma_bf16(c1a, ah[mt], bl[2], bl[3]);
                    mma_bf16(c0a, al[mt], bh[0], bh[1]);
                    mma_bf16(c1a, al[mt], bh[2], bh[3]);
                }
            }
        }
        __syncthreads();
    }

    int crow = lane >> 2, cc = (lane & 3) * 2;
    unsigned char* qb = qkvout + (size_t)zz * 32 * 32 * 16384;
#pragma unroll
    for (int mt = 0; mt < 2; mt++) {
#pragma unroll
        for (int t8 = 0; t8 < 8; t8++) {
            const float* c = acc[mt * 8 + t8];
            int n = n0 + warp_n * 64 + t8 * 8 + cc;
            int r0 = m0 + warp_m * 32 + mt * 16 + crow;
            float bb0 = bias[n], bb1 = bias[n + 1];
            if (mode == 2) {
                *(float2*)(fout + (size_t)r0 * E_DIM + n)       = make_float2(c[0] + bb0, c[1] + bb1);
                *(float2*)(fout + (size_t)(r0 + 8) * E_DIM + n) = make_float2(c[2] + bb0, c[3] + bb1);
            } else {
                int h = n >> 6, d = n & 63;
#pragma unroll
                for (int rr = 0; rr < 2; rr++) {
                    int m = r0 + rr * 8;
                    int b = m >> 11, s = m & (S_DIM - 1);
                    int z = b * H_NUM + h;
                    uint32_t lo;
                    uint32_t hi = pack_f16(c[2 * rr] + bb0, c[2 * rr + 1] + bb1, lo);
                    unsigned char* tb = qb + ((size_t)(z * 32 + (s >> 6))) * 16384;
                    uint32_t sw = swp128(s & 63, d * 2);
                    *(uint32_t*)(tb + sw)        = hi;
                    *(uint32_t*)(tb + 8192 + sw) = lo;
                }
            }
        }
    }
}

// ---------------------------------------------------------------------------
// Fused attention, fp16 operands, 2 CTAs/SM.
// Pass 1: row sums, 1-term QK (K hi). Pass 2: 2-term QK ((qh+ql)·kh) +
// 1-term PV (p_hi·vh). Staging: 128-j stages (two 64-j sub-chunks per sync).
// Pass-2 stage = K hi 16KB + V hi 16KB; double-buffered 64KB + mask 8KB.
// ---------------------------------------------------------------------------
#define FA_SMEM (65536 + 8192)
__global__ void __launch_bounds__(256, 2) fused_attn(
    const unsigned char* __restrict__ q2, const unsigned char* __restrict__ k2,
    const unsigned char* __restrict__ v2, const float* __restrict__ mask,
    float* __restrict__ attn, unsigned char* __restrict__ ctx2)
{
    extern __shared__ char sm[];
    uint32_t sb = smem_u32(sm);
    float* mrow = (float*)(sm + 65536);
    int tid = threadIdx.x, lane = tid & 31, wid = tid >> 5;
    int z = blockIdx.y, i0 = blockIdx.x * 128;
    const unsigned char* Kb = k2 + ((size_t)z * 32) * 16384;
    const unsigned char* Vb = v2 + ((size_t)z * 32) * 16384;
    const float* mb = mask + (size_t)(z >> 4) * S_DIM;
    int lrow = lane & 7, grp = lane >> 3;
    int g = lane >> 2, cc = (lane & 3) * 2;

    for (int t = tid; t < S_DIM; t += 256) mrow[t] = -1e9f * mb[t];
    {
        const unsigned char* qg = q2 + ((size_t)(z * 32 + (i0 >> 6))) * 16384;
#pragma unroll
        for (int i = 0; i < 8; i++)
            cpa16(sb + tid * 16 + i * 4096, qg + tid * 16 + i * 4096);
        CPA_COMMIT();
        CPA_WAIT0();
    }
    __syncthreads();

    uint32_t qh[4][4], ql[4][4];
#pragma unroll
    for (int t = 0; t < 4; t++) {
        int row = wid * 16 + lrow + (grp & 1) * 8;
        uint32_t off = (uint32_t)(row >> 6) * 16384 + swp128(row & 63, (t * 16 + (grp >> 1) * 8) * 2);
        ldm4(qh[t], sb + off);
        ldm4(ql[t], sb + 8192 + off);
    }
    __syncthreads();

    // ---------------- pass 1: row sums (K hi, 1-term QK, 128-j stages) ----------------
    float rsum0 = 0.f, rsum1 = 0.f;
    cp_tile8(sb, Kb, tid);
    cp_tile8(sb + 8192, Kb + 16384, tid);
    CPA_COMMIT();
    for (int c = 0; c < 16; c++) {
        int cur = (c & 1) * 16384;
        if (c < 15) {
            int nb = ((c + 1) & 1) * 16384;
            cp_tile8(sb + nb, Kb + (size_t)(2 * c + 2) * 16384, tid);
            cp_tile8(sb + nb + 8192, Kb + (size_t)(2 * c + 3) * 16384, tid);
            CPA_COMMIT();
            CPA_WAIT1();
        } else {
            CPA_WAIT0();
        }
        __syncthreads();
#pragma unroll
        for (int sub = 0; sub < 2; sub++) {
            uint32_t kh_base = sb + cur + sub * 8192;
            float sc[8][4] = {};
#pragma unroll
            for (int t = 0; t < 4; t++) {
#pragma unroll
                for (int nt = 0; nt < 4; nt++) {
                    int rowb = nt * 16 + lrow + ((grp >> 1) & 1) * 8;
                    uint32_t offb = swp128(rowb, (t * 16 + (grp & 1) * 8) * 2);
                    uint32_t bh[4];
                    ldm4(bh, kh_base + offb);
                    mma_f16(sc[nt * 2],     qh[t], bh[0], bh[1]);
                    mma_f16(sc[nt * 2 + 1], qh[t], bh[2], bh[3]);
                }
            }
            int jb = c * 128 + sub * 64;
#pragma unroll
            for (int t8 = 0; t8 < 8; t8++) {
                int j = jb + t8 * 8 + cc;
                float m0 = mrow[j], m1 = mrow[j + 1];
                rsum0 += __expf(sc[t8][0] * 0.125f + m0) + __expf(sc[t8][1] * 0.125f + m1);
                rsum1 += __expf(sc[t8][2] * 0.125f + m0) + __expf(sc[t8][3] * 0.125f + m1);
            }
        }
        __syncthreads();
    }
    rsum0 += __shfl_xor_sync(0xFFFFFFFFu, rsum0, 1);
    rsum0 += __shfl_xor_sync(0xFFFFFFFFu, rsum0, 2);
    rsum1 += __shfl_xor_sync(0xFFFFFFFFu, rsum1, 1);
    rsum1 += __shfl_xor_sync(0xFFFFFFFFu, rsum1, 2);
    float inv0 = 1.0f / rsum0;
    float inv1 = 1.0f / rsum1;

    // ---------------- pass 2: attn + ctx (128-j stages: K hi + V hi) ----------------
    int iRow = i0 + wid * 16 + g;
    float* attn0 = attn + ((size_t)z * S_DIM + iRow) * S_DIM;
    float* attn1 = attn0 + 8 * S_DIM;
    float cacc[8][4] = {};

    cp_tile8(sb, Kb, tid);
    cp_tile8(sb + 8192, Kb + 16384, tid);
    cp_tile8(sb + 16384, Vb, tid);
    cp_tile8(sb + 24576, Vb + 16384, tid);
    CPA_COMMIT();
    for (int c = 0; c < 16; c++) {
        int cur = (c & 1) * 32768;
        if (c < 15) {
            int nb = ((c + 1) & 1) * 32768;
            cp_tile8(sb + nb,         Kb + (size_t)(2 * c + 2) * 16384, tid);
            cp_tile8(sb + nb + 8192,  Kb + (size_t)(2 * c + 3) * 16384, tid);
            cp_tile8(sb + nb + 16384, Vb + (size_t)(2 * c + 2) * 16384, tid);
            cp_tile8(sb + nb + 24576, Vb + (size_t)(2 * c + 3) * 16384, tid);
            CPA_COMMIT();
            CPA_WAIT1();
        } else {
            CPA_WAIT0();
        }
        __syncthreads();
#pragma unroll
        for (int sub = 0; sub < 2; sub++) {
            uint32_t kh_base = sb + cur + sub * 8192;
            uint32_t vh_base = sb + cur + 16384 + sub * 8192;
            float sc[8][4] = {};
#pragma unroll
            for (int t = 0; t < 4; t++) {
#pragma unroll
                for (int nt = 0; nt < 4; nt++) {
                    int rowb = nt * 16 + lrow + ((grp >> 1) & 1) * 8;
                    uint32_t offb = swp128(rowb, (t * 16 + (grp & 1) * 8) * 2);
                    uint32_t bh[4];
                    ldm4(bh, kh_base + offb);
                    float* c0a = sc[nt * 2];
                    float* c1a = sc[nt * 2 + 1];
                    mma_f16(c0a, qh[t], bh[0], bh[1]);
                    mma_f16(c1a, qh[t], bh[2], bh[3]);
                    mma_f16(c0a, ql[t], bh[0], bh[1]);
                    mma_f16(c1a, ql[t], bh[2], bh[3]);
                }
            }
            // per k16-step: exp/normalize/write/pack then 1-term PV
            int jb = c * 128 + sub * 64;
#pragma unroll
            for (int t = 0; t < 4; t++) {
                uint32_t pah[4];
#pragma unroll
                for (int h2 = 0; h2 < 2; h2++) {
                    int t8 = t * 2 + h2;
                    int j = jb + t8 * 8 + cc;
                    float m0 = mrow[j], m1 = mrow[j + 1];
                    float p0 = __expf(sc[t8][0] * 0.125f + m0) * inv0;
                    float p1 = __expf(sc[t8][1] * 0.125f + m1) * inv0;
                    float p2 = __expf(sc[t8][2] * 0.125f + m0) * inv1;
                    float p3 = __expf(sc[t8][3] * 0.125f + m1) * inv1;
                    *(float2*)(attn0 + j) = make_float2(p0, p1);
                    *(float2*)(attn1 + j) = make_float2(p2, p3);
                    pah[h2 * 2]     = pack_f16_hi(p0, p1);
                    pah[h2 * 2 + 1] = pack_f16_hi(p2, p3);
                }
#pragma unroll
                for (int dt = 0; dt < 4; dt++) {
                    int krow = t * 16 + (lane & 15);
                    int ncol = dt * 16 + (lane >> 4) * 8;
                    uint32_t offb = swp128(krow, ncol * 2);
                    uint32_t vh[4];
                    ldm4t(vh, vh_base + offb);
                    mma_f16(cacc[dt * 2],     pah, vh[0], vh[1]);
                    mma_f16(cacc[dt * 2 + 1], pah, vh[2], vh[3]);
                }
            }
        }
        __syncthreads();
    }

    // ctx epilogue: write tiled bf16 hi/lo for O-proj A operand
    int b = z >> 4, h = z & 15;
    int mb2 = (b * S_DIM + i0) >> 7;
    int r = wid * 16 + g;
#pragma unroll
    for (int t8 = 0; t8 < 8; t8++) {
        int d0 = t8 * 8 + cc;
        int n = h * DH_DIM + d0;
        int kc = n >> 5, col = n & 31;
        unsigned char* base = ctx2 + ((size_t)(mb2 * 32 + kc)) * 16384;
        uint32_t lo0, lo1;
        uint32_t hi0 = pack_hilo(cacc[t8][0], cacc[t8][1], lo0);
        uint32_t hi1 = pack_hilo(cacc[t8][2], cacc[t8][3], lo1);
        uint32_t a0 = swp64(r, col * 2);
        uint32_t a1 = swp64(r + 8, col * 2);
        *(uint32_t*)(base + a0)        = hi0;
        *(uint32_t*)(base + 8192 + a0) = lo0;
        *(uint32_t*)(base + a1)        = hi1;
        *(uint32_t*)(base + 8192 + a1) = lo1;
    }
}

// ---------------------------------------------------------------------------

extern "C" void kernel_launch(void* const* d_in, const int* in_sizes, int n_in,
                              void* d_out, int out_size)
{
    const float* features = (const float*)d_in[0];
    const float* mask     = (const float*)d_in[1];
    const float* Wq = (const float*)d_in[2];
    const float* bq = (const float*)d_in[3];
    const float* Wk = (const float*)d_in[4];
    const float* bk = (const float*)d_in[5];
    const float* Wv = (const float*)d_in[6];
    const float* bv = (const float*)d_in[7];
    const float* Wo = (const float*)d_in[8];
    const float* bo = (const float*)d_in[9];
    float* out = (float*)d_out;

    unsigned char *A2, *W2, *qkv2, *ctx2;
    float* attn_scratch;
    cudaGetSymbolAddress((void**)&A2, g_A2);
    cudaGetSymbolAddress((void**)&W2, g_W2);
    cudaGetSymbolAddress((void**)&qkv2, g_qkv2);
    cudaGetSymbolAddress((void**)&ctx2, g_ctx2);
    cudaGetSymbolAddress((void**)&attn_scratch, g_attn);

    const long long OUT_ELEMS  = (long long)M_ROWS * E_DIM;
    const long long ATTN_ELEMS = (long long)BH_NUM * S_DIM * S_DIM;
    float* attn = ((long long)out_size >= OUT_ELEMS + ATTN_ELEMS)
                      ? (out + OUT_ELEMS) : attn_scratch;

    cudaFuncSetAttribute(proj_mma, cudaFuncAttributeMaxDynamicSharedMemorySize, PROJ_SMEM);
    cudaFuncSetAttribute(fused_attn, cudaFuncAttributeMaxDynamicSharedMemorySize, FA_SMEM);
    cudaFuncSetAttribute(proj_mma, cudaFuncAttributePreferredSharedMemoryCarveout, 100);
    cudaFuncSetAttribute(fused_attn, cudaFuncAttributePreferredSharedMemoryCarveout, 100);

    dim3 blk(256);
    convA<<<dim3(32, 32), blk>>>(features, A2);
    convW<<<dim3(32, 8, 4), blk>>>(Wq, Wk, Wv, Wo, W2);
    proj_mma<<<dim3(8, 32, 3), blk, PROJ_SMEM>>>(A2, W2, bq, bk, bv, qkv2, nullptr, 0);
    fused_attn<<<dim3(16, 32), blk, FA_SMEM>>>(
        qkv2, qkv2 + (size_t)32 * 32 * 16384, qkv2 + (size_t)2 * 32 * 32 * 16384,
        mask, attn, ctx2);
    proj_mma<<<dim3(8, 32, 1), blk, PROJ_SMEM>>>(
        ctx2, W2 + (size_t)3 * 8 * 32 * 16384, bo, bo, bo, nullptr, out, 2);
}

// round 14
// speedup vs baseline: 3.0668x; 1.1584x over previous
#include <cuda_runtime.h>
#include <cuda_bf16.h>
#include <cuda_fp16.h>
#include <cstdint>
#include <cstddef>

#define S_DIM 2048
#define E_DIM 1024
#define H_NUM 16
#define DH_DIM 64
#define B_NUM 2
#define BH_NUM (B_NUM * H_NUM)     // 32
#define M_ROWS (B_NUM * S_DIM)     // 4096

// tiled fp16 hi/lo operand images (each tile = 8KB hi plane + 8KB lo plane)
__device__ __align__(16) unsigned char g_A2[(size_t)32 * 32 * 16384];        // features tiled [mb][kc]
__device__ __align__(16) unsigned char g_W2[(size_t)4 * 8 * 32 * 16384];     // 4 weights [w][nb][kc]
__device__ __align__(16) unsigned char g_qkv2[(size_t)3 * 32 * 32 * 16384];  // q/k/v [which][z][t]
__device__ __align__(16) unsigned char g_ctx2[(size_t)32 * 32 * 16384];      // ctx tiled [mb][kc]
__device__ float g_attn[(size_t)BH_NUM * S_DIM * S_DIM];                     // fallback

// ---------------------------------------------------------------------------
// helpers
// ---------------------------------------------------------------------------
__device__ __forceinline__ uint32_t smem_u32(const void* p) {
    uint32_t a;
    asm("{ .reg .u64 t; cvta.to.shared.u64 t, %1; cvt.u32.u64 %0, t; }" : "=r"(a) : "l"(p));
    return a;
}
__device__ __forceinline__ void ldm4(uint32_t* r, uint32_t a) {
    asm volatile("ldmatrix.sync.aligned.m8n8.x4.shared.b16 {%0,%1,%2,%3}, [%4];"
        : "=r"(r[0]), "=r"(r[1]), "=r"(r[2]), "=r"(r[3]) : "r"(a));
}
__device__ __forceinline__ void ldm4t(uint32_t* r, uint32_t a) {
    asm volatile("ldmatrix.sync.aligned.m8n8.x4.trans.shared.b16 {%0,%1,%2,%3}, [%4];"
        : "=r"(r[0]), "=r"(r[1]), "=r"(r[2]), "=r"(r[3]) : "r"(a));
}
__device__ __forceinline__ void mma_f16(float* c, const uint32_t* a, uint32_t b0, uint32_t b1) {
    asm volatile(
        "mma.sync.aligned.m16n8k16.row.col.f32.f16.f16.f32 "
        "{%0,%1,%2,%3}, {%4,%5,%6,%7}, {%8,%9}, {%0,%1,%2,%3};"
        : "+f"(c[0]), "+f"(c[1]), "+f"(c[2]), "+f"(c[3])
        : "r"(a[0]), "r"(a[1]), "r"(a[2]), "r"(a[3]), "r"(b0), "r"(b1));
}
__device__ __forceinline__ void cpa16(uint32_t s, const void* g) {
    asm volatile("cp.async.cg.shared.global [%0], [%1], 16;" :: "r"(s), "l"(g));
}
#define CPA_COMMIT() asm volatile("cp.async.commit_group;" ::: "memory")
#define CPA_WAIT0()  asm volatile("cp.async.wait_group 0;" ::: "memory")
#define CPA_WAIT1()  asm volatile("cp.async.wait_group 1;" ::: "memory")

__device__ __forceinline__ uint32_t swp128(int row, int c2) { return (uint32_t)(row * 128 + c2) ^ ((row & 7) << 4); }
__device__ __forceinline__ uint32_t swp64 (int row, int c2) { return (uint32_t)(row * 64  + c2) ^ (((row >> 1) & 3) << 4); }
__device__ __forceinline__ uint32_t swp256(int row, int c2) { return (uint32_t)(row * 256 + c2) ^ ((row & 7) << 4); }

// fp16 hi/lo split of 8 floats
__device__ __forceinline__ void split8_f16(const float* v, uint32_t* hi, uint32_t* lo) {
#pragma unroll
    for (int q = 0; q < 4; q++) {
        __half h0 = __float2half_rn(v[2*q]);
        __half h1 = __float2half_rn(v[2*q+1]);
        __half l0 = __float2half_rn(v[2*q]   - __half2float(h0));
        __half l1 = __float2half_rn(v[2*q+1] - __half2float(h1));
        hi[q] = (uint32_t)__half_as_ushort(h0) | ((uint32_t)__half_as_ushort(h1) << 16);
        lo[q] = (uint32_t)__half_as_ushort(l0) | ((uint32_t)__half_as_ushort(l1) << 16);
    }
}
__device__ __forceinline__ uint32_t pack_f16(float a, float b, uint32_t& lo) {
    __half ha = __float2half_rn(a), hb = __float2half_rn(b);
    __half la = __float2half_rn(a - __half2float(ha));
    __half lb = __float2half_rn(b - __half2float(hb));
    lo = (uint32_t)__half_as_ushort(la) | ((uint32_t)__half_as_ushort(lb) << 16);
    return (uint32_t)__half_as_ushort(ha) | ((uint32_t)__half_as_ushort(hb) << 16);
}
__device__ __forceinline__ uint32_t pack_f16_hi(float a, float b) {
    __half ha = __float2half_rn(a), hb = __float2half_rn(b);
    return (uint32_t)__half_as_ushort(ha) | ((uint32_t)__half_as_ushort(hb) << 16);
}
// copy one 16KB tile (hi+lo planes) gmem->smem, 256 threads
__device__ __forceinline__ void cp_tile16(uint32_t sdst, const unsigned char* gsrc, int tid) {
#pragma unroll
    for (int i = 0; i < 4; i++)
        cpa16(sdst + tid * 16 + i * 4096, gsrc + tid * 16 + i * 4096);
}
// copy only the 8KB hi plane
__device__ __forceinline__ void cp_tile8(uint32_t sdst, const unsigned char* gsrc, int tid) {
#pragma unroll
    for (int i = 0; i < 2; i++)
        cpa16(sdst + tid * 16 + i * 4096, gsrc + tid * 16 + i * 4096);
}

// ---------------------------------------------------------------------------
// conversion kernels (run once, cheap) — fp16 hi/lo images
// ---------------------------------------------------------------------------
__global__ void __launch_bounds__(256) convA(const float* __restrict__ src,
                                             unsigned char* __restrict__ dst)
{
    int kc = blockIdx.x, mb = blockIdx.y;
    int tid = threadIdx.x;
    int row = tid >> 1, c0 = (tid & 1) * 16;
    const float* p = src + (size_t)(mb * 128 + row) * E_DIM + kc * 32 + c0;
    unsigned char* base = dst + ((size_t)(mb * 32 + kc)) * 16384;
#pragma unroll
    for (int gi = 0; gi < 2; gi++) {
        float v[8];
        *(float4*)(v)     = *(const float4*)(p + gi * 8);
        *(float4*)(v + 4) = *(const float4*)(p + gi * 8 + 4);
        uint32_t hi[4], lo[4];
        split8_f16(v, hi, lo);
        uint32_t sw = swp64(row, (c0 + gi * 8) * 2);
        *(uint4*)(base + sw)        = make_uint4(hi[0], hi[1], hi[2], hi[3]);
        *(uint4*)(base + 8192 + sw) = make_uint4(lo[0], lo[1], lo[2], lo[3]);
    }
}
__global__ void __launch_bounds__(256) convW(
    const float* __restrict__ Wq, const float* __restrict__ Wk,
    const float* __restrict__ Wv, const float* __restrict__ Wo,
    unsigned char* __restrict__ dst)
{
    int kc = blockIdx.x, nb = blockIdx.y, w = blockIdx.z;
    const float* W = w == 0 ? Wq : (w == 1 ? Wk : (w == 2 ? Wv : Wo));
    int tid = threadIdx.x;
    int krow = tid >> 3, nseg = (tid & 7) * 16;
    const float* p = W + (size_t)(kc * 32 + krow) * E_DIM + nb * 128 + nseg;
    unsigned char* base = dst + ((size_t)w * 8 * 32 + (size_t)(nb * 32 + kc)) * 16384;
#pragma unroll
    for (int gi = 0; gi < 2; gi++) {
        float v[8];
        *(float4*)(v)     = *(const float4*)(p + gi * 8);
        *(float4*)(v + 4) = *(const float4*)(p + gi * 8 + 4);
        uint32_t hi[4], lo[4];
        split8_f16(v, hi, lo);
        uint32_t sw = swp256(krow, (nseg + gi * 8) * 2);
        *(uint4*)(base + sw)        = make_uint4(hi[0], hi[1], hi[2], hi[3]);
        *(uint4*)(base + 8192 + sw) = make_uint4(lo[0], lo[1], lo[2], lo[3]);
    }
}

// ---------------------------------------------------------------------------
// Projection GEMM, fp16 2-term: C = (A_hi + A_lo) @ W_hi + bias.
// Stage = A hi/lo 16KB + W hi 8KB = 24KB, double-buffered (48KB smem).
// mode 0: epilogue packs q/k/v as fp16 hi/lo tiles.  mode 2: fp32 out + bias.
// ---------------------------------------------------------------------------
#define PROJ_SMEM 49152
__global__ void __launch_bounds__(256, 2) proj_mma(
    const unsigned char* __restrict__ A2, const unsigned char* __restrict__ W2,
    const float* __restrict__ b0p, const float* __restrict__ b1p, const float* __restrict__ b2p,
    unsigned char* __restrict__ qkvout, float* __restrict__ fout, int mode)
{
    extern __shared__ char sm[];
    uint32_t sb = smem_u32(sm);
    int zz = blockIdx.z;
    const float* bias = zz == 0 ? b0p : (zz == 1 ? b1p : b2p);
    const unsigned char* Wsel = W2 + (size_t)zz * 8 * 32 * 16384;

    int tid = threadIdx.x, lane = tid & 31, wid = tid >> 5;
    int warp_m = wid & 3, warp_n = wid >> 2;
    int n0 = blockIdx.x * 128, m0 = blockIdx.y * 128;
    int lrow = lane & 7, grp = lane >> 3;
    const unsigned char* Abase = A2 + ((size_t)(m0 >> 7) * 32) * 16384;
    const unsigned char* Wbase = Wsel + ((size_t)(n0 >> 7) * 32) * 16384;

    float acc[16][4] = {};
    cp_tile16(sb, Abase, tid);
    cp_tile8(sb + 16384, Wbase, tid);
    CPA_COMMIT();

    for (int c = 0; c < 32; c++) {
        int cur = (c & 1) * 24576;
        if (c < 31) {
            int nb = ((c + 1) & 1) * 24576;
            cp_tile16(sb + nb, Abase + (size_t)(c + 1) * 16384, tid);
            cp_tile8(sb + nb + 16384, Wbase + (size_t)(c + 1) * 16384, tid);
            CPA_COMMIT();
            CPA_WAIT1();
        } else {
            CPA_WAIT0();
        }
        __syncthreads();
        uint32_t sa_hi = sb + cur, sa_lo = sb + cur + 8192;
        uint32_t sw_hi = sb + cur + 16384;
#pragma unroll
        for (int ks = 0; ks < 2; ks++) {
            int k = ks * 16;
            uint32_t ah[2][4], al[2][4];
#pragma unroll
            for (int mt = 0; mt < 2; mt++) {
                int row = warp_m * 32 + mt * 16 + lrow + (grp & 1) * 8;
                uint32_t off = swp64(row, (k + (grp >> 1) * 8) * 2);
                ldm4(ah[mt], sa_hi + off);
                ldm4(al[mt], sa_lo + off);
            }
#pragma unroll
            for (int nh = 0; nh < 4; nh++) {
                int krow = k + (lane & 15);
                int ncol = warp_n * 64 + nh * 16 + (lane >> 4) * 8;
                uint32_t offb = swp256(krow, ncol * 2);
                uint32_t bh[4];
                ldm4t(bh, sw_hi + offb);
#pragma unroll
                for (int mt = 0; mt < 2; mt++) {
                    float* c0a = acc[mt * 8 + nh * 2];
                    float* c1a = acc[mt * 8 + nh * 2 + 1];
                    mma_f16(c0a, ah[mt], bh[0], bh[1]);
                    mma_f16(c1a, ah[mt], bh[2], bh[3]);
                    mma_f16(c0a, al[mt], bh[0], bh[1]);
                    mma_f16(c1a, al[mt], bh[2], bh[3]);
                }
            }
        }
        __syncthreads();
    }

    int crow = lane >> 2, cc = (lane & 3) * 2;
    unsigned char* qb = qkvout + (size_t)zz * 32 * 32 * 16384;
#pragma unroll
    for (int mt = 0; mt < 2; mt++) {
#pragma unroll
        for (int t8 = 0; t8 < 8; t8++) {
            const float* c = acc[mt * 8 + t8];
            int n = n0 + warp_n * 64 + t8 * 8 + cc;
            int r0 = m0 + warp_m * 32 + mt * 16 + crow;
            float bb0 = bias[n], bb1 = bias[n + 1];
            if (mode == 2) {
                *(float2*)(fout + (size_t)r0 * E_DIM + n)       = make_float2(c[0] + bb0, c[1] + bb1);
                *(float2*)(fout + (size_t)(r0 + 8) * E_DIM + n) = make_float2(c[2] + bb0, c[3] + bb1);
            } else {
                int h = n >> 6, d = n & 63;
#pragma unroll
                for (int rr = 0; rr < 2; rr++) {
                    int m = r0 + rr * 8;
                    int b = m >> 11, s = m & (S_DIM - 1);
                    int z = b * H_NUM + h;
                    uint32_t lo;
                    uint32_t hi = pack_f16(c[2 * rr] + bb0, c[2 * rr + 1] + bb1, lo);
                    unsigned char* tb = qb + ((size_t)(z * 32 + (s >> 6))) * 16384;
                    uint32_t sw = swp128(s & 63, d * 2);
                    *(uint32_t*)(tb + sw)        = hi;
                    *(uint32_t*)(tb + 8192 + sw) = lo;
                }
            }
        }
    }
}

// ---------------------------------------------------------------------------
// Fused attention, fp16 operands, 2 CTAs/SM.
// Pass 1: row sums, 1-term QK (K hi). Pass 2: 2-term QK ((qh+ql)·kh) +
// 1-term PV (p_hi·vh). Staging: 128-j stages (two 64-j sub-chunks per sync).
// ---------------------------------------------------------------------------
#define FA_SMEM (65536 + 8192)
__global__ void __launch_bounds__(256, 2) fused_attn(
    const unsigned char* __restrict__ q2, const unsigned char* __restrict__ k2,
    const unsigned char* __restrict__ v2, const float* __restrict__ mask,
    float* __restrict__ attn, unsigned char* __restrict__ ctx2)
{
    extern __shared__ char sm[];
    uint32_t sb = smem_u32(sm);
    float* mrow = (float*)(sm + 65536);
    int tid = threadIdx.x, lane = tid & 31, wid = tid >> 5;
    int z = blockIdx.y, i0 = blockIdx.x * 128;
    const unsigned char* Kb = k2 + ((size_t)z * 32) * 16384;
    const unsigned char* Vb = v2 + ((size_t)z * 32) * 16384;
    const float* mb = mask + (size_t)(z >> 4) * S_DIM;
    int lrow = lane & 7, grp = lane >> 3;
    int g = lane >> 2, cc = (lane & 3) * 2;

    for (int t = tid; t < S_DIM; t += 256) mrow[t] = -1e9f * mb[t];
    {
        const unsigned char* qg = q2 + ((size_t)(z * 32 + (i0 >> 6))) * 16384;
#pragma unroll
        for (int i = 0; i < 8; i++)
            cpa16(sb + tid * 16 + i * 4096, qg + tid * 16 + i * 4096);
        CPA_COMMIT();
        CPA_WAIT0();
    }
    __syncthreads();

    uint32_t qh[4][4], ql[4][4];
#pragma unroll
    for (int t = 0; t < 4; t++) {
        int row = wid * 16 + lrow + (grp & 1) * 8;
        uint32_t off = (uint32_t)(row >> 6) * 16384 + swp128(row & 63, (t * 16 + (grp >> 1) * 8) * 2);
        ldm4(qh[t], sb + off);
        ldm4(ql[t], sb + 8192 + off);
    }
    __syncthreads();

    // ---------------- pass 1: row sums (K hi, 1-term QK, 128-j stages) ----------------
    float rsum0 = 0.f, rsum1 = 0.f;
    cp_tile8(sb, Kb, tid);
    cp_tile8(sb + 8192, Kb + 16384, tid);
    CPA_COMMIT();
    for (int c = 0; c < 16; c++) {
        int cur = (c & 1) * 16384;
        if (c < 15) {
            int nb = ((c + 1) & 1) * 16384;
            cp_tile8(sb + nb, Kb + (size_t)(2 * c + 2) * 16384, tid);
            cp_tile8(sb + nb + 8192, Kb + (size_t)(2 * c + 3) * 16384, tid);
            CPA_COMMIT();
            CPA_WAIT1();
        } else {
            CPA_WAIT0();
        }
        __syncthreads();
#pragma unroll
        for (int sub = 0; sub < 2; sub++) {
            uint32_t kh_base = sb + cur + sub * 8192;
            float sc[8][4] = {};
#pragma unroll
            for (int t = 0; t < 4; t++) {
#pragma unroll
                for (int nt = 0; nt < 4; nt++) {
                    int rowb = nt * 16 + lrow + ((grp >> 1) & 1) * 8;
                    uint32_t offb = swp128(rowb, (t * 16 + (grp & 1) * 8) * 2);
                    uint32_t bh[4];
                    ldm4(bh, kh_base + offb);
                    mma_f16(sc[nt * 2],     qh[t], bh[0], bh[1]);
                    mma_f16(sc[nt * 2 + 1], qh[t], bh[2], bh[3]);
                }
            }
            int jb = c * 128 + sub * 64;
#pragma unroll
            for (int t8 = 0; t8 < 8; t8++) {
                int j = jb + t8 * 8 + cc;
                float m0 = mrow[j], m1 = mrow[j + 1];
                rsum0 += __expf(sc[t8][0] * 0.125f + m0) + __expf(sc[t8][1] * 0.125f + m1);
                rsum1 += __expf(sc[t8][2] * 0.125f + m0) + __expf(sc[t8][3] * 0.125f + m1);
            }
        }
        __syncthreads();
    }
    rsum0 += __shfl_xor_sync(0xFFFFFFFFu, rsum0, 1);
    rsum0 += __shfl_xor_sync(0xFFFFFFFFu, rsum0, 2);
    rsum1 += __shfl_xor_sync(0xFFFFFFFFu, rsum1, 1);
    rsum1 += __shfl_xor_sync(0xFFFFFFFFu, rsum1, 2);
    float inv0 = 1.0f / rsum0;
    float inv1 = 1.0f / rsum1;

    // ---------------- pass 2: attn + ctx (128-j stages: K hi + V hi) ----------------
    int iRow = i0 + wid * 16 + g;
    float* attn0 = attn + ((size_t)z * S_DIM + iRow) * S_DIM;
    float* attn1 = attn0 + 8 * S_DIM;
    float cacc[8][4] = {};

    cp_tile8(sb, Kb, tid);
    cp_tile8(sb + 8192, Kb + 16384, tid);
    cp_tile8(sb + 16384, Vb, tid);
    cp_tile8(sb + 24576, Vb + 16384, tid);
    CPA_COMMIT();
    for (int c = 0; c < 16; c++) {
        int cur = (c & 1) * 32768;
        if (c < 15) {
            int nb = ((c + 1) & 1) * 32768;
            cp_tile8(sb + nb,         Kb + (size_t)(2 * c + 2) * 16384, tid);
            cp_tile8(sb + nb + 8192,  Kb + (size_t)(2 * c + 3) * 16384, tid);
            cp_tile8(sb + nb + 16384, Vb + (size_t)(2 * c + 2) * 16384, tid);
            cp_tile8(sb + nb + 24576, Vb + (size_t)(2 * c + 3) * 16384, tid);
            CPA_COMMIT();
            CPA_WAIT1();
        } else {
            CPA_WAIT0();
        }
        __syncthreads();
#pragma unroll
        for (int sub = 0; sub < 2; sub++) {
            uint32_t kh_base = sb + cur + sub * 8192;
            uint32_t vh_base = sb + cur + 16384 + sub * 8192;
            float sc[8][4] = {};
#pragma unroll
            for (int t = 0; t < 4; t++) {
#pragma unroll
                for (int nt = 0; nt < 4; nt++) {
                    int rowb = nt * 16 + lrow + ((grp >> 1) & 1) * 8;
                    uint32_t offb = swp128(rowb, (t * 16 + (grp & 1) * 8) * 2);
                    uint32_t bh[4];
                    ldm4(bh, kh_base + offb);
                    float* c0a = sc[nt * 2];
                    float* c1a = sc[nt * 2 + 1];
                    mma_f16(c0a, qh[t], bh[0], bh[1]);
                    mma_f16(c1a, qh[t], bh[2], bh[3]);
                    mma_f16(c0a, ql[t], bh[0], bh[1]);
                    mma_f16(c1a, ql[t], bh[2], bh[3]);
                }
            }
            // per k16-step: exp/normalize/write/pack then 1-term PV
            int jb = c * 128 + sub * 64;
#pragma unroll
            for (int t = 0; t < 4; t++) {
                uint32_t pah[4];
#pragma unroll
                for (int h2 = 0; h2 < 2; h2++) {
                    int t8 = t * 2 + h2;
                    int j = jb + t8 * 8 + cc;
                    float m0 = mrow[j], m1 = mrow[j + 1];
                    float p0 = __expf(sc[t8][0] * 0.125f + m0) * inv0;
                    float p1 = __expf(sc[t8][1] * 0.125f + m1) * inv0;
                    float p2 = __expf(sc[t8][2] * 0.125f + m0) * inv1;
                    float p3 = __expf(sc[t8][3] * 0.125f + m1) * inv1;
                    *(float2*)(attn0 + j) = make_float2(p0, p1);
                    *(float2*)(attn1 + j) = make_float2(p2, p3);
                    pah[h2 * 2]     = pack_f16_hi(p0, p1);
                    pah[h2 * 2 + 1] = pack_f16_hi(p2, p3);
                }
#pragma unroll
                for (int dt = 0; dt < 4; dt++) {
                    int krow = t * 16 + (lane & 15);
                    int ncol = dt * 16 + (lane >> 4) * 8;
                    uint32_t offb = swp128(krow, ncol * 2);
                    uint32_t vh[4];
                    ldm4t(vh, vh_base + offb);
                    mma_f16(cacc[dt * 2],     pah, vh[0], vh[1]);
                    mma_f16(cacc[dt * 2 + 1], pah, vh[2], vh[3]);
                }
            }
        }
        __syncthreads();
    }

    // ctx epilogue: write tiled fp16 hi/lo for O-proj A operand
    int b = z >> 4, h = z & 15;
    int mb2 = (b * S_DIM + i0) >> 7;
    int r = wid * 16 + g;
#pragma unroll
    for (int t8 = 0; t8 < 8; t8++) {
        int d0 = t8 * 8 + cc;
        int n = h * DH_DIM + d0;
        int kc = n >> 5, col = n & 31;
        unsigned char* base = ctx2 + ((size_t)(mb2 * 32 + kc)) * 16384;
        uint32_t lo0, lo1;
        uint32_t hi0 = pack_f16(cacc[t8][0], cacc[t8][1], lo0);
        uint32_t hi1 = pack_f16(cacc[t8][2], cacc[t8][3], lo1);
        uint32_t a0 = swp64(r, col * 2);
        uint32_t a1 = swp64(r + 8, col * 2);
        *(uint32_t*)(base + a0)        = hi0;
        *(uint32_t*)(base + 8192 + a0) = lo0;
        *(uint32_t*)(base + a1)        = hi1;
        *(uint32_t*)(base + 8192 + a1) = lo1;
    }
}

// ---------------------------------------------------------------------------

extern "C" void kernel_launch(void* const* d_in, const int* in_sizes, int n_in,
                              void* d_out, int out_size)
{
    const float* features = (const float*)d_in[0];
    const float* mask     = (const float*)d_in[1];
    const float* Wq = (const float*)d_in[2];
    const float* bq = (const float*)d_in[3];
    const float* Wk = (const float*)d_in[4];
    const float* bk = (const float*)d_in[5];
    const float* Wv = (const float*)d_in[6];
    const float* bv = (const float*)d_in[7];
    const float* Wo = (const float*)d_in[8];
    const float* bo = (const float*)d_in[9];
    float* out = (float*)d_out;

    unsigned char *A2, *W2, *qkv2, *ctx2;
    float* attn_scratch;
    cudaGetSymbolAddress((void**)&A2, g_A2);
    cudaGetSymbolAddress((void**)&W2, g_W2);
    cudaGetSymbolAddress((void**)&qkv2, g_qkv2);
    cudaGetSymbolAddress((void**)&ctx2, g_ctx2);
    cudaGetSymbolAddress((void**)&attn_scratch, g_attn);

    const long long OUT_ELEMS  = (long long)M_ROWS * E_DIM;
    const long long ATTN_ELEMS = (long long)BH_NUM * S_DIM * S_DIM;
    float* attn = ((long long)out_size >= OUT_ELEMS + ATTN_ELEMS)
                      ? (out + OUT_ELEMS) : attn_scratch;

    cudaFuncSetAttribute(proj_mma, cudaFuncAttributeMaxDynamicSharedMemorySize, PROJ_SMEM);
    cudaFuncSetAttribute(fused_attn, cudaFuncAttributeMaxDynamicSharedMemorySize, FA_SMEM);
    cudaFuncSetAttribute(proj_mma, cudaFuncAttributePreferredSharedMemoryCarveout, 100);
    cudaFuncSetAttribute(fused_attn, cudaFuncAttributePreferredSharedMemoryCarveout, 100);

    dim3 blk(256);
    convA<<<dim3(32, 32), blk>>>(features, A2);
    convW<<<dim3(32, 8, 4), blk>>>(Wq, Wk, Wv, Wo, W2);
    proj_mma<<<dim3(8, 32, 3), blk, PROJ_SMEM>>>(A2, W2, bq, bk, bv, qkv2, nullptr, 0);
    fused_attn<<<dim3(16, 32), blk, FA_SMEM>>>(
        qkv2, qkv2 + (size_t)32 * 32 * 16384, qkv2 + (size_t)2 * 32 * 32 * 16384,
        mask, attn, ctx2);
    proj_mma<<<dim3(8, 32, 1), blk, PROJ_SMEM>>>(
        ctx2, W2 + (size_t)3 * 8 * 32 * 16384, bo, bo, bo, nullptr, out, 2);
}